// round 2
// baseline (speedup 1.0000x reference)
#include <cuda_runtime.h>
#include <cuda_bf16.h>
#include <math.h>

// ---------------- problem constants ----------------
#define BTOK 8192
#define DDIM 1280
#define NEXP 4
#define NCH  20
#define CDIM 64
#define NHEAD 4
#define HDIM 16
#define FFH  256
#define TB   16      // tokens per expert-block

// ---------------- device scratch (allocation-free) ----------------
__device__ float g_w[BTOK * NEXP];          // combine weights (0 for unselected)
__device__ int   g_cnt[NEXP];               // per-expert token counts
__device__ int   g_list[NEXP * BTOK];       // compact token lists
__device__ int   g_slot[2 * BTOK];          // token -> global slot (e*B + slot)
__device__ int   g_tope[2 * BTOK];          // token -> expert ids (top2)
__device__ float g_topw[2 * BTOK];          // token -> weights (top2)
__device__ float g_xs[(size_t)NEXP * BTOK * DDIM];   // post-attention residual
__device__ float g_h [(size_t)NEXP * BTOK * DDIM];   // w-scaled final hidden
__device__ float g_y [(size_t)NEXP * BTOK * DDIM];   // per-slot proj output

// ---------------- K0: init ----------------
__global__ void k_init() {
    if (threadIdx.x < NEXP) g_cnt[threadIdx.x] = 0;
}

// ---------------- K1: gating + routing ----------------
__global__ void k_gate(const float* __restrict__ x,
                       const float* __restrict__ gw1, const float* __restrict__ gb1,
                       const float* __restrict__ gw2, const float* __restrict__ gb2) {
    __shared__ float s_x[8][DDIM];
    int warp = threadIdx.x >> 5, lane = threadIdx.x & 31;
    int b = blockIdx.x * 8 + warp;
    const float* xr = x + (size_t)b * DDIM;
    for (int d = lane; d < DDIM; d += 32) s_x[warp][d] = xr[d];
    __syncwarp();
    float h1[16];
#pragma unroll
    for (int j = 0; j < 16; j++) {
        float s = 0.f;
        const float* wr = gw1 + j * DDIM;
        for (int d = lane; d < DDIM; d += 32) s += s_x[warp][d] * wr[d];
#pragma unroll
        for (int o = 16; o; o >>= 1) s += __shfl_xor_sync(0xffffffffu, s, o);
        h1[j] = tanhf(s + gb1[j]);
    }
    if (lane == 0) {
        float logits[NEXP];
#pragma unroll
        for (int e = 0; e < NEXP; e++) {
            float s = gb2[e];
#pragma unroll
            for (int j = 0; j < 16; j++) s += h1[j] * gw2[e * 16 + j];
            logits[e] = s;
        }
        float m = logits[0];
#pragma unroll
        for (int e = 1; e < NEXP; e++) m = fmaxf(m, logits[e]);
        float p[NEXP], sum = 0.f;
#pragma unroll
        for (int e = 0; e < NEXP; e++) { p[e] = expf(logits[e] - m); sum += p[e]; }
#pragma unroll
        for (int e = 0; e < NEXP; e++) p[e] /= sum;
        // top-2, ties -> lower index (strict > keeps first max)
        int e0 = 0;
#pragma unroll
        for (int e = 1; e < NEXP; e++) if (p[e] > p[e0]) e0 = e;
        int e1 = -1;
#pragma unroll
        for (int e = 0; e < NEXP; e++) {
            if (e == e0) continue;
            if (e1 < 0 || p[e] > p[e1]) e1 = e;
        }
        float den = p[e0] + p[e1] + 1e-6f;
        float w0 = p[e0] / den, w1 = p[e1] / den;
        float wv[NEXP] = {0.f, 0.f, 0.f, 0.f};
        wv[e0] = w0; wv[e1] = w1;
#pragma unroll
        for (int e = 0; e < NEXP; e++) g_w[b * NEXP + e] = wv[e];
        int s0 = atomicAdd(&g_cnt[e0], 1);
        int s1 = atomicAdd(&g_cnt[e1], 1);
        g_list[e0 * BTOK + s0] = b;
        g_list[e1 * BTOK + s1] = b;
        g_slot[2 * b]     = e0 * BTOK + s0;
        g_slot[2 * b + 1] = e1 * BTOK + s1;
        g_tope[2 * b] = e0; g_tope[2 * b + 1] = e1;
        g_topw[2 * b] = w0; g_topw[2 * b + 1] = w1;
    }
}

// ---------------- K2a: pos + rms1 + attention + out_proj + residual ----------------
#define A_IPW 0
#define A_OPW 13056
#define A_POS 17408
#define A_XS  18688
#define A_XN  19968
#define A_QKV 21248
#define A_O   25168
#define A_IPB 26448
#define A_OPB 26640
#define A_N1G 26704
#define A_LS1 26768
#define A_TOT 26832

__global__ void __launch_bounds__(256) k_exp_a(
    const float* __restrict__ x, const float* __restrict__ pos,
    const float* __restrict__ n1g,
    const float* __restrict__ ipw, const float* __restrict__ ipb,
    const float* __restrict__ opw, const float* __restrict__ opb,
    const float* __restrict__ ls1) {
    extern __shared__ float sm[];
    int e = blockIdx.y, g = blockIdx.x, t = threadIdx.x;
    int warp = t >> 5, lane = t & 31;
    // stage weights
    for (int i = t; i < 192 * 64; i += 256) { int j = i >> 6, d = i & 63; sm[A_IPW + j * 68 + d] = ipw[(size_t)e * 192 * 64 + i]; }
    for (int i = t; i < 64 * 64; i += 256)  { int j = i >> 6, d = i & 63; sm[A_OPW + j * 68 + d] = opw[(size_t)e * 64 * 64 + i]; }
    for (int i = t; i < DDIM; i += 256) sm[A_POS + i] = pos[(size_t)e * DDIM + i];
    if (t < 192) sm[A_IPB + t] = ipb[e * 192 + t];
    if (t < 64) {
        sm[A_OPB + t] = opb[e * 64 + t];
        sm[A_N1G + t] = n1g[e * 64 + t];
        sm[A_LS1 + t] = ls1[e * 64 + t];
    }
    __syncthreads();

    for (int ti = 0; ti < TB; ti++) {
        int b = g * TB + ti;
        float wgt = g_w[b * NEXP + e];
        if (wgt == 0.f) continue;   // uniform across block
        // xs = x + pos
        const float* xr = x + (size_t)b * DDIM;
        for (int i = t; i < DDIM; i += 256) sm[A_XS + i] = xr[i] + sm[A_POS + i];
        __syncthreads();
        // rms1 -> xn
        for (int c = warp; c < NCH; c += 8) {
            float v0 = sm[A_XS + c * 64 + lane], v1 = sm[A_XS + c * 64 + 32 + lane];
            float ss = v0 * v0 + v1 * v1;
#pragma unroll
            for (int o = 16; o; o >>= 1) ss += __shfl_xor_sync(0xffffffffu, ss, o);
            float inv = 1.f / (sqrtf(ss * (1.f / 64.f)) + 1e-8f);
            sm[A_XN + c * 64 + lane]      = v0 * inv * sm[A_N1G + lane];
            sm[A_XN + c * 64 + 32 + lane] = v1 * inv * sm[A_N1G + 32 + lane];
        }
        __syncthreads();
        // in_proj: qkv[c][j] (threads 0..191 = j)
        if (t < 192) {
            int j = t;
            float acc[NCH];
#pragma unroll
            for (int c = 0; c < NCH; c++) acc[c] = sm[A_IPB + j];
#pragma unroll
            for (int d = 0; d < 64; d += 4) {
                float4 wf = *(const float4*)&sm[A_IPW + j * 68 + d];
#pragma unroll
                for (int c = 0; c < NCH; c++) {
                    float4 xf = *(const float4*)&sm[A_XN + c * 64 + d];
                    acc[c] += wf.x * xf.x + wf.y * xf.y + wf.z * xf.z + wf.w * xf.w;
                }
            }
#pragma unroll
            for (int c = 0; c < NCH; c++) sm[A_QKV + c * 196 + j] = acc[c];
        }
        __syncthreads();
        // attention: warp -> (head = warp/2, rows = (warp%2)*10..+9)
        // NOTE: every __shfl_sync below is executed by ALL 32 lanes
        // (divergent full-mask shfl deadlocks on sm_103a).
        {
            int h = warp >> 1;
            int c1base = (warp & 1) * 10;
            for (int cc = 0; cc < 10; cc++) {
                int c1 = c1base + cc;
                float sc = -1e30f;
                if (lane < NCH) {
                    float s = 0.f;
#pragma unroll
                    for (int d = 0; d < HDIM; d++)
                        s += sm[A_QKV + c1 * 196 + h * 16 + d] *
                             sm[A_QKV + lane * 196 + 64 + h * 16 + d];
                    sc = s * 0.25f;
                }
                float m = sc;
#pragma unroll
                for (int o = 16; o; o >>= 1) m = fmaxf(m, __shfl_xor_sync(0xffffffffu, m, o));
                float p = (lane < NCH) ? __expf(sc - m) : 0.f;
                float sum = p;
#pragma unroll
                for (int o = 16; o; o >>= 1) sum += __shfl_xor_sync(0xffffffffu, sum, o);
                float att = p / sum;
                float acc = 0.f;
#pragma unroll
                for (int c2 = 0; c2 < NCH; c2++) {
                    float a = __shfl_sync(0xffffffffu, att, c2);   // all lanes execute
                    if (lane < HDIM)
                        acc += a * sm[A_QKV + c2 * 196 + 128 + h * 16 + lane];
                }
                if (lane < HDIM)
                    sm[A_O + c1 * 64 + h * 16 + lane] = acc;
            }
        }
        __syncthreads();
        // out_proj + residual -> g_xs
        {
            int j = t & 63, cg = t >> 6;
            float acc[5];
#pragma unroll
            for (int i = 0; i < 5; i++) acc[i] = sm[A_OPB + j];
#pragma unroll
            for (int d = 0; d < 64; d += 4) {
                float4 wf = *(const float4*)&sm[A_OPW + j * 68 + d];
#pragma unroll
                for (int i = 0; i < 5; i++) {
                    int c = cg * 5 + i;
                    float4 xf = *(const float4*)&sm[A_O + c * 64 + d];
                    acc[i] += wf.x * xf.x + wf.y * xf.y + wf.z * xf.z + wf.w * xf.w;
                }
            }
            float* gout = g_xs + ((size_t)e * BTOK + b) * DDIM;
#pragma unroll
            for (int i = 0; i < 5; i++) {
                int c = cg * 5 + i;
                gout[c * 64 + j] = sm[A_XS + c * 64 + j] + sm[A_LS1 + j] * acc[i];
            }
        }
        __syncthreads();
    }
}

// ---------------- K2b: rms2 + FFN + residual, scale by w -> g_h ----------------
#define B_FW1 0
#define B_FW2 17408
#define B_F1  34048
#define B_XS  39168
#define B_H2  40448
#define B_FB1 41728
#define B_FB2 41984
#define B_N2G 42048
#define B_LS2 42112
#define B_TOT 42176

__global__ void __launch_bounds__(256) k_exp_b(
    const float* __restrict__ n2g,
    const float* __restrict__ fw1, const float* __restrict__ fb1,
    const float* __restrict__ fw2, const float* __restrict__ fb2,
    const float* __restrict__ ls2) {
    extern __shared__ float sm[];
    int e = blockIdx.y, g = blockIdx.x, t = threadIdx.x;
    int warp = t >> 5, lane = t & 31;
    for (int i = t; i < 256 * 64; i += 256) { int j = i >> 6, d = i & 63; sm[B_FW1 + j * 68 + d] = fw1[(size_t)e * 256 * 64 + i]; }
    for (int i = t; i < 64 * 256; i += 256) { int j = i >> 8, d = i & 255; sm[B_FW2 + j * 260 + d] = fw2[(size_t)e * 64 * 256 + i]; }
    if (t < 256) sm[B_FB1 + t] = fb1[e * 256 + t];
    if (t < 64) {
        sm[B_FB2 + t] = fb2[e * 64 + t];
        sm[B_N2G + t] = n2g[e * 64 + t];
        sm[B_LS2 + t] = ls2[e * 64 + t];
    }
    __syncthreads();

    for (int ti = 0; ti < TB; ti++) {
        int b = g * TB + ti;
        float wgt = g_w[b * NEXP + e];
        if (wgt == 0.f) continue;
        const float* gin = g_xs + ((size_t)e * BTOK + b) * DDIM;
        for (int i = t; i < DDIM; i += 256) sm[B_XS + i] = gin[i];
        __syncthreads();
        // rms2 -> h2
        for (int c = warp; c < NCH; c += 8) {
            float v0 = sm[B_XS + c * 64 + lane], v1 = sm[B_XS + c * 64 + 32 + lane];
            float ss = v0 * v0 + v1 * v1;
#pragma unroll
            for (int o = 16; o; o >>= 1) ss += __shfl_xor_sync(0xffffffffu, ss, o);
            float inv = 1.f / (sqrtf(ss * (1.f / 64.f)) + 1e-8f);
            sm[B_H2 + c * 64 + lane]      = v0 * inv * sm[B_N2G + lane];
            sm[B_H2 + c * 64 + 32 + lane] = v1 * inv * sm[B_N2G + 32 + lane];
        }
        __syncthreads();
        // ffn1 (relu): all 256 threads = j
        {
            int j = t;
            float acc[NCH];
#pragma unroll
            for (int c = 0; c < NCH; c++) acc[c] = sm[B_FB1 + j];
#pragma unroll
            for (int d = 0; d < 64; d += 4) {
                float4 wf = *(const float4*)&sm[B_FW1 + j * 68 + d];
#pragma unroll
                for (int c = 0; c < NCH; c++) {
                    float4 xf = *(const float4*)&sm[B_H2 + c * 64 + d];
                    acc[c] += wf.x * xf.x + wf.y * xf.y + wf.z * xf.z + wf.w * xf.w;
                }
            }
#pragma unroll
            for (int c = 0; c < NCH; c++) sm[B_F1 + c * 256 + j] = fmaxf(acc[c], 0.f);
        }
        __syncthreads();
        // ffn2 + residual + scale -> g_h
        {
            int j = t & 63, cg = t >> 6;
            float acc[5];
#pragma unroll
            for (int i = 0; i < 5; i++) acc[i] = sm[B_FB2 + j];
            for (int d = 0; d < 256; d += 4) {
                float4 wf = *(const float4*)&sm[B_FW2 + j * 260 + d];
#pragma unroll
                for (int i = 0; i < 5; i++) {
                    int c = cg * 5 + i;
                    float4 xf = *(const float4*)&sm[B_F1 + c * 256 + d];
                    acc[i] += wf.x * xf.x + wf.y * xf.y + wf.z * xf.z + wf.w * xf.w;
                }
            }
            float* gout = g_h + ((size_t)e * BTOK + b) * DDIM;
#pragma unroll
            for (int i = 0; i < 5; i++) {
                int c = cg * 5 + i;
                float v = sm[B_XS + c * 64 + j] + sm[B_LS2 + j] * acc[i];
                gout[c * 64 + j] = wgt * v;
            }
        }
        __syncthreads();
    }
}

// ---------------- K3: gathered proj GEMM (compact per-expert) ----------------
__global__ void __launch_bounds__(256, 2) k_proj(const float* __restrict__ pw) {
    int e  = blockIdx.y >> 6;       // 64 row-tiles per expert
    int rt = blockIdx.y & 63;
    int nt = blockIdx.x;            // 0..9
    int cnt = g_cnt[e];
    int row0 = rt * 128;
    if (row0 >= cnt) return;
    __shared__ float As[16][132];
    __shared__ float Bs[16][132];
    __shared__ int s_tok[128];
    int t = threadIdx.x;
    if (t < 128) {
        int row = row0 + t;
        s_tok[t] = (row < cnt) ? g_list[e * BTOK + row] : -1;
    }
    __syncthreads();
    int tx = t & 15, ty = t >> 4;
    float acc[8][8];
#pragma unroll
    for (int i = 0; i < 8; i++)
#pragma unroll
        for (int j = 0; j < 8; j++) acc[i][j] = 0.f;

    const float* Bbase = pw + (size_t)e * DDIM * DDIM + (size_t)(nt * 128) * DDIM;
    const float* Abase = g_h + (size_t)e * BTOK * DDIM;

    for (int k0 = 0; k0 < DDIM; k0 += 16) {
#pragma unroll
        for (int i = 0; i < 2; i++) {
            int slot = t + i * 256;
            int m = slot >> 2, k4 = slot & 3;
            int tok = s_tok[m];
            float4 v = make_float4(0.f, 0.f, 0.f, 0.f);
            if (tok >= 0) v = *(const float4*)&Abase[(size_t)tok * DDIM + k0 + k4 * 4];
            As[k4 * 4 + 0][m] = v.x; As[k4 * 4 + 1][m] = v.y;
            As[k4 * 4 + 2][m] = v.z; As[k4 * 4 + 3][m] = v.w;
        }
#pragma unroll
        for (int i = 0; i < 2; i++) {
            int slot = t + i * 256;
            int n = slot >> 2, k4 = slot & 3;
            float4 v = *(const float4*)&Bbase[(size_t)n * DDIM + k0 + k4 * 4];
            Bs[k4 * 4 + 0][n] = v.x; Bs[k4 * 4 + 1][n] = v.y;
            Bs[k4 * 4 + 2][n] = v.z; Bs[k4 * 4 + 3][n] = v.w;
        }
        __syncthreads();
#pragma unroll
        for (int k = 0; k < 16; k++) {
            float a[8], bb[8];
            *(float4*)&a[0]  = *(const float4*)&As[k][ty * 8];
            *(float4*)&a[4]  = *(const float4*)&As[k][ty * 8 + 4];
            *(float4*)&bb[0] = *(const float4*)&Bs[k][tx * 8];
            *(float4*)&bb[4] = *(const float4*)&Bs[k][tx * 8 + 4];
#pragma unroll
            for (int i = 0; i < 8; i++)
#pragma unroll
                for (int j = 0; j < 8; j++) acc[i][j] += a[i] * bb[j];
        }
        __syncthreads();
    }
#pragma unroll
    for (int i = 0; i < 8; i++) {
        int row = row0 + ty * 8 + i;
        if (row < cnt) {
            float* yr = g_y + ((size_t)e * BTOK + row) * DDIM + nt * 128;
            *(float4*)&yr[tx * 8]     = *(const float4*)&acc[i][0];
            *(float4*)&yr[tx * 8 + 4] = *(const float4*)&acc[i][4];
        }
    }
}

// ---------------- K4: combine (+bias) + aux/load tail ----------------
__global__ void k_combine(const float* __restrict__ pb, float* __restrict__ out,
                          long long out_size) {
    long long idx = (long long)blockIdx.x * 256 + threadIdx.x;
    const long long TOT = (long long)BTOK * DDIM;
    if (idx < TOT) {
        int b = (int)(idx / DDIM), d = (int)(idx % DDIM);
        int s0 = g_slot[2 * b], s1 = g_slot[2 * b + 1];
        int e0 = g_tope[2 * b], e1 = g_tope[2 * b + 1];
        float v = g_y[(size_t)s0 * DDIM + d] + g_y[(size_t)s1 * DDIM + d]
                + g_topw[2 * b] * pb[e0 * DDIM + d]
                + g_topw[2 * b + 1] * pb[e1 * DDIM + d];
        out[idx] = v;
    }
    if (idx == 0 && out_size >= TOT + 5) {
        out[TOT] = 0.f;  // aux_loss
#pragma unroll
        for (int e = 0; e < NEXP; e++) out[TOT + 1 + e] = (float)g_cnt[e];
    }
}

// ---------------- host launcher ----------------
extern "C" void kernel_launch(void* const* d_in, const int* in_sizes, int n_in,
                              void* d_out, int out_size) {
    const float* x    = (const float*)d_in[0];
    const float* gw1  = (const float*)d_in[1];
    const float* gb1  = (const float*)d_in[2];
    const float* gw2  = (const float*)d_in[3];
    const float* gb2  = (const float*)d_in[4];
    const float* pos  = (const float*)d_in[5];
    const float* n1g  = (const float*)d_in[6];
    const float* ipw  = (const float*)d_in[7];
    const float* ipb  = (const float*)d_in[8];
    const float* opw  = (const float*)d_in[9];
    const float* opb  = (const float*)d_in[10];
    const float* ls1  = (const float*)d_in[11];
    const float* n2g  = (const float*)d_in[12];
    const float* fw1  = (const float*)d_in[13];
    const float* fb1  = (const float*)d_in[14];
    const float* fw2  = (const float*)d_in[15];
    const float* fb2  = (const float*)d_in[16];
    const float* ls2  = (const float*)d_in[17];
    const float* pw   = (const float*)d_in[18];
    const float* pb   = (const float*)d_in[19];
    float* out = (float*)d_out;

    cudaFuncSetAttribute(k_exp_a, cudaFuncAttributeMaxDynamicSharedMemorySize, A_TOT * 4);
    cudaFuncSetAttribute(k_exp_b, cudaFuncAttributeMaxDynamicSharedMemorySize, B_TOT * 4);

    k_init<<<1, 32>>>();
    k_gate<<<BTOK / 8, 256>>>(x, gw1, gb1, gw2, gb2);
    k_exp_a<<<dim3(BTOK / TB, NEXP), 256, A_TOT * 4>>>(x, pos, n1g, ipw, ipb, opw, opb, ls1);
    k_exp_b<<<dim3(BTOK / TB, NEXP), 256, B_TOT * 4>>>(n2g, fw1, fb1, fw2, fb2, ls2);
    k_proj<<<dim3(DDIM / 128, NEXP * (BTOK / 128)), 256>>>(pw);
    long long tot = (long long)BTOK * DDIM;
    k_combine<<<(unsigned)((tot + 255) / 256), 256>>>(pb, out, (long long)out_size);
}

// round 4
// speedup vs baseline: 1.2171x; 1.2171x over previous
#include <cuda_runtime.h>
#include <cuda_bf16.h>
#include <math.h>
#include <cstdint>

// ---------------- problem constants ----------------
#define BTOK 8192
#define DDIM 1280
#define NEXP 4
#define NCH  20
#define CDIM 64
#define NHEAD 4
#define HDIM 16
#define FFH  256
#define TB   16      // tokens per expert-block

// ---------------- device scratch (allocation-free) ----------------
__device__ float g_w[BTOK * NEXP];          // combine weights (0 for unselected)
__device__ int   g_cnt[NEXP];               // per-expert token counts
__device__ int   g_slot[2 * BTOK];          // token -> global slot (e*B + slot)
__device__ int   g_slotbe[BTOK * NEXP];     // (token,expert) -> global slot
__device__ int   g_tope[2 * BTOK];          // token -> expert ids (top2)
__device__ float g_topw[2 * BTOK];          // token -> weights (top2)
__device__ float g_xs[(size_t)NEXP * BTOK * DDIM];   // post-attention residual
__device__ __nv_bfloat16 g_hbh[(size_t)NEXP * BTOK * DDIM]; // compact hidden, hi
__device__ __nv_bfloat16 g_hbl[(size_t)NEXP * BTOK * DDIM]; // compact hidden, lo
__device__ __nv_bfloat16 g_pwh[(size_t)NEXP * DDIM * DDIM]; // proj weight hi
__device__ __nv_bfloat16 g_pwl[(size_t)NEXP * DDIM * DDIM]; // proj weight lo
__device__ float g_y [(size_t)NEXP * BTOK * DDIM];   // per-slot proj output

// ---------------- warp MMA helpers (baseline PTX, OK on plain sm_103) -------
__device__ __forceinline__ uint32_t smem_u32(const void* p) {
    uint32_t a;
    asm("{ .reg .u64 t; cvta.to.shared.u64 t, %1; cvt.u32.u64 %0, t; }" : "=r"(a) : "l"(p));
    return a;
}
__device__ __forceinline__ void ldm_x4(uint32_t& r0, uint32_t& r1, uint32_t& r2, uint32_t& r3,
                                       uint32_t addr) {
    asm volatile("ldmatrix.sync.aligned.m8n8.x4.shared.b16 {%0,%1,%2,%3}, [%4];"
                 : "=r"(r0), "=r"(r1), "=r"(r2), "=r"(r3) : "r"(addr));
}
__device__ __forceinline__ void mma16816(float* d, const uint32_t* a, const uint32_t* b) {
    asm volatile("mma.sync.aligned.m16n8k16.row.col.f32.bf16.bf16.f32 "
                 "{%0,%1,%2,%3}, {%4,%5,%6,%7}, {%8,%9}, {%0,%1,%2,%3};"
                 : "+f"(d[0]), "+f"(d[1]), "+f"(d[2]), "+f"(d[3])
                 : "r"(a[0]), "r"(a[1]), "r"(a[2]), "r"(a[3]), "r"(b[0]), "r"(b[1]));
}

// ---------------- K0: init ----------------
__global__ void k_init() {
    if (threadIdx.x < NEXP) g_cnt[threadIdx.x] = 0;
}

// ---------------- K1: gating + routing ----------------
__global__ void k_gate(const float* __restrict__ x,
                       const float* __restrict__ gw1, const float* __restrict__ gb1,
                       const float* __restrict__ gw2, const float* __restrict__ gb2) {
    __shared__ float s_x[8][DDIM];
    int warp = threadIdx.x >> 5, lane = threadIdx.x & 31;
    int b = blockIdx.x * 8 + warp;
    const float* xr = x + (size_t)b * DDIM;
    for (int d = lane; d < DDIM; d += 32) s_x[warp][d] = xr[d];
    __syncwarp();
    float h1[16];
#pragma unroll
    for (int j = 0; j < 16; j++) {
        float s = 0.f;
        const float* wr = gw1 + j * DDIM;
        for (int d = lane; d < DDIM; d += 32) s += s_x[warp][d] * wr[d];
#pragma unroll
        for (int o = 16; o; o >>= 1) s += __shfl_xor_sync(0xffffffffu, s, o);
        h1[j] = tanhf(s + gb1[j]);
    }
    if (lane == 0) {
        float logits[NEXP];
#pragma unroll
        for (int e = 0; e < NEXP; e++) {
            float s = gb2[e];
#pragma unroll
            for (int j = 0; j < 16; j++) s += h1[j] * gw2[e * 16 + j];
            logits[e] = s;
        }
        float m = logits[0];
#pragma unroll
        for (int e = 1; e < NEXP; e++) m = fmaxf(m, logits[e]);
        float p[NEXP], sum = 0.f;
#pragma unroll
        for (int e = 0; e < NEXP; e++) { p[e] = expf(logits[e] - m); sum += p[e]; }
#pragma unroll
        for (int e = 0; e < NEXP; e++) p[e] /= sum;
        int e0 = 0;
#pragma unroll
        for (int e = 1; e < NEXP; e++) if (p[e] > p[e0]) e0 = e;
        int e1 = -1;
#pragma unroll
        for (int e = 0; e < NEXP; e++) {
            if (e == e0) continue;
            if (e1 < 0 || p[e] > p[e1]) e1 = e;
        }
        float den = p[e0] + p[e1] + 1e-6f;
        float w0 = p[e0] / den, w1 = p[e1] / den;
        float wv[NEXP] = {0.f, 0.f, 0.f, 0.f};
        wv[e0] = w0; wv[e1] = w1;
#pragma unroll
        for (int e = 0; e < NEXP; e++) g_w[b * NEXP + e] = wv[e];
        int s0 = atomicAdd(&g_cnt[e0], 1);
        int s1 = atomicAdd(&g_cnt[e1], 1);
        g_slot[2 * b]     = e0 * BTOK + s0;
        g_slot[2 * b + 1] = e1 * BTOK + s1;
        g_slotbe[b * NEXP + e0] = e0 * BTOK + s0;
        g_slotbe[b * NEXP + e1] = e1 * BTOK + s1;
        g_tope[2 * b] = e0; g_tope[2 * b + 1] = e1;
        g_topw[2 * b] = w0; g_topw[2 * b + 1] = w1;
    }
}

// ---------------- K1b: split proj weights into bf16 hi/lo ----------------
__global__ void k_convw(const float* __restrict__ pw) {
    size_t i = ((size_t)blockIdx.x * 256 + threadIdx.x) * 4;
    const size_t TOT = (size_t)NEXP * DDIM * DDIM;
    if (i >= TOT) return;
    float4 v = *(const float4*)&pw[i];
    __nv_bfloat16 h0 = __float2bfloat16(v.x), h1 = __float2bfloat16(v.y);
    __nv_bfloat16 h2 = __float2bfloat16(v.z), h3 = __float2bfloat16(v.w);
    __nv_bfloat16 l0 = __float2bfloat16(v.x - __bfloat162float(h0));
    __nv_bfloat16 l1 = __float2bfloat16(v.y - __bfloat162float(h1));
    __nv_bfloat16 l2 = __float2bfloat16(v.z - __bfloat162float(h2));
    __nv_bfloat16 l3 = __float2bfloat16(v.w - __bfloat162float(h3));
    *(__nv_bfloat162*)&g_pwh[i]     = __nv_bfloat162(h0, h1);
    *(__nv_bfloat162*)&g_pwh[i + 2] = __nv_bfloat162(h2, h3);
    *(__nv_bfloat162*)&g_pwl[i]     = __nv_bfloat162(l0, l1);
    *(__nv_bfloat162*)&g_pwl[i + 2] = __nv_bfloat162(l2, l3);
}

// ---------------- K2a: pos + rms1 + attention + out_proj + residual ----------------
#define A_IPW 0
#define A_OPW 13056
#define A_POS 17408
#define A_XS  18688
#define A_XN  19968
#define A_QKV 21248
#define A_O   25168
#define A_IPB 26448
#define A_OPB 26640
#define A_N1G 26704
#define A_LS1 26768
#define A_TOT 26832

__global__ void __launch_bounds__(256) k_exp_a(
    const float* __restrict__ x, const float* __restrict__ pos,
    const float* __restrict__ n1g,
    const float* __restrict__ ipw, const float* __restrict__ ipb,
    const float* __restrict__ opw, const float* __restrict__ opb,
    const float* __restrict__ ls1) {
    extern __shared__ float sm[];
    int e = blockIdx.y, g = blockIdx.x, t = threadIdx.x;
    int warp = t >> 5, lane = t & 31;
    for (int i = t; i < 192 * 64; i += 256) { int j = i >> 6, d = i & 63; sm[A_IPW + j * 68 + d] = ipw[(size_t)e * 192 * 64 + i]; }
    for (int i = t; i < 64 * 64; i += 256)  { int j = i >> 6, d = i & 63; sm[A_OPW + j * 68 + d] = opw[(size_t)e * 64 * 64 + i]; }
    for (int i = t; i < DDIM; i += 256) sm[A_POS + i] = pos[(size_t)e * DDIM + i];
    if (t < 192) sm[A_IPB + t] = ipb[e * 192 + t];
    if (t < 64) {
        sm[A_OPB + t] = opb[e * 64 + t];
        sm[A_N1G + t] = n1g[e * 64 + t];
        sm[A_LS1 + t] = ls1[e * 64 + t];
    }
    __syncthreads();

    for (int ti = 0; ti < TB; ti++) {
        int b = g * TB + ti;
        float wgt = g_w[b * NEXP + e];
        if (wgt == 0.f) continue;
        const float* xr = x + (size_t)b * DDIM;
        for (int i = t; i < DDIM; i += 256) sm[A_XS + i] = xr[i] + sm[A_POS + i];
        __syncthreads();
        for (int c = warp; c < NCH; c += 8) {
            float v0 = sm[A_XS + c * 64 + lane], v1 = sm[A_XS + c * 64 + 32 + lane];
            float ss = v0 * v0 + v1 * v1;
#pragma unroll
            for (int o = 16; o; o >>= 1) ss += __shfl_xor_sync(0xffffffffu, ss, o);
            float inv = 1.f / (sqrtf(ss * (1.f / 64.f)) + 1e-8f);
            sm[A_XN + c * 64 + lane]      = v0 * inv * sm[A_N1G + lane];
            sm[A_XN + c * 64 + 32 + lane] = v1 * inv * sm[A_N1G + 32 + lane];
        }
        __syncthreads();
        if (t < 192) {
            int j = t;
            float acc[NCH];
#pragma unroll
            for (int c = 0; c < NCH; c++) acc[c] = sm[A_IPB + j];
#pragma unroll
            for (int d = 0; d < 64; d += 4) {
                float4 wf = *(const float4*)&sm[A_IPW + j * 68 + d];
#pragma unroll
                for (int c = 0; c < NCH; c++) {
                    float4 xf = *(const float4*)&sm[A_XN + c * 64 + d];
                    acc[c] += wf.x * xf.x + wf.y * xf.y + wf.z * xf.z + wf.w * xf.w;
                }
            }
#pragma unroll
            for (int c = 0; c < NCH; c++) sm[A_QKV + c * 196 + j] = acc[c];
        }
        __syncthreads();
        {
            int h = warp >> 1;
            int c1base = (warp & 1) * 10;
            for (int cc = 0; cc < 10; cc++) {
                int c1 = c1base + cc;
                float sc = -1e30f;
                if (lane < NCH) {
                    float s = 0.f;
#pragma unroll
                    for (int d = 0; d < HDIM; d++)
                        s += sm[A_QKV + c1 * 196 + h * 16 + d] *
                             sm[A_QKV + lane * 196 + 64 + h * 16 + d];
                    sc = s * 0.25f;
                }
                float m = sc;
#pragma unroll
                for (int o = 16; o; o >>= 1) m = fmaxf(m, __shfl_xor_sync(0xffffffffu, m, o));
                float p = (lane < NCH) ? __expf(sc - m) : 0.f;
                float sum = p;
#pragma unroll
                for (int o = 16; o; o >>= 1) sum += __shfl_xor_sync(0xffffffffu, sum, o);
                float att = p / sum;
                float acc = 0.f;
#pragma unroll
                for (int c2 = 0; c2 < NCH; c2++) {
                    float a = __shfl_sync(0xffffffffu, att, c2);
                    if (lane < HDIM)
                        acc += a * sm[A_QKV + c2 * 196 + 128 + h * 16 + lane];
                }
                if (lane < HDIM)
                    sm[A_O + c1 * 64 + h * 16 + lane] = acc;
            }
        }
        __syncthreads();
        {
            int j = t & 63, cg = t >> 6;
            float acc[5];
#pragma unroll
            for (int i = 0; i < 5; i++) acc[i] = sm[A_OPB + j];
#pragma unroll
            for (int d = 0; d < 64; d += 4) {
                float4 wf = *(const float4*)&sm[A_OPW + j * 68 + d];
#pragma unroll
                for (int i = 0; i < 5; i++) {
                    int c = cg * 5 + i;
                    float4 xf = *(const float4*)&sm[A_O + c * 64 + d];
                    acc[i] += wf.x * xf.x + wf.y * xf.y + wf.z * xf.z + wf.w * xf.w;
                }
            }
            float* gout = g_xs + ((size_t)e * BTOK + b) * DDIM;
#pragma unroll
            for (int i = 0; i < 5; i++) {
                int c = cg * 5 + i;
                gout[c * 64 + j] = sm[A_XS + c * 64 + j] + sm[A_LS1 + j] * acc[i];
            }
        }
        __syncthreads();
    }
}

// ---------------- K2b: rms2 + FFN + residual, w-scale, bf16 hi/lo compact ----------------
#define B_FW1 0
#define B_FW2 17408
#define B_F1  34048
#define B_XS  39168
#define B_H2  40448
#define B_FB1 41728
#define B_FB2 41984
#define B_N2G 42048
#define B_LS2 42112
#define B_TOT 42176

__global__ void __launch_bounds__(256) k_exp_b(
    const float* __restrict__ n2g,
    const float* __restrict__ fw1, const float* __restrict__ fb1,
    const float* __restrict__ fw2, const float* __restrict__ fb2,
    const float* __restrict__ ls2) {
    extern __shared__ float sm[];
    int e = blockIdx.y, g = blockIdx.x, t = threadIdx.x;
    int warp = t >> 5, lane = t & 31;
    for (int i = t; i < 256 * 64; i += 256) { int j = i >> 6, d = i & 63; sm[B_FW1 + j * 68 + d] = fw1[(size_t)e * 256 * 64 + i]; }
    for (int i = t; i < 64 * 256; i += 256) { int j = i >> 8, d = i & 255; sm[B_FW2 + j * 260 + d] = fw2[(size_t)e * 64 * 256 + i]; }
    if (t < 256) sm[B_FB1 + t] = fb1[e * 256 + t];
    if (t < 64) {
        sm[B_FB2 + t] = fb2[e * 64 + t];
        sm[B_N2G + t] = n2g[e * 64 + t];
        sm[B_LS2 + t] = ls2[e * 64 + t];
    }
    __syncthreads();

    for (int ti = 0; ti < TB; ti++) {
        int b = g * TB + ti;
        float wgt = g_w[b * NEXP + e];
        if (wgt == 0.f) continue;
        const float* gin = g_xs + ((size_t)e * BTOK + b) * DDIM;
        for (int i = t; i < DDIM; i += 256) sm[B_XS + i] = gin[i];
        __syncthreads();
        for (int c = warp; c < NCH; c += 8) {
            float v0 = sm[B_XS + c * 64 + lane], v1 = sm[B_XS + c * 64 + 32 + lane];
            float ss = v0 * v0 + v1 * v1;
#pragma unroll
            for (int o = 16; o; o >>= 1) ss += __shfl_xor_sync(0xffffffffu, ss, o);
            float inv = 1.f / (sqrtf(ss * (1.f / 64.f)) + 1e-8f);
            sm[B_H2 + c * 64 + lane]      = v0 * inv * sm[B_N2G + lane];
            sm[B_H2 + c * 64 + 32 + lane] = v1 * inv * sm[B_N2G + 32 + lane];
        }
        __syncthreads();
        {
            int j = t;
            float acc[NCH];
#pragma unroll
            for (int c = 0; c < NCH; c++) acc[c] = sm[B_FB1 + j];
#pragma unroll
            for (int d = 0; d < 64; d += 4) {
                float4 wf = *(const float4*)&sm[B_FW1 + j * 68 + d];
#pragma unroll
                for (int c = 0; c < NCH; c++) {
                    float4 xf = *(const float4*)&sm[B_H2 + c * 64 + d];
                    acc[c] += wf.x * xf.x + wf.y * xf.y + wf.z * xf.z + wf.w * xf.w;
                }
            }
#pragma unroll
            for (int c = 0; c < NCH; c++) sm[B_F1 + c * 256 + j] = fmaxf(acc[c], 0.f);
        }
        __syncthreads();
        {
            int j = t & 63, cg = t >> 6;
            float acc[5];
#pragma unroll
            for (int i = 0; i < 5; i++) acc[i] = sm[B_FB2 + j];
            for (int d = 0; d < 256; d += 4) {
                float4 wf = *(const float4*)&sm[B_FW2 + j * 260 + d];
#pragma unroll
                for (int i = 0; i < 5; i++) {
                    int c = cg * 5 + i;
                    float4 xf = *(const float4*)&sm[B_F1 + c * 256 + d];
                    acc[i] += wf.x * xf.x + wf.y * xf.y + wf.z * xf.z + wf.w * xf.w;
                }
            }
            int slotg = g_slotbe[b * NEXP + e];
            __nv_bfloat16* gh = g_hbh + (size_t)slotg * DDIM;
            __nv_bfloat16* gl = g_hbl + (size_t)slotg * DDIM;
#pragma unroll
            for (int i = 0; i < 5; i++) {
                int c = cg * 5 + i;
                float v = wgt * (sm[B_XS + c * 64 + j] + sm[B_LS2 + j] * acc[i]);
                __nv_bfloat16 hi = __float2bfloat16(v);
                __nv_bfloat16 lo = __float2bfloat16(v - __bfloat162float(hi));
                gh[c * 64 + j] = hi;
                gl[c * 64 + j] = lo;
            }
        }
        __syncthreads();
    }
}

// ---------------- K3: warp-MMA bf16x3 dense proj GEMM per expert ----------------
// D[m][n] = Ahi*Bhi + Ahi*Blo + Alo*Bhi  (fp32 accum in registers)
// Block tile 128x128, K-chunk 32. 8 warps: 2(M) x 4(N), warp tile 64x32.
#define KC 32
#define SSTRIDE 40   // bf16 elems per smem row (32 + 8 pad) -> 80B, 16B-aligned

__global__ void __launch_bounds__(256) k_proj_mma() {
    int e  = blockIdx.y >> 6;
    int mt = blockIdx.y & 63;
    int nt = blockIdx.x;
    int cnt = g_cnt[e];
    int row0 = mt * 128;
    if (row0 >= cnt) return;

    __shared__ __nv_bfloat16 sAh[128 * SSTRIDE];
    __shared__ __nv_bfloat16 sAl[128 * SSTRIDE];
    __shared__ __nv_bfloat16 sBh[128 * SSTRIDE];
    __shared__ __nv_bfloat16 sBl[128 * SSTRIDE];

    int t = threadIdx.x;
    int wid = t >> 5, lane = t & 31;
    int wm = wid & 1, wn = wid >> 1;      // warp tile: rows wm*64.., cols wn*32..

    const __nv_bfloat16* Ah = g_hbh + (size_t)(e * BTOK) * DDIM;
    const __nv_bfloat16* Al = g_hbl + (size_t)(e * BTOK) * DDIM;
    const __nv_bfloat16* Bh = g_pwh + (size_t)e * DDIM * DDIM + (size_t)(nt * 128) * DDIM;
    const __nv_bfloat16* Bl = g_pwl + (size_t)e * DDIM * DDIM + (size_t)(nt * 128) * DDIM;

    float acc[4][4][4];
#pragma unroll
    for (int i = 0; i < 4; i++)
#pragma unroll
        for (int j = 0; j < 4; j++)
#pragma unroll
            for (int q = 0; q < 4; q++) acc[i][j][q] = 0.f;

    // per-thread load slots: 2 per matrix (512 uint4 per 128x32 tile)
    int rw0 = t >> 2,        q0 = t & 3;
    int rw1 = (t + 256) >> 2, q1 = (t + 256) & 3;
    bool v0 = (row0 + rw0) < cnt, v1 = (row0 + rw1) < cnt;
    const uint4 Z = make_uint4(0u, 0u, 0u, 0u);

    uint4 pAh0, pAh1, pAl0, pAl1, pBh0, pBh1, pBl0, pBl1;
#define LOADCHUNK(k0) do { \
        size_t a0 = (size_t)(row0 + rw0) * DDIM + (k0) + q0 * 8; \
        size_t a1 = (size_t)(row0 + rw1) * DDIM + (k0) + q1 * 8; \
        size_t b0 = (size_t)rw0 * DDIM + (k0) + q0 * 8; \
        size_t b1 = (size_t)rw1 * DDIM + (k0) + q1 * 8; \
        pAh0 = v0 ? *(const uint4*)(Ah + a0) : Z; \
        pAh1 = v1 ? *(const uint4*)(Ah + a1) : Z; \
        pAl0 = v0 ? *(const uint4*)(Al + a0) : Z; \
        pAl1 = v1 ? *(const uint4*)(Al + a1) : Z; \
        pBh0 = *(const uint4*)(Bh + b0); \
        pBh1 = *(const uint4*)(Bh + b1); \
        pBl0 = *(const uint4*)(Bl + b0); \
        pBl1 = *(const uint4*)(Bl + b1); \
    } while (0)

    int s0 = rw0 * 5 + q0, s1 = rw1 * 5 + q1;   // uint4 index (stride 5 per row)

    uint32_t sbAh = smem_u32(sAh), sbAl = smem_u32(sAl);
    uint32_t sbBh = smem_u32(sBh), sbBl = smem_u32(sBl);

    // ldmatrix lane addressing (byte offsets into smem, stride 80B/row)
    // A tile mt2: rows wm*64+mt2*16+(lane&15), k += ((lane>>4)<<3)
    int a_r = (lane & 15), a_k = ((lane >> 4) << 3);
    // B x4 over 2 n-tiles: rows np*16 + (lane&7) + ((lane>>4)<<3), k += (((lane>>3)&1)<<3)
    int b_r = (lane & 7) + ((lane >> 4) << 3), b_k = (((lane >> 3) & 1) << 3);

    LOADCHUNK(0);

    const int NCHUNK = DDIM / KC;     // 40
    for (int c = 0; c < NCHUNK; c++) {
        __syncthreads();
        ((uint4*)sAh)[s0] = pAh0; ((uint4*)sAh)[s1] = pAh1;
        ((uint4*)sAl)[s0] = pAl0; ((uint4*)sAl)[s1] = pAl1;
        ((uint4*)sBh)[s0] = pBh0; ((uint4*)sBh)[s1] = pBh1;
        ((uint4*)sBl)[s0] = pBl0; ((uint4*)sBl)[s1] = pBl1;
        __syncthreads();
        if (c + 1 < NCHUNK) LOADCHUNK((c + 1) * KC);   // overlaps MMA below

#pragma unroll
        for (int k16 = 0; k16 < 2; k16++) {
            int kb = k16 * 16;
            // B fragments: 4 n-tiles (2 ldmatrix.x4 per matrix)
            uint32_t bh[4][2], bl[4][2];
#pragma unroll
            for (int np = 0; np < 2; np++) {
                uint32_t boff = (uint32_t)((wn * 32 + np * 16 + b_r) * SSTRIDE + kb + b_k) * 2;
                ldm_x4(bh[np * 2][0], bh[np * 2][1], bh[np * 2 + 1][0], bh[np * 2 + 1][1], sbBh + boff);
                ldm_x4(bl[np * 2][0], bl[np * 2][1], bl[np * 2 + 1][0], bl[np * 2 + 1][1], sbBl + boff);
            }
#pragma unroll
            for (int mt2 = 0; mt2 < 4; mt2++) {
                uint32_t aoff = (uint32_t)((wm * 64 + mt2 * 16 + a_r) * SSTRIDE + kb + a_k) * 2;
                uint32_t ah[4], al[4];
                ldm_x4(ah[0], ah[1], ah[2], ah[3], sbAh + aoff);
                ldm_x4(al[0], al[1], al[2], al[3], sbAl + aoff);
#pragma unroll
                for (int ntl = 0; ntl < 4; ntl++) {
                    mma16816(acc[mt2][ntl], ah, bh[ntl]);
                    mma16816(acc[mt2][ntl], al, bh[ntl]);
                    mma16816(acc[mt2][ntl], ah, bl[ntl]);
                }
            }
        }
    }

    // epilogue
    int lrow = lane >> 2, lcol = (lane & 3) * 2;
    float* Ybase = g_y + (size_t)(e * BTOK) * DDIM;
#pragma unroll
    for (int mt2 = 0; mt2 < 4; mt2++) {
        int rbase = row0 + wm * 64 + mt2 * 16;
        int r1 = rbase + lrow, r2 = rbase + 8 + lrow;
#pragma unroll
        for (int ntl = 0; ntl < 4; ntl++) {
            int col = nt * 128 + wn * 32 + ntl * 8 + lcol;
            if (r1 < cnt) {
                float2 vv = make_float2(acc[mt2][ntl][0], acc[mt2][ntl][1]);
                *(float2*)&Ybase[(size_t)r1 * DDIM + col] = vv;
            }
            if (r2 < cnt) {
                float2 vv = make_float2(acc[mt2][ntl][2], acc[mt2][ntl][3]);
                *(float2*)&Ybase[(size_t)r2 * DDIM + col] = vv;
            }
        }
    }
}

// ---------------- K4: combine (+bias) + aux/load tail ----------------
__global__ void k_combine(const float* __restrict__ pb, float* __restrict__ out,
                          long long out_size) {
    long long idx = (long long)blockIdx.x * 256 + threadIdx.x;
    const long long TOT = (long long)BTOK * DDIM;
    if (idx < TOT) {
        int b = (int)(idx / DDIM), d = (int)(idx % DDIM);
        int s0 = g_slot[2 * b], s1 = g_slot[2 * b + 1];
        int e0 = g_tope[2 * b], e1 = g_tope[2 * b + 1];
        float v = g_y[(size_t)s0 * DDIM + d] + g_y[(size_t)s1 * DDIM + d]
                + g_topw[2 * b] * pb[e0 * DDIM + d]
                + g_topw[2 * b + 1] * pb[e1 * DDIM + d];
        out[idx] = v;
    }
    if (idx == 0 && out_size >= TOT + 5) {
        out[TOT] = 0.f;
#pragma unroll
        for (int e = 0; e < NEXP; e++) out[TOT + 1 + e] = (float)g_cnt[e];
    }
}

// ---------------- host launcher ----------------
extern "C" void kernel_launch(void* const* d_in, const int* in_sizes, int n_in,
                              void* d_out, int out_size) {
    const float* x    = (const float*)d_in[0];
    const float* gw1  = (const float*)d_in[1];
    const float* gb1  = (const float*)d_in[2];
    const float* gw2  = (const float*)d_in[3];
    const float* gb2  = (const float*)d_in[4];
    const float* pos  = (const float*)d_in[5];
    const float* n1g  = (const float*)d_in[6];
    const float* ipw  = (const float*)d_in[7];
    const float* ipb  = (const float*)d_in[8];
    const float* opw  = (const float*)d_in[9];
    const float* opb  = (const float*)d_in[10];
    const float* ls1  = (const float*)d_in[11];
    const float* n2g  = (const float*)d_in[12];
    const float* fw1  = (const float*)d_in[13];
    const float* fb1  = (const float*)d_in[14];
    const float* fw2  = (const float*)d_in[15];
    const float* fb2  = (const float*)d_in[16];
    const float* ls2  = (const float*)d_in[17];
    const float* pw   = (const float*)d_in[18];
    const float* pb   = (const float*)d_in[19];
    float* out = (float*)d_out;

    cudaFuncSetAttribute(k_exp_a, cudaFuncAttributeMaxDynamicSharedMemorySize, A_TOT * 4);
    cudaFuncSetAttribute(k_exp_b, cudaFuncAttributeMaxDynamicSharedMemorySize, B_TOT * 4);

    k_init<<<1, 32>>>();
    k_gate<<<BTOK / 8, 256>>>(x, gw1, gb1, gw2, gb2);
    {
        size_t tot4 = (size_t)NEXP * DDIM * DDIM / 4;
        k_convw<<<(unsigned)((tot4 + 255) / 256), 256>>>(pw);
    }
    k_exp_a<<<dim3(BTOK / TB, NEXP), 256, A_TOT * 4>>>(x, pos, n1g, ipw, ipb, opw, opb, ls1);
    k_exp_b<<<dim3(BTOK / TB, NEXP), 256, B_TOT * 4>>>(n2g, fw1, fb1, fw2, fb2, ls2);
    k_proj_mma<<<dim3(DDIM / 128, NEXP * 64), 256>>>();
    long long tot = (long long)BTOK * DDIM;
    k_combine<<<(unsigned)((tot + 255) / 256), 256>>>(pb, out, (long long)out_size);
}

// round 5
// speedup vs baseline: 1.9763x; 1.6239x over previous
#include <cuda_runtime.h>
#include <cuda_bf16.h>
#include <math.h>
#include <cstdint>

// ---------------- problem constants ----------------
#define BTOK 8192
#define DDIM 1280
#define NEXP 4
#define NCH  20
#define CDIM 64
#define NHEAD 4
#define HDIM 16
#define FFH  256
#define TB   16      // tokens per expert-block

// ---------------- device scratch (allocation-free) ----------------
__device__ float g_w[BTOK * NEXP];          // combine weights (0 for unselected)
__device__ float g_wslot[NEXP * BTOK];      // slot -> combine weight
__device__ int   g_cnt[NEXP];               // per-expert token counts
__device__ int   g_slot[2 * BTOK];          // token -> global slot (e*B + slot)
__device__ int   g_slotbe[BTOK * NEXP];     // (token,expert) -> global slot
__device__ int   g_tope[2 * BTOK];          // token -> expert ids (top2)
__device__ float g_topw[2 * BTOK];          // token -> weights (top2)
__device__ float g_xs[(size_t)NEXP * BTOK * DDIM];   // post-attn residual (slot-major)
__device__ __nv_bfloat16 g_hbh[(size_t)NEXP * BTOK * DDIM]; // compact hidden, hi
__device__ __nv_bfloat16 g_hbl[(size_t)NEXP * BTOK * DDIM]; // compact hidden, lo
__device__ __nv_bfloat16 g_pwh[(size_t)NEXP * DDIM * DDIM]; // proj weight hi
__device__ __nv_bfloat16 g_pwl[(size_t)NEXP * DDIM * DDIM]; // proj weight lo
__device__ __nv_bfloat16 g_fw1b[NEXP * FFH * CDIM];  // ffn w1 bf16
__device__ __nv_bfloat16 g_fw2b[NEXP * CDIM * FFH];  // ffn w2 bf16
__device__ float g_y [(size_t)NEXP * BTOK * DDIM];   // per-slot proj output

// ---------------- warp MMA helpers (baseline PTX, OK on plain sm_103) -------
__device__ __forceinline__ uint32_t smem_u32(const void* p) {
    uint32_t a;
    asm("{ .reg .u64 t; cvta.to.shared.u64 t, %1; cvt.u32.u64 %0, t; }" : "=r"(a) : "l"(p));
    return a;
}
__device__ __forceinline__ void ldm_x4(uint32_t& r0, uint32_t& r1, uint32_t& r2, uint32_t& r3,
                                       uint32_t addr) {
    asm volatile("ldmatrix.sync.aligned.m8n8.x4.shared.b16 {%0,%1,%2,%3}, [%4];"
                 : "=r"(r0), "=r"(r1), "=r"(r2), "=r"(r3) : "r"(addr));
}
__device__ __forceinline__ void mma16816(float* d, const uint32_t* a, const uint32_t* b) {
    asm volatile("mma.sync.aligned.m16n8k16.row.col.f32.bf16.bf16.f32 "
                 "{%0,%1,%2,%3}, {%4,%5,%6,%7}, {%8,%9}, {%0,%1,%2,%3};"
                 : "+f"(d[0]), "+f"(d[1]), "+f"(d[2]), "+f"(d[3])
                 : "r"(a[0]), "r"(a[1]), "r"(a[2]), "r"(a[3]), "r"(b[0]), "r"(b[1]));
}

// ---------------- K0: init ----------------
__global__ void k_init() {
    if (threadIdx.x < NEXP) g_cnt[threadIdx.x] = 0;
}

// ---------------- K1: gating + routing ----------------
__global__ void k_gate(const float* __restrict__ x,
                       const float* __restrict__ gw1, const float* __restrict__ gb1,
                       const float* __restrict__ gw2, const float* __restrict__ gb2) {
    __shared__ float s_x[8][DDIM];
    int warp = threadIdx.x >> 5, lane = threadIdx.x & 31;
    int b = blockIdx.x * 8 + warp;
    const float* xr = x + (size_t)b * DDIM;
    for (int d = lane; d < DDIM; d += 32) s_x[warp][d] = xr[d];
    __syncwarp();
    float h1[16];
#pragma unroll
    for (int j = 0; j < 16; j++) {
        float s = 0.f;
        const float* wr = gw1 + j * DDIM;
        for (int d = lane; d < DDIM; d += 32) s += s_x[warp][d] * wr[d];
#pragma unroll
        for (int o = 16; o; o >>= 1) s += __shfl_xor_sync(0xffffffffu, s, o);
        h1[j] = tanhf(s + gb1[j]);
    }
    if (lane == 0) {
        float logits[NEXP];
#pragma unroll
        for (int e = 0; e < NEXP; e++) {
            float s = gb2[e];
#pragma unroll
            for (int j = 0; j < 16; j++) s += h1[j] * gw2[e * 16 + j];
            logits[e] = s;
        }
        float m = logits[0];
#pragma unroll
        for (int e = 1; e < NEXP; e++) m = fmaxf(m, logits[e]);
        float p[NEXP], sum = 0.f;
#pragma unroll
        for (int e = 0; e < NEXP; e++) { p[e] = expf(logits[e] - m); sum += p[e]; }
#pragma unroll
        for (int e = 0; e < NEXP; e++) p[e] /= sum;
        int e0 = 0;
#pragma unroll
        for (int e = 1; e < NEXP; e++) if (p[e] > p[e0]) e0 = e;
        int e1 = -1;
#pragma unroll
        for (int e = 0; e < NEXP; e++) {
            if (e == e0) continue;
            if (e1 < 0 || p[e] > p[e1]) e1 = e;
        }
        float den = p[e0] + p[e1] + 1e-6f;
        float w0 = p[e0] / den, w1 = p[e1] / den;
        float wv[NEXP] = {0.f, 0.f, 0.f, 0.f};
        wv[e0] = w0; wv[e1] = w1;
#pragma unroll
        for (int e = 0; e < NEXP; e++) g_w[b * NEXP + e] = wv[e];
        int s0 = atomicAdd(&g_cnt[e0], 1);
        int s1 = atomicAdd(&g_cnt[e1], 1);
        g_slot[2 * b]     = e0 * BTOK + s0;
        g_slot[2 * b + 1] = e1 * BTOK + s1;
        g_slotbe[b * NEXP + e0] = e0 * BTOK + s0;
        g_slotbe[b * NEXP + e1] = e1 * BTOK + s1;
        g_wslot[e0 * BTOK + s0] = w0;
        g_wslot[e1 * BTOK + s1] = w1;
        g_tope[2 * b] = e0; g_tope[2 * b + 1] = e1;
        g_topw[2 * b] = w0; g_topw[2 * b + 1] = w1;
    }
}

// ---------------- K1b: split proj weights into bf16 hi/lo ----------------
__global__ void k_convw(const float* __restrict__ pw) {
    size_t i = ((size_t)blockIdx.x * 256 + threadIdx.x) * 4;
    const size_t TOT = (size_t)NEXP * DDIM * DDIM;
    if (i >= TOT) return;
    float4 v = *(const float4*)&pw[i];
    __nv_bfloat16 h0 = __float2bfloat16(v.x), h1 = __float2bfloat16(v.y);
    __nv_bfloat16 h2 = __float2bfloat16(v.z), h3 = __float2bfloat16(v.w);
    __nv_bfloat16 l0 = __float2bfloat16(v.x - __bfloat162float(h0));
    __nv_bfloat16 l1 = __float2bfloat16(v.y - __bfloat162float(h1));
    __nv_bfloat16 l2 = __float2bfloat16(v.z - __bfloat162float(h2));
    __nv_bfloat16 l3 = __float2bfloat16(v.w - __bfloat162float(h3));
    *(__nv_bfloat162*)&g_pwh[i]     = __nv_bfloat162(h0, h1);
    *(__nv_bfloat162*)&g_pwh[i + 2] = __nv_bfloat162(h2, h3);
    *(__nv_bfloat162*)&g_pwl[i]     = __nv_bfloat162(l0, l1);
    *(__nv_bfloat162*)&g_pwl[i + 2] = __nv_bfloat162(l2, l3);
}

// ---------------- K1c: convert FFN weights to bf16 ----------------
__global__ void k_convb(const float* __restrict__ fw1, const float* __restrict__ fw2) {
    int i = blockIdx.x * 256 + threadIdx.x;
    const int TOT = NEXP * FFH * CDIM;   // 65536 (same for both)
    if (i < TOT) {
        g_fw1b[i] = __float2bfloat16(fw1[i]);
        g_fw2b[i] = __float2bfloat16(fw2[i]);
    }
}

// ---------------- K2a: pos + rms1 + attention + out_proj + residual ----------------
#define A_IPW 0
#define A_OPW 13056
#define A_POS 17408
#define A_XS  18688
#define A_XN  19968
#define A_QKV 21248
#define A_O   25168
#define A_IPB 26448
#define A_OPB 26640
#define A_N1G 26704
#define A_LS1 26768
#define A_TOT 26832

__global__ void __launch_bounds__(256) k_exp_a(
    const float* __restrict__ x, const float* __restrict__ pos,
    const float* __restrict__ n1g,
    const float* __restrict__ ipw, const float* __restrict__ ipb,
    const float* __restrict__ opw, const float* __restrict__ opb,
    const float* __restrict__ ls1) {
    extern __shared__ float sm[];
    int e = blockIdx.y, g = blockIdx.x, t = threadIdx.x;
    int warp = t >> 5, lane = t & 31;
    for (int i = t; i < 192 * 64; i += 256) { int j = i >> 6, d = i & 63; sm[A_IPW + j * 68 + d] = ipw[(size_t)e * 192 * 64 + i]; }
    for (int i = t; i < 64 * 64; i += 256)  { int j = i >> 6, d = i & 63; sm[A_OPW + j * 68 + d] = opw[(size_t)e * 64 * 64 + i]; }
    for (int i = t; i < DDIM; i += 256) sm[A_POS + i] = pos[(size_t)e * DDIM + i];
    if (t < 192) sm[A_IPB + t] = ipb[e * 192 + t];
    if (t < 64) {
        sm[A_OPB + t] = opb[e * 64 + t];
        sm[A_N1G + t] = n1g[e * 64 + t];
        sm[A_LS1 + t] = ls1[e * 64 + t];
    }
    __syncthreads();

    for (int ti = 0; ti < TB; ti++) {
        int b = g * TB + ti;
        float wgt = g_w[b * NEXP + e];
        if (wgt == 0.f) continue;
        const float* xr = x + (size_t)b * DDIM;
        for (int i = t; i < DDIM; i += 256) sm[A_XS + i] = xr[i] + sm[A_POS + i];
        __syncthreads();
        for (int c = warp; c < NCH; c += 8) {
            float v0 = sm[A_XS + c * 64 + lane], v1 = sm[A_XS + c * 64 + 32 + lane];
            float ss = v0 * v0 + v1 * v1;
#pragma unroll
            for (int o = 16; o; o >>= 1) ss += __shfl_xor_sync(0xffffffffu, ss, o);
            float inv = 1.f / (sqrtf(ss * (1.f / 64.f)) + 1e-8f);
            sm[A_XN + c * 64 + lane]      = v0 * inv * sm[A_N1G + lane];
            sm[A_XN + c * 64 + 32 + lane] = v1 * inv * sm[A_N1G + 32 + lane];
        }
        __syncthreads();
        if (t < 192) {
            int j = t;
            float acc[NCH];
#pragma unroll
            for (int c = 0; c < NCH; c++) acc[c] = sm[A_IPB + j];
#pragma unroll
            for (int d = 0; d < 64; d += 4) {
                float4 wf = *(const float4*)&sm[A_IPW + j * 68 + d];
#pragma unroll
                for (int c = 0; c < NCH; c++) {
                    float4 xf = *(const float4*)&sm[A_XN + c * 64 + d];
                    acc[c] += wf.x * xf.x + wf.y * xf.y + wf.z * xf.z + wf.w * xf.w;
                }
            }
#pragma unroll
            for (int c = 0; c < NCH; c++) sm[A_QKV + c * 196 + j] = acc[c];
        }
        __syncthreads();
        {
            int h = warp >> 1;
            int c1base = (warp & 1) * 10;
            for (int cc = 0; cc < 10; cc++) {
                int c1 = c1base + cc;
                float sc = -1e30f;
                if (lane < NCH) {
                    float s = 0.f;
#pragma unroll
                    for (int d = 0; d < HDIM; d++)
                        s += sm[A_QKV + c1 * 196 + h * 16 + d] *
                             sm[A_QKV + lane * 196 + 64 + h * 16 + d];
                    sc = s * 0.25f;
                }
                float m = sc;
#pragma unroll
                for (int o = 16; o; o >>= 1) m = fmaxf(m, __shfl_xor_sync(0xffffffffu, m, o));
                float p = (lane < NCH) ? __expf(sc - m) : 0.f;
                float sum = p;
#pragma unroll
                for (int o = 16; o; o >>= 1) sum += __shfl_xor_sync(0xffffffffu, sum, o);
                float att = p / sum;
                float acc = 0.f;
#pragma unroll
                for (int c2 = 0; c2 < NCH; c2++) {
                    float a = __shfl_sync(0xffffffffu, att, c2);
                    if (lane < HDIM)
                        acc += a * sm[A_QKV + c2 * 196 + 128 + h * 16 + lane];
                }
                if (lane < HDIM)
                    sm[A_O + c1 * 64 + h * 16 + lane] = acc;
            }
        }
        __syncthreads();
        {
            int j = t & 63, cg = t >> 6;
            float acc[5];
#pragma unroll
            for (int i = 0; i < 5; i++) acc[i] = sm[A_OPB + j];
#pragma unroll
            for (int d = 0; d < 64; d += 4) {
                float4 wf = *(const float4*)&sm[A_OPW + j * 68 + d];
#pragma unroll
                for (int i = 0; i < 5; i++) {
                    int c = cg * 5 + i;
                    float4 xf = *(const float4*)&sm[A_O + c * 64 + d];
                    acc[i] += wf.x * xf.x + wf.y * xf.y + wf.z * xf.z + wf.w * xf.w;
                }
            }
            int slotg = g_slotbe[b * NEXP + e];
            float* gout = g_xs + (size_t)slotg * DDIM;   // slot-major!
#pragma unroll
            for (int i = 0; i < 5; i++) {
                int c = cg * 5 + i;
                gout[c * 64 + j] = sm[A_XS + c * 64 + j] + sm[A_LS1 + j] * acc[i];
            }
        }
        __syncthreads();
    }
}

// ---------------- K2b: warp-MMA FFN over compact chunk-rows ----------------
// rows: r in [0, cnt*20) of expert e; row r = slot r/20, chunk r%20
// smem byte offsets
#define F_XS   0          // 128x64 f32      (32768)
#define F_XN   32768      // 128x72 bf16     (18432)
#define F_F1   51200      // 128x264 bf16    (67584)
#define F_W1   118784     // 256x72 bf16     (36864)
#define F_W2   155648     // 64x264 bf16     (33792)
#define F_N2G  189440     // 64 f
#define F_FB1  189696     // 256 f
#define F_FB2  190720     // 64 f
#define F_LS2  190976     // 64 f
#define F_WGT  191232     // 128 f
#define F_TOT  191744

__global__ void __launch_bounds__(256) k_ffn(
    const float* __restrict__ n2g, const float* __restrict__ fb1,
    const float* __restrict__ fb2, const float* __restrict__ ls2) {
    int e  = blockIdx.y;
    int r0 = blockIdx.x * 128;
    int rows_e = g_cnt[e] * NCH;
    if (r0 >= rows_e) return;

    extern __shared__ char smb[];
    float*          sXS  = (float*)(smb + F_XS);
    __nv_bfloat16*  sXN  = (__nv_bfloat16*)(smb + F_XN);
    __nv_bfloat16*  sF1  = (__nv_bfloat16*)(smb + F_F1);
    __nv_bfloat16*  sW1  = (__nv_bfloat16*)(smb + F_W1);
    __nv_bfloat16*  sW2  = (__nv_bfloat16*)(smb + F_W2);
    float*          sN2G = (float*)(smb + F_N2G);
    float*          sFB1 = (float*)(smb + F_FB1);
    float*          sFB2 = (float*)(smb + F_FB2);
    float*          sLS2 = (float*)(smb + F_LS2);
    float*          sWGT = (float*)(smb + F_WGT);

    int t = threadIdx.x, wid = t >> 5, lane = t & 31;

    // ---- staging ----
    {
        const __nv_bfloat16* w1g = g_fw1b + e * FFH * CDIM;
        const __nv_bfloat16* w2g = g_fw2b + e * CDIM * FFH;
        const float* xsg = g_xs + (size_t)e * BTOK * DDIM + (size_t)r0 * 64;
#pragma unroll
        for (int i = t; i < 2048; i += 256) {           // fw1: 256 rows x 64
            int j = i >> 3, sg = i & 7;
            *(uint4*)(sW1 + j * 72 + sg * 8) = *(const uint4*)(w1g + j * 64 + sg * 8);
        }
#pragma unroll
        for (int i = t; i < 2048; i += 256) {           // fw2: 64 rows x 256
            int n = i >> 5, sg = i & 31;
            *(uint4*)(sW2 + n * 264 + sg * 8) = *(const uint4*)(w2g + n * 256 + sg * 8);
        }
#pragma unroll
        for (int i = t; i < 2048; i += 256) {           // xs: 128 rows x 64 f32
            int r = i >> 4, sg = i & 15;
            *(float4*)(sXS + r * 64 + sg * 4) = *(const float4*)(xsg + (size_t)r * 64 + sg * 4);
        }
        if (t < 64) { sN2G[t] = n2g[e * 64 + t]; sFB2[t] = fb2[e * 64 + t]; sLS2[t] = ls2[e * 64 + t]; }
        if (t < 256) sFB1[t] = fb1[e * 256 + t];
        if (t < 128) {
            int rr = r0 + t;
            sWGT[t] = (rr < rows_e) ? g_wslot[e * BTOK + rr / 20] : 0.f;
        }
    }
    __syncthreads();

    // ---- rms2 -> xn bf16 ----
    {
#pragma unroll
        for (int i = 0; i < 16; i++) {
            int r = wid * 16 + i;
            float v0 = sXS[r * 64 + lane], v1 = sXS[r * 64 + 32 + lane];
            float ss = v0 * v0 + v1 * v1;
#pragma unroll
            for (int o = 16; o; o >>= 1) ss += __shfl_xor_sync(0xffffffffu, ss, o);
            float inv = 1.f / (sqrtf(ss * (1.f / 64.f)) + 1e-8f);
            sXN[r * 72 + lane]      = __float2bfloat16(v0 * inv * sN2G[lane]);
            sXN[r * 72 + 32 + lane] = __float2bfloat16(v1 * inv * sN2G[32 + lane]);
        }
    }
    __syncthreads();

    uint32_t sbXN = smem_u32(sXN), sbW1 = smem_u32(sW1);
    uint32_t sbF1 = smem_u32(sF1), sbW2 = smem_u32(sW2);
    int a_r = (lane & 15), a_k = ((lane >> 4) << 3);
    int b_r = (lane & 7) + ((lane >> 4) << 3), b_k = (((lane >> 3) & 1) << 3);

    // ---- ffn1: [128,64] x [256,64]^T -> relu -> f1 bf16 ----
    {
        int wm = wid & 1, wn = wid >> 1;     // 2 x 4
#pragma unroll
        for (int nh = 0; nh < 2; nh++) {
            float acc[4][4][4];
#pragma unroll
            for (int i = 0; i < 4; i++)
#pragma unroll
                for (int j = 0; j < 4; j++)
#pragma unroll
                    for (int q = 0; q < 4; q++) acc[i][j][q] = 0.f;
#pragma unroll
            for (int k16 = 0; k16 < 4; k16++) {
                int kb = k16 * 16;
                uint32_t bh[4][2];
#pragma unroll
                for (int np = 0; np < 2; np++) {
                    uint32_t boff = (uint32_t)((nh * 128 + wn * 32 + np * 16 + b_r) * 72 + kb + b_k) * 2;
                    ldm_x4(bh[np * 2][0], bh[np * 2][1], bh[np * 2 + 1][0], bh[np * 2 + 1][1], sbW1 + boff);
                }
#pragma unroll
                for (int mt2 = 0; mt2 < 4; mt2++) {
                    uint32_t aoff = (uint32_t)((wm * 64 + mt2 * 16 + a_r) * 72 + kb + a_k) * 2;
                    uint32_t ah[4];
                    ldm_x4(ah[0], ah[1], ah[2], ah[3], sbXN + aoff);
#pragma unroll
                    for (int ntl = 0; ntl < 4; ntl++) mma16816(acc[mt2][ntl], ah, bh[ntl]);
                }
            }
            // epilogue: +bias, relu, bf16 pack -> sF1
#pragma unroll
            for (int mt2 = 0; mt2 < 4; mt2++) {
#pragma unroll
                for (int ntl = 0; ntl < 4; ntl++) {
                    int col = nh * 128 + wn * 32 + ntl * 8 + (lane & 3) * 2;
                    int r1 = wm * 64 + mt2 * 16 + (lane >> 2), r2 = r1 + 8;
                    float b0 = sFB1[col], b1 = sFB1[col + 1];
                    float c0 = fmaxf(acc[mt2][ntl][0] + b0, 0.f);
                    float c1 = fmaxf(acc[mt2][ntl][1] + b1, 0.f);
                    float c2 = fmaxf(acc[mt2][ntl][2] + b0, 0.f);
                    float c3 = fmaxf(acc[mt2][ntl][3] + b1, 0.f);
                    *(__nv_bfloat162*)(sF1 + r1 * 264 + col) = __float22bfloat162_rn(make_float2(c0, c1));
                    *(__nv_bfloat162*)(sF1 + r2 * 264 + col) = __float22bfloat162_rn(make_float2(c2, c3));
                }
            }
        }
    }
    __syncthreads();

    // ---- ffn2: [128,256] x [64,256]^T + residual + scale + hi/lo split ----
    {
        int wm2 = wid & 3, wn2 = wid >> 2;   // 4 x 2
        float acc2[2][4][4];
#pragma unroll
        for (int i = 0; i < 2; i++)
#pragma unroll
            for (int j = 0; j < 4; j++)
#pragma unroll
                for (int q = 0; q < 4; q++) acc2[i][j][q] = 0.f;
#pragma unroll
        for (int k16 = 0; k16 < 16; k16++) {
            int kb = k16 * 16;
            uint32_t bh[4][2];
#pragma unroll
            for (int np = 0; np < 2; np++) {
                uint32_t boff = (uint32_t)((wn2 * 32 + np * 16 + b_r) * 264 + kb + b_k) * 2;
                ldm_x4(bh[np * 2][0], bh[np * 2][1], bh[np * 2 + 1][0], bh[np * 2 + 1][1], sbW2 + boff);
            }
#pragma unroll
            for (int mt2 = 0; mt2 < 2; mt2++) {
                uint32_t aoff = (uint32_t)((wm2 * 32 + mt2 * 16 + a_r) * 264 + kb + a_k) * 2;
                uint32_t ah[4];
                ldm_x4(ah[0], ah[1], ah[2], ah[3], sbF1 + aoff);
#pragma unroll
                for (int ntl = 0; ntl < 4; ntl++) mma16816(acc2[mt2][ntl], ah, bh[ntl]);
            }
        }
        // epilogue
        __nv_bfloat16* ghb = g_hbh + (size_t)e * BTOK * DDIM + (size_t)r0 * 64;
        __nv_bfloat16* glb = g_hbl + (size_t)e * BTOK * DDIM + (size_t)r0 * 64;
#pragma unroll
        for (int mt2 = 0; mt2 < 2; mt2++) {
#pragma unroll
            for (int ntl = 0; ntl < 4; ntl++) {
                int col = wn2 * 32 + ntl * 8 + (lane & 3) * 2;
                float b0 = sFB2[col], b1 = sFB2[col + 1];
                float l0 = sLS2[col], l1 = sLS2[col + 1];
#pragma unroll
                for (int half = 0; half < 2; half++) {
                    int r = wm2 * 32 + mt2 * 16 + (lane >> 2) + half * 8;
                    if (r0 + r < rows_e) {
                        float w = sWGT[r];
                        float v0 = w * (sXS[r * 64 + col]     + l0 * (acc2[mt2][ntl][half * 2]     + b0));
                        float v1 = w * (sXS[r * 64 + col + 1] + l1 * (acc2[mt2][ntl][half * 2 + 1] + b1));
                        __nv_bfloat16 h0 = __float2bfloat16(v0), h1 = __float2bfloat16(v1);
                        __nv_bfloat16 q0 = __float2bfloat16(v0 - __bfloat162float(h0));
                        __nv_bfloat16 q1 = __float2bfloat16(v1 - __bfloat162float(h1));
                        *(__nv_bfloat162*)(ghb + (size_t)r * 64 + col) = __nv_bfloat162(h0, h1);
                        *(__nv_bfloat162*)(glb + (size_t)r * 64 + col) = __nv_bfloat162(q0, q1);
                    }
                }
            }
        }
    }
}

// ---------------- K3: warp-MMA bf16x3 dense proj GEMM per expert ----------------
#define KC 32
#define SSTRIDE 40   // bf16 elems per smem row (32 + 8 pad) -> 80B, 16B-aligned

__global__ void __launch_bounds__(256) k_proj_mma() {
    int e  = blockIdx.y >> 6;
    int mt = blockIdx.y & 63;
    int nt = blockIdx.x;
    int cnt = g_cnt[e];
    int row0 = mt * 128;
    if (row0 >= cnt) return;

    __shared__ __nv_bfloat16 sAh[128 * SSTRIDE];
    __shared__ __nv_bfloat16 sAl[128 * SSTRIDE];
    __shared__ __nv_bfloat16 sBh[128 * SSTRIDE];
    __shared__ __nv_bfloat16 sBl[128 * SSTRIDE];

    int t = threadIdx.x;
    int wid = t >> 5, lane = t & 31;
    int wm = wid & 1, wn = wid >> 1;

    const __nv_bfloat16* Ah = g_hbh + (size_t)(e * BTOK) * DDIM;
    const __nv_bfloat16* Al = g_hbl + (size_t)(e * BTOK) * DDIM;
    const __nv_bfloat16* Bh = g_pwh + (size_t)e * DDIM * DDIM + (size_t)(nt * 128) * DDIM;
    const __nv_bfloat16* Bl = g_pwl + (size_t)e * DDIM * DDIM + (size_t)(nt * 128) * DDIM;

    float acc[4][4][4];
#pragma unroll
    for (int i = 0; i < 4; i++)
#pragma unroll
        for (int j = 0; j < 4; j++)
#pragma unroll
            for (int q = 0; q < 4; q++) acc[i][j][q] = 0.f;

    int rw0 = t >> 2,        q0 = t & 3;
    int rw1 = (t + 256) >> 2, q1 = (t + 256) & 3;
    bool v0 = (row0 + rw0) < cnt, v1 = (row0 + rw1) < cnt;
    const uint4 Z = make_uint4(0u, 0u, 0u, 0u);

    uint4 pAh0, pAh1, pAl0, pAl1, pBh0, pBh1, pBl0, pBl1;
#define LOADCHUNK(k0) do { \
        size_t a0 = (size_t)(row0 + rw0) * DDIM + (k0) + q0 * 8; \
        size_t a1 = (size_t)(row0 + rw1) * DDIM + (k0) + q1 * 8; \
        size_t b0 = (size_t)rw0 * DDIM + (k0) + q0 * 8; \
        size_t b1 = (size_t)rw1 * DDIM + (k0) + q1 * 8; \
        pAh0 = v0 ? *(const uint4*)(Ah + a0) : Z; \
        pAh1 = v1 ? *(const uint4*)(Ah + a1) : Z; \
        pAl0 = v0 ? *(const uint4*)(Al + a0) : Z; \
        pAl1 = v1 ? *(const uint4*)(Al + a1) : Z; \
        pBh0 = *(const uint4*)(Bh + b0); \
        pBh1 = *(const uint4*)(Bh + b1); \
        pBl0 = *(const uint4*)(Bl + b0); \
        pBl1 = *(const uint4*)(Bl + b1); \
    } while (0)

    int s0 = rw0 * 5 + q0, s1 = rw1 * 5 + q1;

    uint32_t sbAh = smem_u32(sAh), sbAl = smem_u32(sAl);
    uint32_t sbBh = smem_u32(sBh), sbBl = smem_u32(sBl);

    int a_r = (lane & 15), a_k = ((lane >> 4) << 3);
    int b_r = (lane & 7) + ((lane >> 4) << 3), b_k = (((lane >> 3) & 1) << 3);

    LOADCHUNK(0);

    const int NCHUNK = DDIM / KC;     // 40
    for (int c = 0; c < NCHUNK; c++) {
        __syncthreads();
        ((uint4*)sAh)[s0] = pAh0; ((uint4*)sAh)[s1] = pAh1;
        ((uint4*)sAl)[s0] = pAl0; ((uint4*)sAl)[s1] = pAl1;
        ((uint4*)sBh)[s0] = pBh0; ((uint4*)sBh)[s1] = pBh1;
        ((uint4*)sBl)[s0] = pBl0; ((uint4*)sBl)[s1] = pBl1;
        __syncthreads();
        if (c + 1 < NCHUNK) LOADCHUNK((c + 1) * KC);

#pragma unroll
        for (int k16 = 0; k16 < 2; k16++) {
            int kb = k16 * 16;
            uint32_t bh[4][2], bl[4][2];
#pragma unroll
            for (int np = 0; np < 2; np++) {
                uint32_t boff = (uint32_t)((wn * 32 + np * 16 + b_r) * SSTRIDE + kb + b_k) * 2;
                ldm_x4(bh[np * 2][0], bh[np * 2][1], bh[np * 2 + 1][0], bh[np * 2 + 1][1], sbBh + boff);
                ldm_x4(bl[np * 2][0], bl[np * 2][1], bl[np * 2 + 1][0], bl[np * 2 + 1][1], sbBl + boff);
            }
#pragma unroll
            for (int mt2 = 0; mt2 < 4; mt2++) {
                uint32_t aoff = (uint32_t)((wm * 64 + mt2 * 16 + a_r) * SSTRIDE + kb + a_k) * 2;
                uint32_t ah[4], al[4];
                ldm_x4(ah[0], ah[1], ah[2], ah[3], sbAh + aoff);
                ldm_x4(al[0], al[1], al[2], al[3], sbAl + aoff);
#pragma unroll
                for (int ntl = 0; ntl < 4; ntl++) {
                    mma16816(acc[mt2][ntl], ah, bh[ntl]);
                    mma16816(acc[mt2][ntl], al, bh[ntl]);
                    mma16816(acc[mt2][ntl], ah, bl[ntl]);
                }
            }
        }
    }

    int lrow = lane >> 2, lcol = (lane & 3) * 2;
    float* Ybase = g_y + (size_t)(e * BTOK) * DDIM;
#pragma unroll
    for (int mt2 = 0; mt2 < 4; mt2++) {
        int rbase = row0 + wm * 64 + mt2 * 16;
        int r1 = rbase + lrow, r2 = rbase + 8 + lrow;
#pragma unroll
        for (int ntl = 0; ntl < 4; ntl++) {
            int col = nt * 128 + wn * 32 + ntl * 8 + lcol;
            if (r1 < cnt) {
                float2 vv = make_float2(acc[mt2][ntl][0], acc[mt2][ntl][1]);
                *(float2*)&Ybase[(size_t)r1 * DDIM + col] = vv;
            }
            if (r2 < cnt) {
                float2 vv = make_float2(acc[mt2][ntl][2], acc[mt2][ntl][3]);
                *(float2*)&Ybase[(size_t)r2 * DDIM + col] = vv;
            }
        }
    }
}

// ---------------- K4: combine (+bias) + aux/load tail ----------------
__global__ void k_combine(const float* __restrict__ pb, float* __restrict__ out,
                          long long out_size) {
    long long idx = (long long)blockIdx.x * 256 + threadIdx.x;
    const long long TOT = (long long)BTOK * DDIM;
    if (idx < TOT) {
        int b = (int)(idx / DDIM), d = (int)(idx % DDIM);
        int s0 = g_slot[2 * b], s1 = g_slot[2 * b + 1];
        int e0 = g_tope[2 * b], e1 = g_tope[2 * b + 1];
        float v = g_y[(size_t)s0 * DDIM + d] + g_y[(size_t)s1 * DDIM + d]
                + g_topw[2 * b] * pb[e0 * DDIM + d]
                + g_topw[2 * b + 1] * pb[e1 * DDIM + d];
        out[idx] = v;
    }
    if (idx == 0 && out_size >= TOT + 5) {
        out[TOT] = 0.f;
#pragma unroll
        for (int e = 0; e < NEXP; e++) out[TOT + 1 + e] = (float)g_cnt[e];
    }
}

// ---------------- host launcher ----------------
extern "C" void kernel_launch(void* const* d_in, const int* in_sizes, int n_in,
                              void* d_out, int out_size) {
    const float* x    = (const float*)d_in[0];
    const float* gw1  = (const float*)d_in[1];
    const float* gb1  = (const float*)d_in[2];
    const float* gw2  = (const float*)d_in[3];
    const float* gb2  = (const float*)d_in[4];
    const float* pos  = (const float*)d_in[5];
    const float* n1g  = (const float*)d_in[6];
    const float* ipw  = (const float*)d_in[7];
    const float* ipb  = (const float*)d_in[8];
    const float* opw  = (const float*)d_in[9];
    const float* opb  = (const float*)d_in[10];
    const float* ls1  = (const float*)d_in[11];
    const float* n2g  = (const float*)d_in[12];
    const float* fw1  = (const float*)d_in[13];
    const float* fb1  = (const float*)d_in[14];
    const float* fw2  = (const float*)d_in[15];
    const float* fb2  = (const float*)d_in[16];
    const float* ls2  = (const float*)d_in[17];
    const float* pw   = (const float*)d_in[18];
    const float* pb   = (const float*)d_in[19];
    float* out = (float*)d_out;

    cudaFuncSetAttribute(k_exp_a, cudaFuncAttributeMaxDynamicSharedMemorySize, A_TOT * 4);
    cudaFuncSetAttribute(k_ffn, cudaFuncAttributeMaxDynamicSharedMemorySize, F_TOT);

    k_init<<<1, 32>>>();
    k_gate<<<BTOK / 8, 256>>>(x, gw1, gb1, gw2, gb2);
    {
        size_t tot4 = (size_t)NEXP * DDIM * DDIM / 4;
        k_convw<<<(unsigned)((tot4 + 255) / 256), 256>>>(pw);
    }
    k_convb<<<(NEXP * FFH * CDIM + 255) / 256, 256>>>(fw1, fw2);
    k_exp_a<<<dim3(BTOK / TB, NEXP), 256, A_TOT * 4>>>(x, pos, n1g, ipw, ipb, opw, opb, ls1);
    k_ffn<<<dim3(BTOK * NCH / 128, NEXP), 256, F_TOT>>>(n2g, fb1, fb2, ls2);
    k_proj_mma<<<dim3(DDIM / 128, NEXP * 64), 256>>>();
    long long tot = (long long)BTOK * DDIM;
    k_combine<<<(unsigned)((tot + 255) / 256), 256>>>(pb, out, (long long)out_size);
}

// round 6
// speedup vs baseline: 3.0715x; 1.5541x over previous
#include <cuda_runtime.h>
#include <cuda_bf16.h>
#include <math.h>
#include <cstdint>

// ---------------- problem constants ----------------
#define BTOK 8192
#define DDIM 1280
#define NEXP 4
#define NCH  20
#define CDIM 64
#define NHEAD 4
#define HDIM 16
#define FFH  256

// ---------------- device scratch (allocation-free) ----------------
__device__ float g_w[BTOK * NEXP];
__device__ float g_wslot[NEXP * BTOK];      // slot -> combine weight
__device__ int   g_tok[NEXP * BTOK];        // slot -> token id
__device__ int   g_cnt[NEXP];
__device__ int   g_slot[2 * BTOK];          // token -> global slot (e*B + slot)
__device__ int   g_tope[2 * BTOK];
__device__ float g_topw[2 * BTOK];
__device__ float g_xs[(size_t)NEXP * BTOK * DDIM];   // post-attn residual (slot-major)
__device__ __nv_bfloat16 g_hbh[(size_t)NEXP * BTOK * DDIM];
__device__ __nv_bfloat16 g_hbl[(size_t)NEXP * BTOK * DDIM];
__device__ __nv_bfloat16 g_pwh[(size_t)NEXP * DDIM * DDIM];
__device__ __nv_bfloat16 g_pwl[(size_t)NEXP * DDIM * DDIM];
__device__ __nv_bfloat16 g_fw1b[NEXP * FFH * CDIM];
__device__ __nv_bfloat16 g_fw2b[NEXP * CDIM * FFH];
__device__ __nv_bfloat16 g_ipwb[NEXP * 3 * CDIM * CDIM];   // 192x64 per expert
__device__ __nv_bfloat16 g_opwb[NEXP * CDIM * CDIM];       // 64x64 per expert
__device__ float g_y [(size_t)NEXP * BTOK * DDIM];

// ---------------- warp MMA helpers ----------------
__device__ __forceinline__ uint32_t smem_u32(const void* p) {
    uint32_t a;
    asm("{ .reg .u64 t; cvta.to.shared.u64 t, %1; cvt.u32.u64 %0, t; }" : "=r"(a) : "l"(p));
    return a;
}
__device__ __forceinline__ void ldm_x4(uint32_t& r0, uint32_t& r1, uint32_t& r2, uint32_t& r3,
                                       uint32_t addr) {
    asm volatile("ldmatrix.sync.aligned.m8n8.x4.shared.b16 {%0,%1,%2,%3}, [%4];"
                 : "=r"(r0), "=r"(r1), "=r"(r2), "=r"(r3) : "r"(addr));
}
__device__ __forceinline__ void mma16816(float* d, const uint32_t* a, const uint32_t* b) {
    asm volatile("mma.sync.aligned.m16n8k16.row.col.f32.bf16.bf16.f32 "
                 "{%0,%1,%2,%3}, {%4,%5,%6,%7}, {%8,%9}, {%0,%1,%2,%3};"
                 : "+f"(d[0]), "+f"(d[1]), "+f"(d[2]), "+f"(d[3])
                 : "r"(a[0]), "r"(a[1]), "r"(a[2]), "r"(a[3]), "r"(b[0]), "r"(b[1]));
}

// ---------------- K0: init ----------------
__global__ void k_init() {
    if (threadIdx.x < NEXP) g_cnt[threadIdx.x] = 0;
}

// ---------------- K1: gating + routing ----------------
__global__ void k_gate(const float* __restrict__ x,
                       const float* __restrict__ gw1, const float* __restrict__ gb1,
                       const float* __restrict__ gw2, const float* __restrict__ gb2) {
    __shared__ float s_x[8][DDIM];
    int warp = threadIdx.x >> 5, lane = threadIdx.x & 31;
    int b = blockIdx.x * 8 + warp;
    const float* xr = x + (size_t)b * DDIM;
    for (int d = lane; d < DDIM; d += 32) s_x[warp][d] = xr[d];
    __syncwarp();
    float h1[16];
#pragma unroll
    for (int j = 0; j < 16; j++) {
        float s = 0.f;
        const float* wr = gw1 + j * DDIM;
        for (int d = lane; d < DDIM; d += 32) s += s_x[warp][d] * wr[d];
#pragma unroll
        for (int o = 16; o; o >>= 1) s += __shfl_xor_sync(0xffffffffu, s, o);
        h1[j] = tanhf(s + gb1[j]);
    }
    if (lane == 0) {
        float logits[NEXP];
#pragma unroll
        for (int e = 0; e < NEXP; e++) {
            float s = gb2[e];
#pragma unroll
            for (int j = 0; j < 16; j++) s += h1[j] * gw2[e * 16 + j];
            logits[e] = s;
        }
        float m = logits[0];
#pragma unroll
        for (int e = 1; e < NEXP; e++) m = fmaxf(m, logits[e]);
        float p[NEXP], sum = 0.f;
#pragma unroll
        for (int e = 0; e < NEXP; e++) { p[e] = expf(logits[e] - m); sum += p[e]; }
#pragma unroll
        for (int e = 0; e < NEXP; e++) p[e] /= sum;
        int e0 = 0;
#pragma unroll
        for (int e = 1; e < NEXP; e++) if (p[e] > p[e0]) e0 = e;
        int e1 = -1;
#pragma unroll
        for (int e = 0; e < NEXP; e++) {
            if (e == e0) continue;
            if (e1 < 0 || p[e] > p[e1]) e1 = e;
        }
        float den = p[e0] + p[e1] + 1e-6f;
        float w0 = p[e0] / den, w1 = p[e1] / den;
        int s0 = atomicAdd(&g_cnt[e0], 1);
        int s1 = atomicAdd(&g_cnt[e1], 1);
        g_slot[2 * b]     = e0 * BTOK + s0;
        g_slot[2 * b + 1] = e1 * BTOK + s1;
        g_wslot[e0 * BTOK + s0] = w0;
        g_wslot[e1 * BTOK + s1] = w1;
        g_tok[e0 * BTOK + s0] = b;
        g_tok[e1 * BTOK + s1] = b;
        g_tope[2 * b] = e0; g_tope[2 * b + 1] = e1;
        g_topw[2 * b] = w0; g_topw[2 * b + 1] = w1;
    }
}

// ---------------- K1b: split proj weights into bf16 hi/lo ----------------
__global__ void k_convw(const float* __restrict__ pw) {
    size_t i = ((size_t)blockIdx.x * 256 + threadIdx.x) * 4;
    const size_t TOT = (size_t)NEXP * DDIM * DDIM;
    if (i >= TOT) return;
    float4 v = *(const float4*)&pw[i];
    __nv_bfloat16 h0 = __float2bfloat16(v.x), h1 = __float2bfloat16(v.y);
    __nv_bfloat16 h2 = __float2bfloat16(v.z), h3 = __float2bfloat16(v.w);
    __nv_bfloat16 l0 = __float2bfloat16(v.x - __bfloat162float(h0));
    __nv_bfloat16 l1 = __float2bfloat16(v.y - __bfloat162float(h1));
    __nv_bfloat16 l2 = __float2bfloat16(v.z - __bfloat162float(h2));
    __nv_bfloat16 l3 = __float2bfloat16(v.w - __bfloat162float(h3));
    *(__nv_bfloat162*)&g_pwh[i]     = __nv_bfloat162(h0, h1);
    *(__nv_bfloat162*)&g_pwh[i + 2] = __nv_bfloat162(h2, h3);
    *(__nv_bfloat162*)&g_pwl[i]     = __nv_bfloat162(l0, l1);
    *(__nv_bfloat162*)&g_pwl[i + 2] = __nv_bfloat162(l2, l3);
}

// ---------------- K1c: convert small weights to bf16 ----------------
__global__ void k_convb(const float* __restrict__ fw1, const float* __restrict__ fw2,
                        const float* __restrict__ ipw, const float* __restrict__ opw) {
    int i = blockIdx.x * 256 + threadIdx.x;
    if (i < NEXP * FFH * CDIM) {
        g_fw1b[i] = __float2bfloat16(fw1[i]);
        g_fw2b[i] = __float2bfloat16(fw2[i]);
    }
    if (i < NEXP * 3 * CDIM * CDIM) g_ipwb[i] = __float2bfloat16(ipw[i]);
    if (i < NEXP * CDIM * CDIM)     g_opwb[i] = __float2bfloat16(opw[i]);
}

// ---------------- K2a: k_att — pos + rms1 + attn (all-MMA) + residual ----------------
// Block: 6 compact slots (120 chunk-rows, padded M=128) of expert e.
#define AT_TOK 6
#define QS 200            // qkv smem row stride (bf16)
// smem byte offsets
#define T_XS   0          // 128x64 f32    32768
#define T_XN   32768      // 128x72 bf16   18432
#define T_QKV  51200      // 128x200 bf16  51200
#define T_O    102400     // 128x72 bf16   18432
#define T_IPW  120832     // 192x72 bf16   27648
#define T_OPW  148480     // 64x72 bf16    9216
#define T_IPB  157696     // 192 f         768
#define T_OPB  158464     // 64 f          256
#define T_N1G  158720     // 64 f          256
#define T_LS1  158976     // 64 f          256
#define T_TOK  159232     // 8 int         32
#define T_TOT  159488

__global__ void __launch_bounds__(256) k_att(
    const float* __restrict__ x, const float* __restrict__ pos,
    const float* __restrict__ n1g, const float* __restrict__ ipb,
    const float* __restrict__ opb, const float* __restrict__ ls1) {
    int e   = blockIdx.y;
    int tk0 = blockIdx.x * AT_TOK;
    int cnt = g_cnt[e];
    if (tk0 >= cnt) return;
    int nval = min(AT_TOK, cnt - tk0);
    int rows = nval * NCH;

    extern __shared__ char smb[];
    float*         sXS  = (float*)(smb + T_XS);
    __nv_bfloat16* sXN  = (__nv_bfloat16*)(smb + T_XN);
    __nv_bfloat16* sQKV = (__nv_bfloat16*)(smb + T_QKV);
    __nv_bfloat16* sO   = (__nv_bfloat16*)(smb + T_O);
    __nv_bfloat16* sIPW = (__nv_bfloat16*)(smb + T_IPW);
    __nv_bfloat16* sOPW = (__nv_bfloat16*)(smb + T_OPW);
    float* sIPB = (float*)(smb + T_IPB);
    float* sOPB = (float*)(smb + T_OPB);
    float* sN1G = (float*)(smb + T_N1G);
    float* sLS1 = (float*)(smb + T_LS1);
    int*   sTok = (int*)(smb + T_TOK);

    int t = threadIdx.x, wid = t >> 5, lane = t & 31;

    if (t < AT_TOK) sTok[t] = (t < nval) ? g_tok[e * BTOK + tk0 + t] : 0;
    __syncthreads();

    // ---- staging ----
    {
        const __nv_bfloat16* ipwg = g_ipwb + e * 192 * 64;
        const __nv_bfloat16* opwg = g_opwb + e * 64 * 64;
#pragma unroll
        for (int i = t; i < 1536; i += 256) {        // ipw 192x64
            int j = i >> 3, sg = i & 7;
            *(uint4*)(sIPW + j * 72 + sg * 8) = *(const uint4*)(ipwg + j * 64 + sg * 8);
        }
#pragma unroll
        for (int i = t; i < 512; i += 256) {         // opw 64x64
            int j = i >> 3, sg = i & 7;
            *(uint4*)(sOPW + j * 72 + sg * 8) = *(const uint4*)(opwg + j * 64 + sg * 8);
        }
        // x gather + pos -> sXS fp32 (zero pad rows)
#pragma unroll
        for (int i = t; i < 2048; i += 256) {        // 128 rows x 16 float4
            int r = i >> 4, q = i & 15;
            float4 v = make_float4(0.f, 0.f, 0.f, 0.f);
            if (r < rows) {
                int tok = sTok[r / NCH], c = r % NCH;
                float4 xv = *(const float4*)(x + (size_t)tok * DDIM + c * 64 + q * 4);
                float4 pv = *(const float4*)(pos + (size_t)e * DDIM + c * 64 + q * 4);
                v = make_float4(xv.x + pv.x, xv.y + pv.y, xv.z + pv.z, xv.w + pv.w);
            }
            *(float4*)(sXS + r * 64 + q * 4) = v;
        }
        if (t < 192) sIPB[t] = ipb[e * 192 + t];
        if (t < 64) {
            sOPB[t] = opb[e * 64 + t];
            sN1G[t] = n1g[e * 64 + t];
            sLS1[t] = ls1[e * 64 + t];
        }
    }
    __syncthreads();

    // ---- rms1 -> xn bf16 ----
#pragma unroll
    for (int i = 0; i < 16; i++) {
        int r = wid * 16 + i;
        float v0 = sXS[r * 64 + lane], v1 = sXS[r * 64 + 32 + lane];
        float ss = v0 * v0 + v1 * v1;
#pragma unroll
        for (int o = 16; o; o >>= 1) ss += __shfl_xor_sync(0xffffffffu, ss, o);
        float inv = 1.f / (sqrtf(ss * (1.f / 64.f)) + 1e-8f);
        sXN[r * 72 + lane]      = __float2bfloat16(v0 * inv * sN1G[lane]);
        sXN[r * 72 + 32 + lane] = __float2bfloat16(v1 * inv * sN1G[32 + lane]);
    }
    __syncthreads();

    uint32_t sbXN = smem_u32(sXN), sbIPW = smem_u32(sIPW);
    uint32_t sbO  = smem_u32(sO),  sbOPW = smem_u32(sOPW);
    int a_r = (lane & 15), a_k = ((lane >> 4) << 3);
    int b_r = (lane & 7) + ((lane >> 4) << 3), b_k = (((lane >> 3) & 1) << 3);

    // ---- in_proj MMA: [128,64] x [192,64]^T + bias -> sQKV bf16 ----
    {
        int wm = wid & 1, wn = wid >> 1;   // 2 x 4; warp covers 64 rows x 48 cols
        float acc[4][6][4];
#pragma unroll
        for (int i = 0; i < 4; i++)
#pragma unroll
            for (int j = 0; j < 6; j++)
#pragma unroll
                for (int q = 0; q < 4; q++) acc[i][j][q] = 0.f;
#pragma unroll
        for (int k16 = 0; k16 < 4; k16++) {
            int kb = k16 * 16;
            uint32_t bh[6][2];
#pragma unroll
            for (int np = 0; np < 3; np++) {
                uint32_t boff = (uint32_t)((wn * 48 + np * 16 + b_r) * 72 + kb + b_k) * 2;
                ldm_x4(bh[np * 2][0], bh[np * 2][1], bh[np * 2 + 1][0], bh[np * 2 + 1][1], sbIPW + boff);
            }
#pragma unroll
            for (int mt2 = 0; mt2 < 4; mt2++) {
                uint32_t aoff = (uint32_t)((wm * 64 + mt2 * 16 + a_r) * 72 + kb + a_k) * 2;
                uint32_t ah[4];
                ldm_x4(ah[0], ah[1], ah[2], ah[3], sbXN + aoff);
#pragma unroll
                for (int ntl = 0; ntl < 6; ntl++) mma16816(acc[mt2][ntl], ah, bh[ntl]);
            }
        }
#pragma unroll
        for (int mt2 = 0; mt2 < 4; mt2++) {
#pragma unroll
            for (int ntl = 0; ntl < 6; ntl++) {
                int col = wn * 48 + ntl * 8 + (lane & 3) * 2;
                int r1 = wm * 64 + mt2 * 16 + (lane >> 2), r2 = r1 + 8;
                float b0 = sIPB[col], b1 = sIPB[col + 1];
                *(__nv_bfloat162*)(sQKV + r1 * QS + col) =
                    __float22bfloat162_rn(make_float2(acc[mt2][ntl][0] + b0, acc[mt2][ntl][1] + b1));
                *(__nv_bfloat162*)(sQKV + r2 * QS + col) =
                    __float22bfloat162_rn(make_float2(acc[mt2][ntl][2] + b0, acc[mt2][ntl][3] + b1));
            }
        }
    }
    __syncthreads();

    // ---- attention: 24 (token,head) tasks, in-lane softmax ----
    for (int task = wid; task < AT_TOK * NHEAD; task += 8) {
        int tk = task >> 2, h = task & 3;
        if (tk >= nval) continue;
        if (lane < NCH) {
            const __nv_bfloat16* qrow = sQKV + (tk * NCH + lane) * QS + h * 16;
            float qv[16];
#pragma unroll
            for (int d2 = 0; d2 < 8; d2++) {
                float2 f = __bfloat1622float2(*(const __nv_bfloat162*)(qrow + d2 * 2));
                qv[d2 * 2] = f.x; qv[d2 * 2 + 1] = f.y;
            }
            float s[NCH];
#pragma unroll
            for (int c2 = 0; c2 < NCH; c2++) {
                const __nv_bfloat16* krow = sQKV + (tk * NCH + c2) * QS + 64 + h * 16;
                float dot = 0.f;
#pragma unroll
                for (int d2 = 0; d2 < 8; d2++) {
                    float2 f = __bfloat1622float2(*(const __nv_bfloat162*)(krow + d2 * 2));
                    dot += qv[d2 * 2] * f.x + qv[d2 * 2 + 1] * f.y;
                }
                s[c2] = dot * 0.25f;
            }
            float m = s[0];
#pragma unroll
            for (int c2 = 1; c2 < NCH; c2++) m = fmaxf(m, s[c2]);
            float sum = 0.f;
#pragma unroll
            for (int c2 = 0; c2 < NCH; c2++) { s[c2] = __expf(s[c2] - m); sum += s[c2]; }
            float inv = 1.f / sum;
            float o[16];
#pragma unroll
            for (int d = 0; d < 16; d++) o[d] = 0.f;
#pragma unroll
            for (int c2 = 0; c2 < NCH; c2++) {
                float a = s[c2] * inv;
                const __nv_bfloat16* vrow = sQKV + (tk * NCH + c2) * QS + 128 + h * 16;
#pragma unroll
                for (int d2 = 0; d2 < 8; d2++) {
                    float2 f = __bfloat1622float2(*(const __nv_bfloat162*)(vrow + d2 * 2));
                    o[d2 * 2] += a * f.x; o[d2 * 2 + 1] += a * f.y;
                }
            }
            __nv_bfloat16* orow = sO + (tk * NCH + lane) * 72 + h * 16;
#pragma unroll
            for (int d2 = 0; d2 < 8; d2++)
                *(__nv_bfloat162*)(orow + d2 * 2) =
                    __float22bfloat162_rn(make_float2(o[d2 * 2], o[d2 * 2 + 1]));
        }
    }
    __syncthreads();

    // ---- out_proj MMA: [128,64] x [64,64]^T, + residual + ls1 -> g_xs ----
    {
        int wm = wid & 1, wn = wid >> 1;   // warp: 64 rows x 16 cols
        float acc[4][2][4];
#pragma unroll
        for (int i = 0; i < 4; i++)
#pragma unroll
            for (int j = 0; j < 2; j++)
#pragma unroll
                for (int q = 0; q < 4; q++) acc[i][j][q] = 0.f;
#pragma unroll
        for (int k16 = 0; k16 < 4; k16++) {
            int kb = k16 * 16;
            uint32_t bh[2][2];
            uint32_t boff = (uint32_t)((wn * 16 + b_r) * 72 + kb + b_k) * 2;
            ldm_x4(bh[0][0], bh[0][1], bh[1][0], bh[1][1], sbOPW + boff);
#pragma unroll
            for (int mt2 = 0; mt2 < 4; mt2++) {
                uint32_t aoff = (uint32_t)((wm * 64 + mt2 * 16 + a_r) * 72 + kb + a_k) * 2;
                uint32_t ah[4];
                ldm_x4(ah[0], ah[1], ah[2], ah[3], sbO + aoff);
#pragma unroll
                for (int ntl = 0; ntl < 2; ntl++) mma16816(acc[mt2][ntl], ah, bh[ntl]);
            }
        }
        float* gout = g_xs + ((size_t)(e * BTOK + tk0)) * DDIM;
#pragma unroll
        for (int mt2 = 0; mt2 < 4; mt2++) {
#pragma unroll
            for (int ntl = 0; ntl < 2; ntl++) {
                int col = wn * 16 + ntl * 8 + (lane & 3) * 2;
                float b0 = sOPB[col], b1 = sOPB[col + 1];
                float l0 = sLS1[col], l1 = sLS1[col + 1];
#pragma unroll
                for (int half = 0; half < 2; half++) {
                    int r = wm * 64 + mt2 * 16 + (lane >> 2) + half * 8;
                    if (r < rows) {
                        float v0 = sXS[r * 64 + col]     + l0 * (acc[mt2][ntl][half * 2]     + b0);
                        float v1 = sXS[r * 64 + col + 1] + l1 * (acc[mt2][ntl][half * 2 + 1] + b1);
                        *(float2*)(gout + (size_t)r * 64 + col) = make_float2(v0, v1);
                    }
                }
            }
        }
    }
}

// ---------------- K2b: warp-MMA FFN over compact chunk-rows ----------------
#define F_XS   0          // 128x64 f32      (32768)
#define F_XN   32768      // 128x72 bf16     (18432)
#define F_F1   51200      // 128x264 bf16    (67584)
#define F_W1   118784     // 256x72 bf16     (36864)
#define F_W2   155648     // 64x264 bf16     (33792)
#define F_N2G  189440
#define F_FB1  189696
#define F_FB2  190720
#define F_LS2  190976
#define F_WGT  191232
#define F_TOT  191744

__global__ void __launch_bounds__(256) k_ffn(
    const float* __restrict__ n2g, const float* __restrict__ fb1,
    const float* __restrict__ fb2, const float* __restrict__ ls2) {
    int e  = blockIdx.y;
    int r0 = blockIdx.x * 128;
    int rows_e = g_cnt[e] * NCH;
    if (r0 >= rows_e) return;

    extern __shared__ char smb[];
    float*          sXS  = (float*)(smb + F_XS);
    __nv_bfloat16*  sXN  = (__nv_bfloat16*)(smb + F_XN);
    __nv_bfloat16*  sF1  = (__nv_bfloat16*)(smb + F_F1);
    __nv_bfloat16*  sW1  = (__nv_bfloat16*)(smb + F_W1);
    __nv_bfloat16*  sW2  = (__nv_bfloat16*)(smb + F_W2);
    float*          sN2G = (float*)(smb + F_N2G);
    float*          sFB1 = (float*)(smb + F_FB1);
    float*          sFB2 = (float*)(smb + F_FB2);
    float*          sLS2 = (float*)(smb + F_LS2);
    float*          sWGT = (float*)(smb + F_WGT);

    int t = threadIdx.x, wid = t >> 5, lane = t & 31;

    {
        const __nv_bfloat16* w1g = g_fw1b + e * FFH * CDIM;
        const __nv_bfloat16* w2g = g_fw2b + e * CDIM * FFH;
        const float* xsg = g_xs + (size_t)e * BTOK * DDIM + (size_t)r0 * 64;
#pragma unroll
        for (int i = t; i < 2048; i += 256) {
            int j = i >> 3, sg = i & 7;
            *(uint4*)(sW1 + j * 72 + sg * 8) = *(const uint4*)(w1g + j * 64 + sg * 8);
        }
#pragma unroll
        for (int i = t; i < 2048; i += 256) {
            int n = i >> 5, sg = i & 31;
            *(uint4*)(sW2 + n * 264 + sg * 8) = *(const uint4*)(w2g + n * 256 + sg * 8);
        }
#pragma unroll
        for (int i = t; i < 2048; i += 256) {
            int r = i >> 4, sg = i & 15;
            *(float4*)(sXS + r * 64 + sg * 4) = *(const float4*)(xsg + (size_t)r * 64 + sg * 4);
        }
        if (t < 64) { sN2G[t] = n2g[e * 64 + t]; sFB2[t] = fb2[e * 64 + t]; sLS2[t] = ls2[e * 64 + t]; }
        if (t < 256) sFB1[t] = fb1[e * 256 + t];
        if (t < 128) {
            int rr = r0 + t;
            sWGT[t] = (rr < rows_e) ? g_wslot[e * BTOK + rr / 20] : 0.f;
        }
    }
    __syncthreads();

#pragma unroll
    for (int i = 0; i < 16; i++) {
        int r = wid * 16 + i;
        float v0 = sXS[r * 64 + lane], v1 = sXS[r * 64 + 32 + lane];
        float ss = v0 * v0 + v1 * v1;
#pragma unroll
        for (int o = 16; o; o >>= 1) ss += __shfl_xor_sync(0xffffffffu, ss, o);
        float inv = 1.f / (sqrtf(ss * (1.f / 64.f)) + 1e-8f);
        sXN[r * 72 + lane]      = __float2bfloat16(v0 * inv * sN2G[lane]);
        sXN[r * 72 + 32 + lane] = __float2bfloat16(v1 * inv * sN2G[32 + lane]);
    }
    __syncthreads();

    uint32_t sbXN = smem_u32(sXN), sbW1 = smem_u32(sW1);
    uint32_t sbF1 = smem_u32(sF1), sbW2 = smem_u32(sW2);
    int a_r = (lane & 15), a_k = ((lane >> 4) << 3);
    int b_r = (lane & 7) + ((lane >> 4) << 3), b_k = (((lane >> 3) & 1) << 3);

    {
        int wm = wid & 1, wn = wid >> 1;
#pragma unroll
        for (int nh = 0; nh < 2; nh++) {
            float acc[4][4][4];
#pragma unroll
            for (int i = 0; i < 4; i++)
#pragma unroll
                for (int j = 0; j < 4; j++)
#pragma unroll
                    for (int q = 0; q < 4; q++) acc[i][j][q] = 0.f;
#pragma unroll
            for (int k16 = 0; k16 < 4; k16++) {
                int kb = k16 * 16;
                uint32_t bh[4][2];
#pragma unroll
                for (int np = 0; np < 2; np++) {
                    uint32_t boff = (uint32_t)((nh * 128 + wn * 32 + np * 16 + b_r) * 72 + kb + b_k) * 2;
                    ldm_x4(bh[np * 2][0], bh[np * 2][1], bh[np * 2 + 1][0], bh[np * 2 + 1][1], sbW1 + boff);
                }
#pragma unroll
                for (int mt2 = 0; mt2 < 4; mt2++) {
                    uint32_t aoff = (uint32_t)((wm * 64 + mt2 * 16 + a_r) * 72 + kb + a_k) * 2;
                    uint32_t ah[4];
                    ldm_x4(ah[0], ah[1], ah[2], ah[3], sbXN + aoff);
#pragma unroll
                    for (int ntl = 0; ntl < 4; ntl++) mma16816(acc[mt2][ntl], ah, bh[ntl]);
                }
            }
#pragma unroll
            for (int mt2 = 0; mt2 < 4; mt2++) {
#pragma unroll
                for (int ntl = 0; ntl < 4; ntl++) {
                    int col = nh * 128 + wn * 32 + ntl * 8 + (lane & 3) * 2;
                    int r1 = wm * 64 + mt2 * 16 + (lane >> 2), r2 = r1 + 8;
                    float b0 = sFB1[col], b1 = sFB1[col + 1];
                    float c0 = fmaxf(acc[mt2][ntl][0] + b0, 0.f);
                    float c1 = fmaxf(acc[mt2][ntl][1] + b1, 0.f);
                    float c2 = fmaxf(acc[mt2][ntl][2] + b0, 0.f);
                    float c3 = fmaxf(acc[mt2][ntl][3] + b1, 0.f);
                    *(__nv_bfloat162*)(sF1 + r1 * 264 + col) = __float22bfloat162_rn(make_float2(c0, c1));
                    *(__nv_bfloat162*)(sF1 + r2 * 264 + col) = __float22bfloat162_rn(make_float2(c2, c3));
                }
            }
        }
    }
    __syncthreads();

    {
        int wm2 = wid & 3, wn2 = wid >> 2;
        float acc2[2][4][4];
#pragma unroll
        for (int i = 0; i < 2; i++)
#pragma unroll
            for (int j = 0; j < 4; j++)
#pragma unroll
                for (int q = 0; q < 4; q++) acc2[i][j][q] = 0.f;
#pragma unroll
        for (int k16 = 0; k16 < 16; k16++) {
            int kb = k16 * 16;
            uint32_t bh[4][2];
#pragma unroll
            for (int np = 0; np < 2; np++) {
                uint32_t boff = (uint32_t)((wn2 * 32 + np * 16 + b_r) * 264 + kb + b_k) * 2;
                ldm_x4(bh[np * 2][0], bh[np * 2][1], bh[np * 2 + 1][0], bh[np * 2 + 1][1], sbW2 + boff);
            }
#pragma unroll
            for (int mt2 = 0; mt2 < 2; mt2++) {
                uint32_t aoff = (uint32_t)((wm2 * 32 + mt2 * 16 + a_r) * 264 + kb + a_k) * 2;
                uint32_t ah[4];
                ldm_x4(ah[0], ah[1], ah[2], ah[3], sbF1 + aoff);
#pragma unroll
                for (int ntl = 0; ntl < 4; ntl++) mma16816(acc2[mt2][ntl], ah, bh[ntl]);
            }
        }
        __nv_bfloat16* ghb = g_hbh + (size_t)e * BTOK * DDIM + (size_t)r0 * 64;
        __nv_bfloat16* glb = g_hbl + (size_t)e * BTOK * DDIM + (size_t)r0 * 64;
#pragma unroll
        for (int mt2 = 0; mt2 < 2; mt2++) {
#pragma unroll
            for (int ntl = 0; ntl < 4; ntl++) {
                int col = wn2 * 32 + ntl * 8 + (lane & 3) * 2;
                float b0 = sFB2[col], b1 = sFB2[col + 1];
                float l0 = sLS2[col], l1 = sLS2[col + 1];
#pragma unroll
                for (int half = 0; half < 2; half++) {
                    int r = wm2 * 32 + mt2 * 16 + (lane >> 2) + half * 8;
                    if (r0 + r < rows_e) {
                        float w = sWGT[r];
                        float v0 = w * (sXS[r * 64 + col]     + l0 * (acc2[mt2][ntl][half * 2]     + b0));
                        float v1 = w * (sXS[r * 64 + col + 1] + l1 * (acc2[mt2][ntl][half * 2 + 1] + b1));
                        __nv_bfloat16 h0 = __float2bfloat16(v0), h1 = __float2bfloat16(v1);
                        __nv_bfloat16 q0 = __float2bfloat16(v0 - __bfloat162float(h0));
                        __nv_bfloat16 q1 = __float2bfloat16(v1 - __bfloat162float(h1));
                        *(__nv_bfloat162*)(ghb + (size_t)r * 64 + col) = __nv_bfloat162(h0, h1);
                        *(__nv_bfloat162*)(glb + (size_t)r * 64 + col) = __nv_bfloat162(q0, q1);
                    }
                }
            }
        }
    }
}

// ---------------- K3: warp-MMA bf16x3 dense proj GEMM per expert ----------------
#define KC 32
#define SSTRIDE 40

__global__ void __launch_bounds__(256) k_proj_mma() {
    int e  = blockIdx.y >> 6;
    int mt = blockIdx.y & 63;
    int nt = blockIdx.x;
    int cnt = g_cnt[e];
    int row0 = mt * 128;
    if (row0 >= cnt) return;

    __shared__ __nv_bfloat16 sAh[128 * SSTRIDE];
    __shared__ __nv_bfloat16 sAl[128 * SSTRIDE];
    __shared__ __nv_bfloat16 sBh[128 * SSTRIDE];
    __shared__ __nv_bfloat16 sBl[128 * SSTRIDE];

    int t = threadIdx.x;
    int wid = t >> 5, lane = t & 31;
    int wm = wid & 1, wn = wid >> 1;

    const __nv_bfloat16* Ah = g_hbh + (size_t)(e * BTOK) * DDIM;
    const __nv_bfloat16* Al = g_hbl + (size_t)(e * BTOK) * DDIM;
    const __nv_bfloat16* Bh = g_pwh + (size_t)e * DDIM * DDIM + (size_t)(nt * 128) * DDIM;
    const __nv_bfloat16* Bl = g_pwl + (size_t)e * DDIM * DDIM + (size_t)(nt * 128) * DDIM;

    float acc[4][4][4];
#pragma unroll
    for (int i = 0; i < 4; i++)
#pragma unroll
        for (int j = 0; j < 4; j++)
#pragma unroll
            for (int q = 0; q < 4; q++) acc[i][j][q] = 0.f;

    int rw0 = t >> 2,        q0 = t & 3;
    int rw1 = (t + 256) >> 2, q1 = (t + 256) & 3;
    bool v0 = (row0 + rw0) < cnt, v1 = (row0 + rw1) < cnt;
    const uint4 Z = make_uint4(0u, 0u, 0u, 0u);

    uint4 pAh0, pAh1, pAl0, pAl1, pBh0, pBh1, pBl0, pBl1;
#define LOADCHUNK(k0) do { \
        size_t a0 = (size_t)(row0 + rw0) * DDIM + (k0) + q0 * 8; \
        size_t a1 = (size_t)(row0 + rw1) * DDIM + (k0) + q1 * 8; \
        size_t b0 = (size_t)rw0 * DDIM + (k0) + q0 * 8; \
        size_t b1 = (size_t)rw1 * DDIM + (k0) + q1 * 8; \
        pAh0 = v0 ? *(const uint4*)(Ah + a0) : Z; \
        pAh1 = v1 ? *(const uint4*)(Ah + a1) : Z; \
        pAl0 = v0 ? *(const uint4*)(Al + a0) : Z; \
        pAl1 = v1 ? *(const uint4*)(Al + a1) : Z; \
        pBh0 = *(const uint4*)(Bh + b0); \
        pBh1 = *(const uint4*)(Bh + b1); \
        pBl0 = *(const uint4*)(Bl + b0); \
        pBl1 = *(const uint4*)(Bl + b1); \
    } while (0)

    int s0 = rw0 * 5 + q0, s1 = rw1 * 5 + q1;

    uint32_t sbAh = smem_u32(sAh), sbAl = smem_u32(sAl);
    uint32_t sbBh = smem_u32(sBh), sbBl = smem_u32(sBl);

    int a_r = (lane & 15), a_k = ((lane >> 4) << 3);
    int b_r = (lane & 7) + ((lane >> 4) << 3), b_k = (((lane >> 3) & 1) << 3);

    LOADCHUNK(0);

    const int NCHUNK = DDIM / KC;
    for (int c = 0; c < NCHUNK; c++) {
        __syncthreads();
        ((uint4*)sAh)[s0] = pAh0; ((uint4*)sAh)[s1] = pAh1;
        ((uint4*)sAl)[s0] = pAl0; ((uint4*)sAl)[s1] = pAl1;
        ((uint4*)sBh)[s0] = pBh0; ((uint4*)sBh)[s1] = pBh1;
        ((uint4*)sBl)[s0] = pBl0; ((uint4*)sBl)[s1] = pBl1;
        __syncthreads();
        if (c + 1 < NCHUNK) LOADCHUNK((c + 1) * KC);

#pragma unroll
        for (int k16 = 0; k16 < 2; k16++) {
            int kb = k16 * 16;
            uint32_t bh[4][2], bl[4][2];
#pragma unroll
            for (int np = 0; np < 2; np++) {
                uint32_t boff = (uint32_t)((wn * 32 + np * 16 + b_r) * SSTRIDE + kb + b_k) * 2;
                ldm_x4(bh[np * 2][0], bh[np * 2][1], bh[np * 2 + 1][0], bh[np * 2 + 1][1], sbBh + boff);
                ldm_x4(bl[np * 2][0], bl[np * 2][1], bl[np * 2 + 1][0], bl[np * 2 + 1][1], sbBl + boff);
            }
#pragma unroll
            for (int mt2 = 0; mt2 < 4; mt2++) {
                uint32_t aoff = (uint32_t)((wm * 64 + mt2 * 16 + a_r) * SSTRIDE + kb + a_k) * 2;
                uint32_t ah[4], al[4];
                ldm_x4(ah[0], ah[1], ah[2], ah[3], sbAh + aoff);
                ldm_x4(al[0], al[1], al[2], al[3], sbAl + aoff);
#pragma unroll
                for (int ntl = 0; ntl < 4; ntl++) {
                    mma16816(acc[mt2][ntl], ah, bh[ntl]);
                    mma16816(acc[mt2][ntl], al, bh[ntl]);
                    mma16816(acc[mt2][ntl], ah, bl[ntl]);
                }
            }
        }
    }

    int lrow = lane >> 2, lcol = (lane & 3) * 2;
    float* Ybase = g_y + (size_t)(e * BTOK) * DDIM;
#pragma unroll
    for (int mt2 = 0; mt2 < 4; mt2++) {
        int rbase = row0 + wm * 64 + mt2 * 16;
        int r1 = rbase + lrow, r2 = rbase + 8 + lrow;
#pragma unroll
        for (int ntl = 0; ntl < 4; ntl++) {
            int col = nt * 128 + wn * 32 + ntl * 8 + lcol;
            if (r1 < cnt) {
                float2 vv = make_float2(acc[mt2][ntl][0], acc[mt2][ntl][1]);
                *(float2*)&Ybase[(size_t)r1 * DDIM + col] = vv;
            }
            if (r2 < cnt) {
                float2 vv = make_float2(acc[mt2][ntl][2], acc[mt2][ntl][3]);
                *(float2*)&Ybase[(size_t)r2 * DDIM + col] = vv;
            }
        }
    }
}

// ---------------- K4: combine (+bias) + aux/load tail ----------------
__global__ void k_combine(const float* __restrict__ pb, float* __restrict__ out,
                          long long out_size) {
    long long idx = (long long)blockIdx.x * 256 + threadIdx.x;
    const long long TOT = (long long)BTOK * DDIM;
    if (idx < TOT) {
        int b = (int)(idx / DDIM), d = (int)(idx % DDIM);
        int s0 = g_slot[2 * b], s1 = g_slot[2 * b + 1];
        int e0 = g_tope[2 * b], e1 = g_tope[2 * b + 1];
        float v = g_y[(size_t)s0 * DDIM + d] + g_y[(size_t)s1 * DDIM + d]
                + g_topw[2 * b] * pb[e0 * DDIM + d]
                + g_topw[2 * b + 1] * pb[e1 * DDIM + d];
        out[idx] = v;
    }
    if (idx == 0 && out_size >= TOT + 5) {
        out[TOT] = 0.f;
#pragma unroll
        for (int e = 0; e < NEXP; e++) out[TOT + 1 + e] = (float)g_cnt[e];
    }
}

// ---------------- host launcher ----------------
extern "C" void kernel_launch(void* const* d_in, const int* in_sizes, int n_in,
                              void* d_out, int out_size) {
    const float* x    = (const float*)d_in[0];
    const float* gw1  = (const float*)d_in[1];
    const float* gb1  = (const float*)d_in[2];
    const float* gw2  = (const float*)d_in[3];
    const float* gb2  = (const float*)d_in[4];
    const float* pos  = (const float*)d_in[5];
    const float* n1g  = (const float*)d_in[6];
    const float* ipw  = (const float*)d_in[7];
    const float* ipb  = (const float*)d_in[8];
    const float* opw  = (const float*)d_in[9];
    const float* opb  = (const float*)d_in[10];
    const float* ls1  = (const float*)d_in[11];
    const float* n2g  = (const float*)d_in[12];
    const float* fw1  = (const float*)d_in[13];
    const float* fb1  = (const float*)d_in[14];
    const float* fw2  = (const float*)d_in[15];
    const float* fb2  = (const float*)d_in[16];
    const float* ls2  = (const float*)d_in[17];
    const float* pw   = (const float*)d_in[18];
    const float* pb   = (const float*)d_in[19];
    float* out = (float*)d_out;

    cudaFuncSetAttribute(k_att, cudaFuncAttributeMaxDynamicSharedMemorySize, T_TOT);
    cudaFuncSetAttribute(k_ffn, cudaFuncAttributeMaxDynamicSharedMemorySize, F_TOT);

    k_init<<<1, 32>>>();
    k_gate<<<BTOK / 8, 256>>>(x, gw1, gb1, gw2, gb2);
    {
        size_t tot4 = (size_t)NEXP * DDIM * DDIM / 4;
        k_convw<<<(unsigned)((tot4 + 255) / 256), 256>>>(pw);
    }
    k_convb<<<(NEXP * FFH * CDIM + 255) / 256, 256>>>(fw1, fw2, ipw, opw);
    k_att<<<dim3((BTOK + AT_TOK - 1) / AT_TOK, NEXP), 256, T_TOT>>>(x, pos, n1g, ipb, opb, ls1);
    k_ffn<<<dim3(BTOK * NCH / 128, NEXP), 256, F_TOT>>>(n2g, fb1, fb2, ls2);
    k_proj_mma<<<dim3(DDIM / 128, NEXP * 64), 256>>>();
    long long tot = (long long)BTOK * DDIM;
    k_combine<<<(unsigned)((tot + 255) / 256), 256>>>(pb, out, (long long)out_size);
}

// round 7
// speedup vs baseline: 3.5775x; 1.1648x over previous
#include <cuda_runtime.h>
#include <cuda_bf16.h>
#include <math.h>
#include <cstdint>

// ---------------- problem constants ----------------
#define BTOK 8192
#define DDIM 1280
#define NEXP 4
#define NCH  20
#define CDIM 64
#define NHEAD 4
#define HDIM 16
#define FFH  256

// ---------------- device scratch (allocation-free) ----------------
__device__ float g_w[BTOK * NEXP];
__device__ float g_wslot[NEXP * BTOK];      // slot -> combine weight
__device__ int   g_tok[NEXP * BTOK];        // slot -> token id
__device__ int   g_cnt[NEXP];
__device__ int   g_slot[2 * BTOK];          // token -> global slot (e*B + slot)
__device__ int   g_tope[2 * BTOK];
__device__ float g_topw[2 * BTOK];
__device__ float g_xs[(size_t)NEXP * BTOK * DDIM];   // post-attn residual (slot-major)
__device__ __nv_bfloat16 g_hbh[(size_t)NEXP * BTOK * DDIM];
__device__ __nv_bfloat16 g_hbl[(size_t)NEXP * BTOK * DDIM];
__device__ __nv_bfloat16 g_pwh[(size_t)NEXP * DDIM * DDIM];
__device__ __nv_bfloat16 g_pwl[(size_t)NEXP * DDIM * DDIM];
__device__ __nv_bfloat16 g_fw1b[NEXP * FFH * CDIM];
__device__ __nv_bfloat16 g_fw2b[NEXP * CDIM * FFH];
__device__ __nv_bfloat16 g_ipwb[NEXP * 3 * CDIM * CDIM];   // 192x64 per expert
__device__ __nv_bfloat16 g_opwb[NEXP * CDIM * CDIM];       // 64x64 per expert
__device__ float g_y [(size_t)NEXP * BTOK * DDIM];

// ---------------- warp MMA helpers ----------------
__device__ __forceinline__ uint32_t smem_u32(const void* p) {
    uint32_t a;
    asm("{ .reg .u64 t; cvta.to.shared.u64 t, %1; cvt.u32.u64 %0, t; }" : "=r"(a) : "l"(p));
    return a;
}
__device__ __forceinline__ void ldm_x4(uint32_t& r0, uint32_t& r1, uint32_t& r2, uint32_t& r3,
                                       uint32_t addr) {
    asm volatile("ldmatrix.sync.aligned.m8n8.x4.shared.b16 {%0,%1,%2,%3}, [%4];"
                 : "=r"(r0), "=r"(r1), "=r"(r2), "=r"(r3) : "r"(addr));
}
__device__ __forceinline__ void mma16816(float* d, const uint32_t* a, const uint32_t* b) {
    asm volatile("mma.sync.aligned.m16n8k16.row.col.f32.bf16.bf16.f32 "
                 "{%0,%1,%2,%3}, {%4,%5,%6,%7}, {%8,%9}, {%0,%1,%2,%3};"
                 : "+f"(d[0]), "+f"(d[1]), "+f"(d[2]), "+f"(d[3])
                 : "r"(a[0]), "r"(a[1]), "r"(a[2]), "r"(a[3]), "r"(b[0]), "r"(b[1]));
}
__device__ __forceinline__ void cpa16(uint32_t dst, const void* src, int srcsize) {
    asm volatile("cp.async.cg.shared.global [%0], [%1], 16, %2;"
                 :: "r"(dst), "l"(src), "r"(srcsize) : "memory");
}
#define CPA_COMMIT() asm volatile("cp.async.commit_group;" ::: "memory")
#define CPA_WAIT1()  asm volatile("cp.async.wait_group 1;" ::: "memory")

// ---------------- K0: init ----------------
__global__ void k_init() {
    if (threadIdx.x < NEXP) g_cnt[threadIdx.x] = 0;
}

// ---------------- K1: gating + routing ----------------
__global__ void k_gate(const float* __restrict__ x,
                       const float* __restrict__ gw1, const float* __restrict__ gb1,
                       const float* __restrict__ gw2, const float* __restrict__ gb2) {
    __shared__ float s_x[8][DDIM];
    int warp = threadIdx.x >> 5, lane = threadIdx.x & 31;
    int b = blockIdx.x * 8 + warp;
    const float* xr = x + (size_t)b * DDIM;
    for (int d = lane; d < DDIM; d += 32) s_x[warp][d] = xr[d];
    __syncwarp();
    float h1[16];
#pragma unroll
    for (int j = 0; j < 16; j++) {
        float s = 0.f;
        const float* wr = gw1 + j * DDIM;
        for (int d = lane; d < DDIM; d += 32) s += s_x[warp][d] * wr[d];
#pragma unroll
        for (int o = 16; o; o >>= 1) s += __shfl_xor_sync(0xffffffffu, s, o);
        h1[j] = tanhf(s + gb1[j]);
    }
    if (lane == 0) {
        float logits[NEXP];
#pragma unroll
        for (int e = 0; e < NEXP; e++) {
            float s = gb2[e];
#pragma unroll
            for (int j = 0; j < 16; j++) s += h1[j] * gw2[e * 16 + j];
            logits[e] = s;
        }
        float m = logits[0];
#pragma unroll
        for (int e = 1; e < NEXP; e++) m = fmaxf(m, logits[e]);
        float p[NEXP], sum = 0.f;
#pragma unroll
        for (int e = 0; e < NEXP; e++) { p[e] = expf(logits[e] - m); sum += p[e]; }
#pragma unroll
        for (int e = 0; e < NEXP; e++) p[e] /= sum;
        int e0 = 0;
#pragma unroll
        for (int e = 1; e < NEXP; e++) if (p[e] > p[e0]) e0 = e;
        int e1 = -1;
#pragma unroll
        for (int e = 0; e < NEXP; e++) {
            if (e == e0) continue;
            if (e1 < 0 || p[e] > p[e1]) e1 = e;
        }
        float den = p[e0] + p[e1] + 1e-6f;
        float w0 = p[e0] / den, w1 = p[e1] / den;
        int s0 = atomicAdd(&g_cnt[e0], 1);
        int s1 = atomicAdd(&g_cnt[e1], 1);
        g_slot[2 * b]     = e0 * BTOK + s0;
        g_slot[2 * b + 1] = e1 * BTOK + s1;
        g_wslot[e0 * BTOK + s0] = w0;
        g_wslot[e1 * BTOK + s1] = w1;
        g_tok[e0 * BTOK + s0] = b;
        g_tok[e1 * BTOK + s1] = b;
        g_tope[2 * b] = e0; g_tope[2 * b + 1] = e1;
        g_topw[2 * b] = w0; g_topw[2 * b + 1] = w1;
    }
}

// ---------------- K1b: split proj weights into bf16 hi/lo ----------------
__global__ void k_convw(const float* __restrict__ pw) {
    size_t i = ((size_t)blockIdx.x * 256 + threadIdx.x) * 4;
    const size_t TOT = (size_t)NEXP * DDIM * DDIM;
    if (i >= TOT) return;
    float4 v = *(const float4*)&pw[i];
    __nv_bfloat16 h0 = __float2bfloat16(v.x), h1 = __float2bfloat16(v.y);
    __nv_bfloat16 h2 = __float2bfloat16(v.z), h3 = __float2bfloat16(v.w);
    __nv_bfloat16 l0 = __float2bfloat16(v.x - __bfloat162float(h0));
    __nv_bfloat16 l1 = __float2bfloat16(v.y - __bfloat162float(h1));
    __nv_bfloat16 l2 = __float2bfloat16(v.z - __bfloat162float(h2));
    __nv_bfloat16 l3 = __float2bfloat16(v.w - __bfloat162float(h3));
    *(__nv_bfloat162*)&g_pwh[i]     = __nv_bfloat162(h0, h1);
    *(__nv_bfloat162*)&g_pwh[i + 2] = __nv_bfloat162(h2, h3);
    *(__nv_bfloat162*)&g_pwl[i]     = __nv_bfloat162(l0, l1);
    *(__nv_bfloat162*)&g_pwl[i + 2] = __nv_bfloat162(l2, l3);
}

// ---------------- K1c: convert small weights to bf16 ----------------
__global__ void k_convb(const float* __restrict__ fw1, const float* __restrict__ fw2,
                        const float* __restrict__ ipw, const float* __restrict__ opw) {
    int i = blockIdx.x * 256 + threadIdx.x;
    if (i < NEXP * FFH * CDIM) {
        g_fw1b[i] = __float2bfloat16(fw1[i]);
        g_fw2b[i] = __float2bfloat16(fw2[i]);
    }
    if (i < NEXP * 3 * CDIM * CDIM) g_ipwb[i] = __float2bfloat16(ipw[i]);
    if (i < NEXP * CDIM * CDIM)     g_opwb[i] = __float2bfloat16(opw[i]);
}

// ---------------- K2a: k_att — pos + rms1 + attn (all-MMA) + residual ----------------
// Block: 6 compact slots (120 chunk-rows, padded M=128) of expert e.
// smem aliasing: XS(f32, phase1) lives under QKV; O lives under XN. 108 KB -> 2 CTAs/SM.
#define AT_TOK 6
#define QS 200
#define T_QKV  0        // phase1: XS fp32 128x64 (32768); then QKV 128x200 bf16 (51200)
#define T_XN   51200    // XN 128x72 bf16 (18432); later O
#define T_IPW  69632    // 192x72 bf16 (27648)
#define T_OPW  97280    // 64x72 bf16 (9216)
#define T_IPB  106496   // 192 f
#define T_OPB  107264   // 64 f
#define T_N1G  107520
#define T_LS1  107776
#define T_TOK  108032
#define T_TOT  108064

__global__ void __launch_bounds__(256, 2) k_att(
    const float* __restrict__ x, const float* __restrict__ pos,
    const float* __restrict__ n1g, const float* __restrict__ ipb,
    const float* __restrict__ opb, const float* __restrict__ ls1) {
    int e   = blockIdx.y;
    int tk0 = blockIdx.x * AT_TOK;
    int cnt = g_cnt[e];
    if (tk0 >= cnt) return;
    int nval = min(AT_TOK, cnt - tk0);
    int rows = nval * NCH;

    extern __shared__ char smb[];
    float*         sXS  = (float*)(smb + T_QKV);            // alias (dead after rms)
    __nv_bfloat16* sQKV = (__nv_bfloat16*)(smb + T_QKV);
    __nv_bfloat16* sXN  = (__nv_bfloat16*)(smb + T_XN);
    __nv_bfloat16* sO   = (__nv_bfloat16*)(smb + T_XN);     // alias (XN dead after in_proj)
    __nv_bfloat16* sIPW = (__nv_bfloat16*)(smb + T_IPW);
    __nv_bfloat16* sOPW = (__nv_bfloat16*)(smb + T_OPW);
    float* sIPB = (float*)(smb + T_IPB);
    float* sOPB = (float*)(smb + T_OPB);
    float* sN1G = (float*)(smb + T_N1G);
    float* sLS1 = (float*)(smb + T_LS1);
    int*   sTok = (int*)(smb + T_TOK);

    int t = threadIdx.x, wid = t >> 5, lane = t & 31;

    if (t < AT_TOK) sTok[t] = (t < nval) ? g_tok[e * BTOK + tk0 + t] : 0;
    __syncthreads();

    // ---- staging ----
    {
        const __nv_bfloat16* ipwg = g_ipwb + e * 192 * 64;
        const __nv_bfloat16* opwg = g_opwb + e * 64 * 64;
#pragma unroll
        for (int i = t; i < 1536; i += 256) {        // ipw 192x64
            int j = i >> 3, sg = i & 7;
            *(uint4*)(sIPW + j * 72 + sg * 8) = *(const uint4*)(ipwg + j * 64 + sg * 8);
        }
#pragma unroll
        for (int i = t; i < 512; i += 256) {         // opw 64x64
            int j = i >> 3, sg = i & 7;
            *(uint4*)(sOPW + j * 72 + sg * 8) = *(const uint4*)(opwg + j * 64 + sg * 8);
        }
#pragma unroll
        for (int i = t; i < 2048; i += 256) {        // xs gather 128 rows x 16 float4
            int r = i >> 4, q = i & 15;
            float4 v = make_float4(0.f, 0.f, 0.f, 0.f);
            if (r < rows) {
                int tok = sTok[r / NCH], c = r % NCH;
                float4 xv = *(const float4*)(x + (size_t)tok * DDIM + c * 64 + q * 4);
                float4 pv = *(const float4*)(pos + (size_t)e * DDIM + c * 64 + q * 4);
                v = make_float4(xv.x + pv.x, xv.y + pv.y, xv.z + pv.z, xv.w + pv.w);
            }
            *(float4*)(sXS + r * 64 + q * 4) = v;
        }
        if (t < 192) sIPB[t] = ipb[e * 192 + t];
        if (t < 64) {
            sOPB[t] = opb[e * 64 + t];
            sN1G[t] = n1g[e * 64 + t];
            sLS1[t] = ls1[e * 64 + t];
        }
    }
    __syncthreads();

    // ---- rms1: XS -> XN bf16 (XS dead afterwards) ----
#pragma unroll
    for (int i = 0; i < 16; i++) {
        int r = wid * 16 + i;
        float v0 = sXS[r * 64 + lane], v1 = sXS[r * 64 + 32 + lane];
        float ss = v0 * v0 + v1 * v1;
#pragma unroll
        for (int o = 16; o; o >>= 1) ss += __shfl_xor_sync(0xffffffffu, ss, o);
        float inv = 1.f / (sqrtf(ss * (1.f / 64.f)) + 1e-8f);
        sXN[r * 72 + lane]      = __float2bfloat16(v0 * inv * sN1G[lane]);
        sXN[r * 72 + 32 + lane] = __float2bfloat16(v1 * inv * sN1G[32 + lane]);
    }
    __syncthreads();

    uint32_t sbXN = smem_u32(sXN), sbIPW = smem_u32(sIPW);
    uint32_t sbO  = smem_u32(sO),  sbOPW = smem_u32(sOPW);
    int a_r = (lane & 15), a_k = ((lane >> 4) << 3);
    int b_r = (lane & 7) + ((lane >> 4) << 3), b_k = (((lane >> 3) & 1) << 3);

    // ---- in_proj MMA: [128,64] x [192,64]^T + bias -> sQKV (overwrites XS; 2 N-halves) ----
    {
        int wm4 = wid & 3, wn2 = wid >> 2;   // 4(M) x 2(N); warp = 32 rows x 48 cols
#pragma unroll
        for (int nh = 0; nh < 2; nh++) {
            float acc[2][6][4];
#pragma unroll
            for (int i = 0; i < 2; i++)
#pragma unroll
                for (int j = 0; j < 6; j++)
#pragma unroll
                    for (int q = 0; q < 4; q++) acc[i][j][q] = 0.f;
#pragma unroll
            for (int k16 = 0; k16 < 4; k16++) {
                int kb = k16 * 16;
                uint32_t bh[6][2];
#pragma unroll
                for (int np = 0; np < 3; np++) {
                    uint32_t boff = (uint32_t)((nh * 96 + wn2 * 48 + np * 16 + b_r) * 72 + kb + b_k) * 2;
                    ldm_x4(bh[np * 2][0], bh[np * 2][1], bh[np * 2 + 1][0], bh[np * 2 + 1][1], sbIPW + boff);
                }
#pragma unroll
                for (int mt2 = 0; mt2 < 2; mt2++) {
                    uint32_t aoff = (uint32_t)((wm4 * 32 + mt2 * 16 + a_r) * 72 + kb + a_k) * 2;
                    uint32_t ah[4];
                    ldm_x4(ah[0], ah[1], ah[2], ah[3], sbXN + aoff);
#pragma unroll
                    for (int ntl = 0; ntl < 6; ntl++) mma16816(acc[mt2][ntl], ah, bh[ntl]);
                }
            }
#pragma unroll
            for (int mt2 = 0; mt2 < 2; mt2++) {
#pragma unroll
                for (int ntl = 0; ntl < 6; ntl++) {
                    int col = nh * 96 + wn2 * 48 + ntl * 8 + (lane & 3) * 2;
                    int r1 = wm4 * 32 + mt2 * 16 + (lane >> 2), r2 = r1 + 8;
                    float b0 = sIPB[col], b1 = sIPB[col + 1];
                    *(__nv_bfloat162*)(sQKV + r1 * QS + col) =
                        __float22bfloat162_rn(make_float2(acc[mt2][ntl][0] + b0, acc[mt2][ntl][1] + b1));
                    *(__nv_bfloat162*)(sQKV + r2 * QS + col) =
                        __float22bfloat162_rn(make_float2(acc[mt2][ntl][2] + b0, acc[mt2][ntl][3] + b1));
                }
            }
        }
    }
    __syncthreads();

    // ---- attention: 24 (token,head) tasks, in-lane softmax; writes sO (= XN region) ----
    for (int task = wid; task < AT_TOK * NHEAD; task += 8) {
        int tk = task >> 2, h = task & 3;
        if (tk >= nval) continue;
        if (lane < NCH) {
            const __nv_bfloat16* qrow = sQKV + (tk * NCH + lane) * QS + h * 16;
            float qv[16];
#pragma unroll
            for (int d2 = 0; d2 < 8; d2++) {
                float2 f = __bfloat1622float2(*(const __nv_bfloat162*)(qrow + d2 * 2));
                qv[d2 * 2] = f.x; qv[d2 * 2 + 1] = f.y;
            }
            float s[NCH];
#pragma unroll
            for (int c2 = 0; c2 < NCH; c2++) {
                const __nv_bfloat16* krow = sQKV + (tk * NCH + c2) * QS + 64 + h * 16;
                float dot = 0.f;
#pragma unroll
                for (int d2 = 0; d2 < 8; d2++) {
                    float2 f = __bfloat1622float2(*(const __nv_bfloat162*)(krow + d2 * 2));
                    dot += qv[d2 * 2] * f.x + qv[d2 * 2 + 1] * f.y;
                }
                s[c2] = dot * 0.25f;
            }
            float m = s[0];
#pragma unroll
            for (int c2 = 1; c2 < NCH; c2++) m = fmaxf(m, s[c2]);
            float sum = 0.f;
#pragma unroll
            for (int c2 = 0; c2 < NCH; c2++) { s[c2] = __expf(s[c2] - m); sum += s[c2]; }
            float inv = 1.f / sum;
            float o[16];
#pragma unroll
            for (int d = 0; d < 16; d++) o[d] = 0.f;
#pragma unroll
            for (int c2 = 0; c2 < NCH; c2++) {
                float a = s[c2] * inv;
                const __nv_bfloat16* vrow = sQKV + (tk * NCH + c2) * QS + 128 + h * 16;
#pragma unroll
                for (int d2 = 0; d2 < 8; d2++) {
                    float2 f = __bfloat1622float2(*(const __nv_bfloat162*)(vrow + d2 * 2));
                    o[d2 * 2] += a * f.x; o[d2 * 2 + 1] += a * f.y;
                }
            }
            __nv_bfloat16* orow = sO + (tk * NCH + lane) * 72 + h * 16;
#pragma unroll
            for (int d2 = 0; d2 < 8; d2++)
                *(__nv_bfloat162*)(orow + d2 * 2) =
                    __float22bfloat162_rn(make_float2(o[d2 * 2], o[d2 * 2 + 1]));
        }
    }
    __syncthreads();

    // ---- out_proj MMA + residual (re-gathered from global) + ls1 -> g_xs ----
    {
        int wm = wid & 1, wn = wid >> 1;   // warp: 64 rows x 16 cols
        float acc[4][2][4];
#pragma unroll
        for (int i = 0; i < 4; i++)
#pragma unroll
            for (int j = 0; j < 2; j++)
#pragma unroll
                for (int q = 0; q < 4; q++) acc[i][j][q] = 0.f;
#pragma unroll
        for (int k16 = 0; k16 < 4; k16++) {
            int kb = k16 * 16;
            uint32_t bh[2][2];
            uint32_t boff = (uint32_t)((wn * 16 + b_r) * 72 + kb + b_k) * 2;
            ldm_x4(bh[0][0], bh[0][1], bh[1][0], bh[1][1], sbOPW + boff);
#pragma unroll
            for (int mt2 = 0; mt2 < 4; mt2++) {
                uint32_t aoff = (uint32_t)((wm * 64 + mt2 * 16 + a_r) * 72 + kb + a_k) * 2;
                uint32_t ah[4];
                ldm_x4(ah[0], ah[1], ah[2], ah[3], sbO + aoff);
#pragma unroll
                for (int ntl = 0; ntl < 2; ntl++) mma16816(acc[mt2][ntl], ah, bh[ntl]);
            }
        }
        float* gout = g_xs + ((size_t)(e * BTOK + tk0)) * DDIM;
        const float* posE = pos + (size_t)e * DDIM;
#pragma unroll
        for (int mt2 = 0; mt2 < 4; mt2++) {
#pragma unroll
            for (int ntl = 0; ntl < 2; ntl++) {
                int col = wn * 16 + ntl * 8 + (lane & 3) * 2;
                float b0 = sOPB[col], b1 = sOPB[col + 1];
                float l0 = sLS1[col], l1 = sLS1[col + 1];
#pragma unroll
                for (int half = 0; half < 2; half++) {
                    int r = wm * 64 + mt2 * 16 + (lane >> 2) + half * 8;
                    if (r < rows) {
                        int tok = sTok[r / NCH], ch = r % NCH;
                        float2 xv = *(const float2*)(x + (size_t)tok * DDIM + ch * 64 + col);
                        float2 pv = *(const float2*)(posE + ch * 64 + col);
                        float v0 = (xv.x + pv.x) + l0 * (acc[mt2][ntl][half * 2]     + b0);
                        float v1 = (xv.y + pv.y) + l1 * (acc[mt2][ntl][half * 2 + 1] + b1);
                        *(float2*)(gout + (size_t)r * 64 + col) = make_float2(v0, v1);
                    }
                }
            }
        }
    }
}

// ---------------- K2b: warp-MMA FFN over compact chunk-rows ----------------
#define F_XS   0          // 128x64 f32      (32768)
#define F_XN   32768      // 128x72 bf16     (18432)
#define F_F1   51200      // 128x264 bf16    (67584)
#define F_W1   118784     // 256x72 bf16     (36864)
#define F_W2   155648     // 64x264 bf16     (33792)
#define F_N2G  189440
#define F_FB1  189696
#define F_FB2  190720
#define F_LS2  190976
#define F_WGT  191232
#define F_TOT  191744

__global__ void __launch_bounds__(256) k_ffn(
    const float* __restrict__ n2g, const float* __restrict__ fb1,
    const float* __restrict__ fb2, const float* __restrict__ ls2) {
    int e  = blockIdx.y;
    int r0 = blockIdx.x * 128;
    int rows_e = g_cnt[e] * NCH;
    if (r0 >= rows_e) return;

    extern __shared__ char smb[];
    float*          sXS  = (float*)(smb + F_XS);
    __nv_bfloat16*  sXN  = (__nv_bfloat16*)(smb + F_XN);
    __nv_bfloat16*  sF1  = (__nv_bfloat16*)(smb + F_F1);
    __nv_bfloat16*  sW1  = (__nv_bfloat16*)(smb + F_W1);
    __nv_bfloat16*  sW2  = (__nv_bfloat16*)(smb + F_W2);
    float*          sN2G = (float*)(smb + F_N2G);
    float*          sFB1 = (float*)(smb + F_FB1);
    float*          sFB2 = (float*)(smb + F_FB2);
    float*          sLS2 = (float*)(smb + F_LS2);
    float*          sWGT = (float*)(smb + F_WGT);

    int t = threadIdx.x, wid = t >> 5, lane = t & 31;

    {
        const __nv_bfloat16* w1g = g_fw1b + e * FFH * CDIM;
        const __nv_bfloat16* w2g = g_fw2b + e * CDIM * FFH;
        const float* xsg = g_xs + (size_t)e * BTOK * DDIM + (size_t)r0 * 64;
#pragma unroll
        for (int i = t; i < 2048; i += 256) {
            int j = i >> 3, sg = i & 7;
            *(uint4*)(sW1 + j * 72 + sg * 8) = *(const uint4*)(w1g + j * 64 + sg * 8);
        }
#pragma unroll
        for (int i = t; i < 2048; i += 256) {
            int n = i >> 5, sg = i & 31;
            *(uint4*)(sW2 + n * 264 + sg * 8) = *(const uint4*)(w2g + n * 256 + sg * 8);
        }
#pragma unroll
        for (int i = t; i < 2048; i += 256) {
            int r = i >> 4, sg = i & 15;
            *(float4*)(sXS + r * 64 + sg * 4) = *(const float4*)(xsg + (size_t)r * 64 + sg * 4);
        }
        if (t < 64) { sN2G[t] = n2g[e * 64 + t]; sFB2[t] = fb2[e * 64 + t]; sLS2[t] = ls2[e * 64 + t]; }
        if (t < 256) sFB1[t] = fb1[e * 256 + t];
        if (t < 128) {
            int rr = r0 + t;
            sWGT[t] = (rr < rows_e) ? g_wslot[e * BTOK + rr / 20] : 0.f;
        }
    }
    __syncthreads();

#pragma unroll
    for (int i = 0; i < 16; i++) {
        int r = wid * 16 + i;
        float v0 = sXS[r * 64 + lane], v1 = sXS[r * 64 + 32 + lane];
        float ss = v0 * v0 + v1 * v1;
#pragma unroll
        for (int o = 16; o; o >>= 1) ss += __shfl_xor_sync(0xffffffffu, ss, o);
        float inv = 1.f / (sqrtf(ss * (1.f / 64.f)) + 1e-8f);
        sXN[r * 72 + lane]      = __float2bfloat16(v0 * inv * sN2G[lane]);
        sXN[r * 72 + 32 + lane] = __float2bfloat16(v1 * inv * sN2G[32 + lane]);
    }
    __syncthreads();

    uint32_t sbXN = smem_u32(sXN), sbW1 = smem_u32(sW1);
    uint32_t sbF1 = smem_u32(sF1), sbW2 = smem_u32(sW2);
    int a_r = (lane & 15), a_k = ((lane >> 4) << 3);
    int b_r = (lane & 7) + ((lane >> 4) << 3), b_k = (((lane >> 3) & 1) << 3);

    {
        int wm = wid & 1, wn = wid >> 1;
#pragma unroll
        for (int nh = 0; nh < 2; nh++) {
            float acc[4][4][4];
#pragma unroll
            for (int i = 0; i < 4; i++)
#pragma unroll
                for (int j = 0; j < 4; j++)
#pragma unroll
                    for (int q = 0; q < 4; q++) acc[i][j][q] = 0.f;
#pragma unroll
            for (int k16 = 0; k16 < 4; k16++) {
                int kb = k16 * 16;
                uint32_t bh[4][2];
#pragma unroll
                for (int np = 0; np < 2; np++) {
                    uint32_t boff = (uint32_t)((nh * 128 + wn * 32 + np * 16 + b_r) * 72 + kb + b_k) * 2;
                    ldm_x4(bh[np * 2][0], bh[np * 2][1], bh[np * 2 + 1][0], bh[np * 2 + 1][1], sbW1 + boff);
                }
#pragma unroll
                for (int mt2 = 0; mt2 < 4; mt2++) {
                    uint32_t aoff = (uint32_t)((wm * 64 + mt2 * 16 + a_r) * 72 + kb + a_k) * 2;
                    uint32_t ah[4];
                    ldm_x4(ah[0], ah[1], ah[2], ah[3], sbXN + aoff);
#pragma unroll
                    for (int ntl = 0; ntl < 4; ntl++) mma16816(acc[mt2][ntl], ah, bh[ntl]);
                }
            }
#pragma unroll
            for (int mt2 = 0; mt2 < 4; mt2++) {
#pragma unroll
                for (int ntl = 0; ntl < 4; ntl++) {
                    int col = nh * 128 + wn * 32 + ntl * 8 + (lane & 3) * 2;
                    int r1 = wm * 64 + mt2 * 16 + (lane >> 2), r2 = r1 + 8;
                    float b0 = sFB1[col], b1 = sFB1[col + 1];
                    float c0 = fmaxf(acc[mt2][ntl][0] + b0, 0.f);
                    float c1 = fmaxf(acc[mt2][ntl][1] + b1, 0.f);
                    float c2 = fmaxf(acc[mt2][ntl][2] + b0, 0.f);
                    float c3 = fmaxf(acc[mt2][ntl][3] + b1, 0.f);
                    *(__nv_bfloat162*)(sF1 + r1 * 264 + col) = __float22bfloat162_rn(make_float2(c0, c1));
                    *(__nv_bfloat162*)(sF1 + r2 * 264 + col) = __float22bfloat162_rn(make_float2(c2, c3));
                }
            }
        }
    }
    __syncthreads();

    {
        int wm2 = wid & 3, wn2 = wid >> 2;
        float acc2[2][4][4];
#pragma unroll
        for (int i = 0; i < 2; i++)
#pragma unroll
            for (int j = 0; j < 4; j++)
#pragma unroll
                for (int q = 0; q < 4; q++) acc2[i][j][q] = 0.f;
#pragma unroll
        for (int k16 = 0; k16 < 16; k16++) {
            int kb = k16 * 16;
            uint32_t bh[4][2];
#pragma unroll
            for (int np = 0; np < 2; np++) {
                uint32_t boff = (uint32_t)((wn2 * 32 + np * 16 + b_r) * 264 + kb + b_k) * 2;
                ldm_x4(bh[np * 2][0], bh[np * 2][1], bh[np * 2 + 1][0], bh[np * 2 + 1][1], sbW2 + boff);
            }
#pragma unroll
            for (int mt2 = 0; mt2 < 2; mt2++) {
                uint32_t aoff = (uint32_t)((wm2 * 32 + mt2 * 16 + a_r) * 264 + kb + a_k) * 2;
                uint32_t ah[4];
                ldm_x4(ah[0], ah[1], ah[2], ah[3], sbF1 + aoff);
#pragma unroll
                for (int ntl = 0; ntl < 4; ntl++) mma16816(acc2[mt2][ntl], ah, bh[ntl]);
            }
        }
        __nv_bfloat16* ghb = g_hbh + (size_t)e * BTOK * DDIM + (size_t)r0 * 64;
        __nv_bfloat16* glb = g_hbl + (size_t)e * BTOK * DDIM + (size_t)r0 * 64;
#pragma unroll
        for (int mt2 = 0; mt2 < 2; mt2++) {
#pragma unroll
            for (int ntl = 0; ntl < 4; ntl++) {
                int col = wn2 * 32 + ntl * 8 + (lane & 3) * 2;
                float b0 = sFB2[col], b1 = sFB2[col + 1];
                float l0 = sLS2[col], l1 = sLS2[col + 1];
#pragma unroll
                for (int half = 0; half < 2; half++) {
                    int r = wm2 * 32 + mt2 * 16 + (lane >> 2) + half * 8;
                    if (r0 + r < rows_e) {
                        float w = sWGT[r];
                        float v0 = w * (sXS[r * 64 + col]     + l0 * (acc2[mt2][ntl][half * 2]     + b0));
                        float v1 = w * (sXS[r * 64 + col + 1] + l1 * (acc2[mt2][ntl][half * 2 + 1] + b1));
                        __nv_bfloat16 h0 = __float2bfloat16(v0), h1 = __float2bfloat16(v1);
                        __nv_bfloat16 q0 = __float2bfloat16(v0 - __bfloat162float(h0));
                        __nv_bfloat16 q1 = __float2bfloat16(v1 - __bfloat162float(h1));
                        *(__nv_bfloat162*)(ghb + (size_t)r * 64 + col) = __nv_bfloat162(h0, h1);
                        *(__nv_bfloat162*)(glb + (size_t)r * 64 + col) = __nv_bfloat162(q0, q1);
                    }
                }
            }
        }
    }
}

// ---------------- K3: warp-MMA bf16x3 proj GEMM, cp.async double-buffered ----------------
#define KC 32
#define SSTRIDE 40                 // bf16 elems per row (32 + 8 pad) = 80B
#define PJ_TILE_BYTES 10240        // 128 rows * 80B
#define PJ_STAGE_BYTES (4 * PJ_TILE_BYTES)
#define PJ_SMEM (2 * PJ_STAGE_BYTES)

__global__ void __launch_bounds__(256, 2) k_proj_mma() {
    int e  = blockIdx.y >> 6;
    int mt = blockIdx.y & 63;
    int nt = blockIdx.x;
    int cnt = g_cnt[e];
    int row0 = mt * 128;
    if (row0 >= cnt) return;

    extern __shared__ char smb[];
    uint32_t sb0 = smem_u32(smb);

    int t = threadIdx.x;
    int wid = t >> 5, lane = t & 31;
    int wm = wid & 1, wn = wid >> 1;

    const __nv_bfloat16* Ah = g_hbh + (size_t)(e * BTOK) * DDIM;
    const __nv_bfloat16* Al = g_hbl + (size_t)(e * BTOK) * DDIM;
    const __nv_bfloat16* Bh = g_pwh + (size_t)e * DDIM * DDIM + (size_t)(nt * 128) * DDIM;
    const __nv_bfloat16* Bl = g_pwl + (size_t)e * DDIM * DDIM + (size_t)(nt * 128) * DDIM;

    float acc[4][4][4];
#pragma unroll
    for (int i = 0; i < 4; i++)
#pragma unroll
        for (int j = 0; j < 4; j++)
#pragma unroll
            for (int q = 0; q < 4; q++) acc[i][j][q] = 0.f;

    // per-thread load slots: 2 x 16B per matrix per chunk
    int rw0 = t >> 2, q0 = t & 3;
    int rw1 = rw0 + 64, q1 = q0;
    bool v0 = (row0 + rw0) < cnt, v1 = (row0 + rw1) < cnt;
    int ra0 = v0 ? (row0 + rw0) : 0, ra1 = v1 ? (row0 + rw1) : 0;
    int sz0 = v0 ? 16 : 0, sz1 = v1 ? 16 : 0;
    uint32_t off0 = (uint32_t)(rw0 * 5 + q0) * 16;
    uint32_t off1 = (uint32_t)(rw1 * 5 + q1) * 16;

#define PJ_ISSUE(cc, stg) do { \
        int k0 = (cc) * KC; \
        uint32_t db = sb0 + (uint32_t)(stg) * PJ_STAGE_BYTES; \
        size_t ea0 = (size_t)ra0 * DDIM + k0 + q0 * 8; \
        size_t ea1 = (size_t)ra1 * DDIM + k0 + q1 * 8; \
        size_t eb0 = (size_t)rw0 * DDIM + k0 + q0 * 8; \
        size_t eb1 = (size_t)rw1 * DDIM + k0 + q1 * 8; \
        cpa16(db + off0,                     Ah + ea0, sz0); \
        cpa16(db + off1,                     Ah + ea1, sz1); \
        cpa16(db + PJ_TILE_BYTES + off0,     Al + ea0, sz0); \
        cpa16(db + PJ_TILE_BYTES + off1,     Al + ea1, sz1); \
        cpa16(db + 2 * PJ_TILE_BYTES + off0, Bh + eb0, 16); \
        cpa16(db + 2 * PJ_TILE_BYTES + off1, Bh + eb1, 16); \
        cpa16(db + 3 * PJ_TILE_BYTES + off0, Bl + eb0, 16); \
        cpa16(db + 3 * PJ_TILE_BYTES + off1, Bl + eb1, 16); \
    } while (0)

    int a_r = (lane & 15), a_k = ((lane >> 4) << 3);
    int b_r = (lane & 7) + ((lane >> 4) << 3), b_k = (((lane >> 3) & 1) << 3);

    const int NCHUNK = DDIM / KC;     // 40
    PJ_ISSUE(0, 0); CPA_COMMIT();
    PJ_ISSUE(1, 1); CPA_COMMIT();

    for (int c = 0; c < NCHUNK; c++) {
        CPA_WAIT1();                  // chunk c resident (invariant: 1 group commit/iter)
        __syncthreads();
        int stg = c & 1;
        uint32_t base = sb0 + (uint32_t)stg * PJ_STAGE_BYTES;
        uint32_t sAh = base, sAl = base + PJ_TILE_BYTES;
        uint32_t sBh = base + 2 * PJ_TILE_BYTES, sBl = base + 3 * PJ_TILE_BYTES;

#pragma unroll
        for (int k16 = 0; k16 < 2; k16++) {
            int kb = k16 * 16;
            uint32_t bh[4][2], bl[4][2];
#pragma unroll
            for (int np = 0; np < 2; np++) {
                uint32_t boff = (uint32_t)((wn * 32 + np * 16 + b_r) * SSTRIDE + kb + b_k) * 2;
                ldm_x4(bh[np * 2][0], bh[np * 2][1], bh[np * 2 + 1][0], bh[np * 2 + 1][1], sBh + boff);
                ldm_x4(bl[np * 2][0], bl[np * 2][1], bl[np * 2 + 1][0], bl[np * 2 + 1][1], sBl + boff);
            }
#pragma unroll
            for (int mt2 = 0; mt2 < 4; mt2++) {
                uint32_t aoff = (uint32_t)((wm * 64 + mt2 * 16 + a_r) * SSTRIDE + kb + a_k) * 2;
                uint32_t ah[4], al[4];
                ldm_x4(ah[0], ah[1], ah[2], ah[3], sAh + aoff);
                ldm_x4(al[0], al[1], al[2], al[3], sAl + aoff);
#pragma unroll
                for (int ntl = 0; ntl < 4; ntl++) {
                    mma16816(acc[mt2][ntl], ah, bh[ntl]);
                    mma16816(acc[mt2][ntl], al, bh[ntl]);
                    mma16816(acc[mt2][ntl], ah, bl[ntl]);
                }
            }
        }
        __syncthreads();              // all reads of stage done before refill
        if (c + 2 < NCHUNK) PJ_ISSUE(c + 2, stg);
        CPA_COMMIT();                 // exactly one group per iteration (may be empty)
    }

    int lrow = lane >> 2, lcol = (lane & 3) * 2;
    float* Ybase = g_y + (size_t)(e * BTOK) * DDIM;
#pragma unroll
    for (int mt2 = 0; mt2 < 4; mt2++) {
        int rbase = row0 + wm * 64 + mt2 * 16;
        int r1 = rbase + lrow, r2 = rbase + 8 + lrow;
#pragma unroll
        for (int ntl = 0; ntl < 4; ntl++) {
            int col = nt * 128 + wn * 32 + ntl * 8 + lcol;
            if (r1 < cnt) {
                float2 vv = make_float2(acc[mt2][ntl][0], acc[mt2][ntl][1]);
                *(float2*)&Ybase[(size_t)r1 * DDIM + col] = vv;
            }
            if (r2 < cnt) {
                float2 vv = make_float2(acc[mt2][ntl][2], acc[mt2][ntl][3]);
                *(float2*)&Ybase[(size_t)r2 * DDIM + col] = vv;
            }
        }
    }
}

// ---------------- K4: combine (+bias) + aux/load tail ----------------
__global__ void k_combine(const float* __restrict__ pb, float* __restrict__ out,
                          long long out_size) {
    long long idx = (long long)blockIdx.x * 256 + threadIdx.x;
    const long long TOT = (long long)BTOK * DDIM;
    if (idx < TOT) {
        int b = (int)(idx / DDIM), d = (int)(idx % DDIM);
        int s0 = g_slot[2 * b], s1 = g_slot[2 * b + 1];
        int e0 = g_tope[2 * b], e1 = g_tope[2 * b + 1];
        float v = g_y[(size_t)s0 * DDIM + d] + g_y[(size_t)s1 * DDIM + d]
                + g_topw[2 * b] * pb[e0 * DDIM + d]
                + g_topw[2 * b + 1] * pb[e1 * DDIM + d];
        out[idx] = v;
    }
    if (idx == 0 && out_size >= TOT + 5) {
        out[TOT] = 0.f;
#pragma unroll
        for (int e = 0; e < NEXP; e++) out[TOT + 1 + e] = (float)g_cnt[e];
    }
}

// ---------------- host launcher ----------------
extern "C" void kernel_launch(void* const* d_in, const int* in_sizes, int n_in,
                              void* d_out, int out_size) {
    const float* x    = (const float*)d_in[0];
    const float* gw1  = (const float*)d_in[1];
    const float* gb1  = (const float*)d_in[2];
    const float* gw2  = (const float*)d_in[3];
    const float* gb2  = (const float*)d_in[4];
    const float* pos  = (const float*)d_in[5];
    const float* n1g  = (const float*)d_in[6];
    const float* ipw  = (const float*)d_in[7];
    const float* ipb  = (const float*)d_in[8];
    const float* opw  = (const float*)d_in[9];
    const float* opb  = (const float*)d_in[10];
    const float* ls1  = (const float*)d_in[11];
    const float* n2g  = (const float*)d_in[12];
    const float* fw1  = (const float*)d_in[13];
    const float* fb1  = (const float*)d_in[14];
    const float* fw2  = (const float*)d_in[15];
    const float* fb2  = (const float*)d_in[16];
    const float* ls2  = (const float*)d_in[17];
    const float* pw   = (const float*)d_in[18];
    const float* pb   = (const float*)d_in[19];
    float* out = (float*)d_out;

    cudaFuncSetAttribute(k_att, cudaFuncAttributeMaxDynamicSharedMemorySize, T_TOT);
    cudaFuncSetAttribute(k_ffn, cudaFuncAttributeMaxDynamicSharedMemorySize, F_TOT);
    cudaFuncSetAttribute(k_proj_mma, cudaFuncAttributeMaxDynamicSharedMemorySize, PJ_SMEM);

    k_init<<<1, 32>>>();
    k_gate<<<BTOK / 8, 256>>>(x, gw1, gb1, gw2, gb2);
    {
        size_t tot4 = (size_t)NEXP * DDIM * DDIM / 4;
        k_convw<<<(unsigned)((tot4 + 255) / 256), 256>>>(pw);
    }
    k_convb<<<(NEXP * FFH * CDIM + 255) / 256, 256>>>(fw1, fw2, ipw, opw);
    k_att<<<dim3((BTOK + AT_TOK - 1) / AT_TOK, NEXP), 256, T_TOT>>>(x, pos, n1g, ipb, opb, ls1);
    k_ffn<<<dim3(BTOK * NCH / 128, NEXP), 256, F_TOT>>>(n2g, fb1, fb2, ls2);
    k_proj_mma<<<dim3(DDIM / 128, NEXP * 64), 256, PJ_SMEM>>>();
    long long tot = (long long)BTOK * DDIM;
    k_combine<<<(unsigned)((tot + 255) / 256), 256>>>(pb, out, (long long)out_size);
}

// round 8
// speedup vs baseline: 4.1945x; 1.1725x over previous
#include <cuda_runtime.h>
#include <cuda_bf16.h>
#include <cuda_fp16.h>
#include <math.h>
#include <cstdint>

// ---------------- problem constants ----------------
#define BTOK 8192
#define DDIM 1280
#define NEXP 4
#define NCH  20
#define CDIM 64
#define NHEAD 4
#define HDIM 16
#define FFH  256

// ---------------- device scratch (allocation-free) ----------------
__device__ float g_w[BTOK * NEXP];
__device__ float g_wslot[NEXP * BTOK];      // slot -> combine weight
__device__ int   g_tok[NEXP * BTOK];        // slot -> token id
__device__ int   g_cnt[NEXP];
__device__ int   g_slot[2 * BTOK];          // token -> global slot (e*B + slot)
__device__ int   g_tope[2 * BTOK];
__device__ float g_topw[2 * BTOK];
__device__ float g_xs[(size_t)NEXP * BTOK * DDIM];   // post-attn residual (slot-major)
__device__ __half g_hf [(size_t)NEXP * BTOK * DDIM]; // compact hidden, fp16 single
__device__ __half g_pwh[(size_t)NEXP * DDIM * DDIM]; // proj weight fp16 hi (x64)
__device__ __half g_pwl[(size_t)NEXP * DDIM * DDIM]; // proj weight fp16 lo (x64)
__device__ __nv_bfloat16 g_fw1b[NEXP * FFH * CDIM];
__device__ __nv_bfloat16 g_fw2b[NEXP * CDIM * FFH];
__device__ __nv_bfloat16 g_ipwb[NEXP * 3 * CDIM * CDIM];   // 192x64 per expert
__device__ __nv_bfloat16 g_opwb[NEXP * CDIM * CDIM];       // 64x64 per expert
__device__ float g_y [(size_t)NEXP * BTOK * DDIM];

// ---------------- warp MMA helpers ----------------
__device__ __forceinline__ uint32_t smem_u32(const void* p) {
    uint32_t a;
    asm("{ .reg .u64 t; cvta.to.shared.u64 t, %1; cvt.u32.u64 %0, t; }" : "=r"(a) : "l"(p));
    return a;
}
__device__ __forceinline__ void ldm_x4(uint32_t& r0, uint32_t& r1, uint32_t& r2, uint32_t& r3,
                                       uint32_t addr) {
    asm volatile("ldmatrix.sync.aligned.m8n8.x4.shared.b16 {%0,%1,%2,%3}, [%4];"
                 : "=r"(r0), "=r"(r1), "=r"(r2), "=r"(r3) : "r"(addr));
}
__device__ __forceinline__ void mma16816(float* d, const uint32_t* a, const uint32_t* b) {
    asm volatile("mma.sync.aligned.m16n8k16.row.col.f32.bf16.bf16.f32 "
                 "{%0,%1,%2,%3}, {%4,%5,%6,%7}, {%8,%9}, {%0,%1,%2,%3};"
                 : "+f"(d[0]), "+f"(d[1]), "+f"(d[2]), "+f"(d[3])
                 : "r"(a[0]), "r"(a[1]), "r"(a[2]), "r"(a[3]), "r"(b[0]), "r"(b[1]));
}
__device__ __forceinline__ void mma16816h(float* d, const uint32_t* a, const uint32_t* b) {
    asm volatile("mma.sync.aligned.m16n8k16.row.col.f32.f16.f16.f32 "
                 "{%0,%1,%2,%3}, {%4,%5,%6,%7}, {%8,%9}, {%0,%1,%2,%3};"
                 : "+f"(d[0]), "+f"(d[1]), "+f"(d[2]), "+f"(d[3])
                 : "r"(a[0]), "r"(a[1]), "r"(a[2]), "r"(a[3]), "r"(b[0]), "r"(b[1]));
}
__device__ __forceinline__ void cpa16(uint32_t dst, const void* src, int srcsize) {
    asm volatile("cp.async.cg.shared.global [%0], [%1], 16, %2;"
                 :: "r"(dst), "l"(src), "r"(srcsize) : "memory");
}
#define CPA_COMMIT() asm volatile("cp.async.commit_group;" ::: "memory")
#define CPA_WAIT1()  asm volatile("cp.async.wait_group 1;" ::: "memory")

// ---------------- K0: init ----------------
__global__ void k_init() {
    if (threadIdx.x < NEXP) g_cnt[threadIdx.x] = 0;
}

// ---------------- K1: gating + routing ----------------
__global__ void k_gate(const float* __restrict__ x,
                       const float* __restrict__ gw1, const float* __restrict__ gb1,
                       const float* __restrict__ gw2, const float* __restrict__ gb2) {
    __shared__ float s_x[8][DDIM];
    int warp = threadIdx.x >> 5, lane = threadIdx.x & 31;
    int b = blockIdx.x * 8 + warp;
    const float* xr = x + (size_t)b * DDIM;
    for (int d = lane; d < DDIM; d += 32) s_x[warp][d] = xr[d];
    __syncwarp();
    float h1[16];
#pragma unroll
    for (int j = 0; j < 16; j++) {
        float s = 0.f;
        const float* wr = gw1 + j * DDIM;
        for (int d = lane; d < DDIM; d += 32) s += s_x[warp][d] * wr[d];
#pragma unroll
        for (int o = 16; o; o >>= 1) s += __shfl_xor_sync(0xffffffffu, s, o);
        h1[j] = tanhf(s + gb1[j]);
    }
    if (lane == 0) {
        float logits[NEXP];
#pragma unroll
        for (int e = 0; e < NEXP; e++) {
            float s = gb2[e];
#pragma unroll
            for (int j = 0; j < 16; j++) s += h1[j] * gw2[e * 16 + j];
            logits[e] = s;
        }
        float m = logits[0];
#pragma unroll
        for (int e = 1; e < NEXP; e++) m = fmaxf(m, logits[e]);
        float p[NEXP], sum = 0.f;
#pragma unroll
        for (int e = 0; e < NEXP; e++) { p[e] = expf(logits[e] - m); sum += p[e]; }
#pragma unroll
        for (int e = 0; e < NEXP; e++) p[e] /= sum;
        int e0 = 0;
#pragma unroll
        for (int e = 1; e < NEXP; e++) if (p[e] > p[e0]) e0 = e;
        int e1 = -1;
#pragma unroll
        for (int e = 0; e < NEXP; e++) {
            if (e == e0) continue;
            if (e1 < 0 || p[e] > p[e1]) e1 = e;
        }
        float den = p[e0] + p[e1] + 1e-6f;
        float w0 = p[e0] / den, w1 = p[e1] / den;
        int s0 = atomicAdd(&g_cnt[e0], 1);
        int s1 = atomicAdd(&g_cnt[e1], 1);
        g_slot[2 * b]     = e0 * BTOK + s0;
        g_slot[2 * b + 1] = e1 * BTOK + s1;
        g_wslot[e0 * BTOK + s0] = w0;
        g_wslot[e1 * BTOK + s1] = w1;
        g_tok[e0 * BTOK + s0] = b;
        g_tok[e1 * BTOK + s1] = b;
        g_tope[2 * b] = e0; g_tope[2 * b + 1] = e1;
        g_topw[2 * b] = w0; g_topw[2 * b + 1] = w1;
    }
}

// ---------------- K1b: split proj weights into fp16 hi/lo (x64 scaled) ----------------
__global__ void k_convw(const float* __restrict__ pw) {
    size_t i = ((size_t)blockIdx.x * 256 + threadIdx.x) * 4;
    const size_t TOT = (size_t)NEXP * DDIM * DDIM;
    if (i >= TOT) return;
    float4 v = *(const float4*)&pw[i];
    float x0 = v.x * 64.f, x1 = v.y * 64.f, x2 = v.z * 64.f, x3 = v.w * 64.f;
    __half h0 = __float2half(x0), h1 = __float2half(x1);
    __half h2 = __float2half(x2), h3 = __float2half(x3);
    __half l0 = __float2half(x0 - __half2float(h0));
    __half l1 = __float2half(x1 - __half2float(h1));
    __half l2 = __float2half(x2 - __half2float(h2));
    __half l3 = __float2half(x3 - __half2float(h3));
    *(__half2*)&g_pwh[i]     = __half2(h0, h1);
    *(__half2*)&g_pwh[i + 2] = __half2(h2, h3);
    *(__half2*)&g_pwl[i]     = __half2(l0, l1);
    *(__half2*)&g_pwl[i + 2] = __half2(l2, l3);
}

// ---------------- K1c: convert small weights to bf16 ----------------
__global__ void k_convb(const float* __restrict__ fw1, const float* __restrict__ fw2,
                        const float* __restrict__ ipw, const float* __restrict__ opw) {
    int i = blockIdx.x * 256 + threadIdx.x;
    if (i < NEXP * FFH * CDIM) {
        g_fw1b[i] = __float2bfloat16(fw1[i]);
        g_fw2b[i] = __float2bfloat16(fw2[i]);
    }
    if (i < NEXP * 3 * CDIM * CDIM) g_ipwb[i] = __float2bfloat16(ipw[i]);
    if (i < NEXP * CDIM * CDIM)     g_opwb[i] = __float2bfloat16(opw[i]);
}

// ---------------- K2a: k_att — pos + rms1 + attn (all-MMA) + residual ----------------
#define AT_TOK 6
#define QS 200
#define T_QKV  0        // phase1: XS fp32 128x64 (32768); then QKV 128x200 bf16 (51200)
#define T_XN   51200    // XN 128x72 bf16 (18432); later O
#define T_IPW  69632    // 192x72 bf16 (27648)
#define T_OPW  97280    // 64x72 bf16 (9216)
#define T_IPB  106496   // 192 f
#define T_OPB  107264   // 64 f
#define T_N1G  107520
#define T_LS1  107776
#define T_TOK  108032
#define T_TOT  108064

__global__ void __launch_bounds__(256, 2) k_att(
    const float* __restrict__ x, const float* __restrict__ pos,
    const float* __restrict__ n1g, const float* __restrict__ ipb,
    const float* __restrict__ opb, const float* __restrict__ ls1) {
    int e   = blockIdx.y;
    int tk0 = blockIdx.x * AT_TOK;
    int cnt = g_cnt[e];
    if (tk0 >= cnt) return;
    int nval = min(AT_TOK, cnt - tk0);
    int rows = nval * NCH;

    extern __shared__ char smb[];
    float*         sXS  = (float*)(smb + T_QKV);            // alias (dead after rms)
    __nv_bfloat16* sQKV = (__nv_bfloat16*)(smb + T_QKV);
    __nv_bfloat16* sXN  = (__nv_bfloat16*)(smb + T_XN);
    __nv_bfloat16* sO   = (__nv_bfloat16*)(smb + T_XN);     // alias (XN dead after in_proj)
    __nv_bfloat16* sIPW = (__nv_bfloat16*)(smb + T_IPW);
    __nv_bfloat16* sOPW = (__nv_bfloat16*)(smb + T_OPW);
    float* sIPB = (float*)(smb + T_IPB);
    float* sOPB = (float*)(smb + T_OPB);
    float* sN1G = (float*)(smb + T_N1G);
    float* sLS1 = (float*)(smb + T_LS1);
    int*   sTok = (int*)(smb + T_TOK);

    int t = threadIdx.x, wid = t >> 5, lane = t & 31;

    if (t < AT_TOK) sTok[t] = (t < nval) ? g_tok[e * BTOK + tk0 + t] : 0;
    __syncthreads();

    // ---- staging ----
    {
        const __nv_bfloat16* ipwg = g_ipwb + e * 192 * 64;
        const __nv_bfloat16* opwg = g_opwb + e * 64 * 64;
#pragma unroll
        for (int i = t; i < 1536; i += 256) {        // ipw 192x64
            int j = i >> 3, sg = i & 7;
            *(uint4*)(sIPW + j * 72 + sg * 8) = *(const uint4*)(ipwg + j * 64 + sg * 8);
        }
#pragma unroll
        for (int i = t; i < 512; i += 256) {         // opw 64x64
            int j = i >> 3, sg = i & 7;
            *(uint4*)(sOPW + j * 72 + sg * 8) = *(const uint4*)(opwg + j * 64 + sg * 8);
        }
#pragma unroll
        for (int i = t; i < 2048; i += 256) {        // xs gather 128 rows x 16 float4
            int r = i >> 4, q = i & 15;
            float4 v = make_float4(0.f, 0.f, 0.f, 0.f);
            if (r < rows) {
                int tok = sTok[r / NCH], c = r % NCH;
                float4 xv = *(const float4*)(x + (size_t)tok * DDIM + c * 64 + q * 4);
                float4 pv = *(const float4*)(pos + (size_t)e * DDIM + c * 64 + q * 4);
                v = make_float4(xv.x + pv.x, xv.y + pv.y, xv.z + pv.z, xv.w + pv.w);
            }
            *(float4*)(sXS + r * 64 + q * 4) = v;
        }
        if (t < 192) sIPB[t] = ipb[e * 192 + t];
        if (t < 64) {
            sOPB[t] = opb[e * 64 + t];
            sN1G[t] = n1g[e * 64 + t];
            sLS1[t] = ls1[e * 64 + t];
        }
    }
    __syncthreads();

    // ---- rms1: XS -> XN bf16 (XS dead afterwards) ----
#pragma unroll
    for (int i = 0; i < 16; i++) {
        int r = wid * 16 + i;
        float v0 = sXS[r * 64 + lane], v1 = sXS[r * 64 + 32 + lane];
        float ss = v0 * v0 + v1 * v1;
#pragma unroll
        for (int o = 16; o; o >>= 1) ss += __shfl_xor_sync(0xffffffffu, ss, o);
        float inv = 1.f / (sqrtf(ss * (1.f / 64.f)) + 1e-8f);
        sXN[r * 72 + lane]      = __float2bfloat16(v0 * inv * sN1G[lane]);
        sXN[r * 72 + 32 + lane] = __float2bfloat16(v1 * inv * sN1G[32 + lane]);
    }
    __syncthreads();

    uint32_t sbXN = smem_u32(sXN), sbIPW = smem_u32(sIPW);
    uint32_t sbO  = smem_u32(sO),  sbOPW = smem_u32(sOPW);
    int a_r = (lane & 15), a_k = ((lane >> 4) << 3);
    int b_r = (lane & 7) + ((lane >> 4) << 3), b_k = (((lane >> 3) & 1) << 3);

    // ---- in_proj MMA: [128,64] x [192,64]^T + bias -> sQKV (overwrites XS; 2 N-halves) ----
    {
        int wm4 = wid & 3, wn2 = wid >> 2;   // 4(M) x 2(N); warp = 32 rows x 48 cols
#pragma unroll
        for (int nh = 0; nh < 2; nh++) {
            float acc[2][6][4];
#pragma unroll
            for (int i = 0; i < 2; i++)
#pragma unroll
                for (int j = 0; j < 6; j++)
#pragma unroll
                    for (int q = 0; q < 4; q++) acc[i][j][q] = 0.f;
#pragma unroll
            for (int k16 = 0; k16 < 4; k16++) {
                int kb = k16 * 16;
                uint32_t bh[6][2];
#pragma unroll
                for (int np = 0; np < 3; np++) {
                    uint32_t boff = (uint32_t)((nh * 96 + wn2 * 48 + np * 16 + b_r) * 72 + kb + b_k) * 2;
                    ldm_x4(bh[np * 2][0], bh[np * 2][1], bh[np * 2 + 1][0], bh[np * 2 + 1][1], sbIPW + boff);
                }
#pragma unroll
                for (int mt2 = 0; mt2 < 2; mt2++) {
                    uint32_t aoff = (uint32_t)((wm4 * 32 + mt2 * 16 + a_r) * 72 + kb + a_k) * 2;
                    uint32_t ah[4];
                    ldm_x4(ah[0], ah[1], ah[2], ah[3], sbXN + aoff);
#pragma unroll
                    for (int ntl = 0; ntl < 6; ntl++) mma16816(acc[mt2][ntl], ah, bh[ntl]);
                }
            }
#pragma unroll
            for (int mt2 = 0; mt2 < 2; mt2++) {
#pragma unroll
                for (int ntl = 0; ntl < 6; ntl++) {
                    int col = nh * 96 + wn2 * 48 + ntl * 8 + (lane & 3) * 2;
                    int r1 = wm4 * 32 + mt2 * 16 + (lane >> 2), r2 = r1 + 8;
                    float b0 = sIPB[col], b1 = sIPB[col + 1];
                    *(__nv_bfloat162*)(sQKV + r1 * QS + col) =
                        __float22bfloat162_rn(make_float2(acc[mt2][ntl][0] + b0, acc[mt2][ntl][1] + b1));
                    *(__nv_bfloat162*)(sQKV + r2 * QS + col) =
                        __float22bfloat162_rn(make_float2(acc[mt2][ntl][2] + b0, acc[mt2][ntl][3] + b1));
                }
            }
        }
    }
    __syncthreads();

    // ---- attention: 24 (token,head) tasks, in-lane softmax; writes sO (= XN region) ----
    for (int task = wid; task < AT_TOK * NHEAD; task += 8) {
        int tk = task >> 2, h = task & 3;
        if (tk >= nval) continue;
        if (lane < NCH) {
            const __nv_bfloat16* qrow = sQKV + (tk * NCH + lane) * QS + h * 16;
            float qv[16];
#pragma unroll
            for (int d2 = 0; d2 < 8; d2++) {
                float2 f = __bfloat1622float2(*(const __nv_bfloat162*)(qrow + d2 * 2));
                qv[d2 * 2] = f.x; qv[d2 * 2 + 1] = f.y;
            }
            float s[NCH];
#pragma unroll
            for (int c2 = 0; c2 < NCH; c2++) {
                const __nv_bfloat16* krow = sQKV + (tk * NCH + c2) * QS + 64 + h * 16;
                float dot = 0.f;
#pragma unroll
                for (int d2 = 0; d2 < 8; d2++) {
                    float2 f = __bfloat1622float2(*(const __nv_bfloat162*)(krow + d2 * 2));
                    dot += qv[d2 * 2] * f.x + qv[d2 * 2 + 1] * f.y;
                }
                s[c2] = dot * 0.25f;
            }
            float m = s[0];
#pragma unroll
            for (int c2 = 1; c2 < NCH; c2++) m = fmaxf(m, s[c2]);
            float sum = 0.f;
#pragma unroll
            for (int c2 = 0; c2 < NCH; c2++) { s[c2] = __expf(s[c2] - m); sum += s[c2]; }
            float inv = 1.f / sum;
            float o[16];
#pragma unroll
            for (int d = 0; d < 16; d++) o[d] = 0.f;
#pragma unroll
            for (int c2 = 0; c2 < NCH; c2++) {
                float a = s[c2] * inv;
                const __nv_bfloat16* vrow = sQKV + (tk * NCH + c2) * QS + 128 + h * 16;
#pragma unroll
                for (int d2 = 0; d2 < 8; d2++) {
                    float2 f = __bfloat1622float2(*(const __nv_bfloat162*)(vrow + d2 * 2));
                    o[d2 * 2] += a * f.x; o[d2 * 2 + 1] += a * f.y;
                }
            }
            __nv_bfloat16* orow = sO + (tk * NCH + lane) * 72 + h * 16;
#pragma unroll
            for (int d2 = 0; d2 < 8; d2++)
                *(__nv_bfloat162*)(orow + d2 * 2) =
                    __float22bfloat162_rn(make_float2(o[d2 * 2], o[d2 * 2 + 1]));
        }
    }
    __syncthreads();

    // ---- out_proj MMA + residual (re-gathered from global) + ls1 -> g_xs ----
    {
        int wm = wid & 1, wn = wid >> 1;   // warp: 64 rows x 16 cols
        float acc[4][2][4];
#pragma unroll
        for (int i = 0; i < 4; i++)
#pragma unroll
            for (int j = 0; j < 2; j++)
#pragma unroll
                for (int q = 0; q < 4; q++) acc[i][j][q] = 0.f;
#pragma unroll
        for (int k16 = 0; k16 < 4; k16++) {
            int kb = k16 * 16;
            uint32_t bh[2][2];
            uint32_t boff = (uint32_t)((wn * 16 + b_r) * 72 + kb + b_k) * 2;
            ldm_x4(bh[0][0], bh[0][1], bh[1][0], bh[1][1], sbOPW + boff);
#pragma unroll
            for (int mt2 = 0; mt2 < 4; mt2++) {
                uint32_t aoff = (uint32_t)((wm * 64 + mt2 * 16 + a_r) * 72 + kb + a_k) * 2;
                uint32_t ah[4];
                ldm_x4(ah[0], ah[1], ah[2], ah[3], sbO + aoff);
#pragma unroll
                for (int ntl = 0; ntl < 2; ntl++) mma16816(acc[mt2][ntl], ah, bh[ntl]);
            }
        }
        float* gout = g_xs + ((size_t)(e * BTOK + tk0)) * DDIM;
        const float* posE = pos + (size_t)e * DDIM;
#pragma unroll
        for (int mt2 = 0; mt2 < 4; mt2++) {
#pragma unroll
            for (int ntl = 0; ntl < 2; ntl++) {
                int col = wn * 16 + ntl * 8 + (lane & 3) * 2;
                float b0 = sOPB[col], b1 = sOPB[col + 1];
                float l0 = sLS1[col], l1 = sLS1[col + 1];
#pragma unroll
                for (int half = 0; half < 2; half++) {
                    int r = wm * 64 + mt2 * 16 + (lane >> 2) + half * 8;
                    if (r < rows) {
                        int tok = sTok[r / NCH], ch = r % NCH;
                        float2 xv = *(const float2*)(x + (size_t)tok * DDIM + ch * 64 + col);
                        float2 pv = *(const float2*)(posE + ch * 64 + col);
                        float v0 = (xv.x + pv.x) + l0 * (acc[mt2][ntl][half * 2]     + b0);
                        float v1 = (xv.y + pv.y) + l1 * (acc[mt2][ntl][half * 2 + 1] + b1);
                        *(float2*)(gout + (size_t)r * 64 + col) = make_float2(v0, v1);
                    }
                }
            }
        }
    }
}

// ---------------- K2b: warp-MMA FFN over compact chunk-rows ----------------
#define F_XS   0          // 128x64 f32      (32768)
#define F_XN   32768      // 128x72 bf16     (18432)
#define F_F1   51200      // 128x264 bf16    (67584)
#define F_W1   118784     // 256x72 bf16     (36864)
#define F_W2   155648     // 64x264 bf16     (33792)
#define F_N2G  189440
#define F_FB1  189696
#define F_FB2  190720
#define F_LS2  190976
#define F_WGT  191232
#define F_TOT  191744

__global__ void __launch_bounds__(256) k_ffn(
    const float* __restrict__ n2g, const float* __restrict__ fb1,
    const float* __restrict__ fb2, const float* __restrict__ ls2) {
    int e  = blockIdx.y;
    int r0 = blockIdx.x * 128;
    int rows_e = g_cnt[e] * NCH;
    if (r0 >= rows_e) return;

    extern __shared__ char smb[];
    float*          sXS  = (float*)(smb + F_XS);
    __nv_bfloat16*  sXN  = (__nv_bfloat16*)(smb + F_XN);
    __nv_bfloat16*  sF1  = (__nv_bfloat16*)(smb + F_F1);
    __nv_bfloat16*  sW1  = (__nv_bfloat16*)(smb + F_W1);
    __nv_bfloat16*  sW2  = (__nv_bfloat16*)(smb + F_W2);
    float*          sN2G = (float*)(smb + F_N2G);
    float*          sFB1 = (float*)(smb + F_FB1);
    float*          sFB2 = (float*)(smb + F_FB2);
    float*          sLS2 = (float*)(smb + F_LS2);
    float*          sWGT = (float*)(smb + F_WGT);

    int t = threadIdx.x, wid = t >> 5, lane = t & 31;

    {
        const __nv_bfloat16* w1g = g_fw1b + e * FFH * CDIM;
        const __nv_bfloat16* w2g = g_fw2b + e * CDIM * FFH;
        const float* xsg = g_xs + (size_t)e * BTOK * DDIM + (size_t)r0 * 64;
#pragma unroll
        for (int i = t; i < 2048; i += 256) {
            int j = i >> 3, sg = i & 7;
            *(uint4*)(sW1 + j * 72 + sg * 8) = *(const uint4*)(w1g + j * 64 + sg * 8);
        }
#pragma unroll
        for (int i = t; i < 2048; i += 256) {
            int n = i >> 5, sg = i & 31;
            *(uint4*)(sW2 + n * 264 + sg * 8) = *(const uint4*)(w2g + n * 256 + sg * 8);
        }
#pragma unroll
        for (int i = t; i < 2048; i += 256) {
            int r = i >> 4, sg = i & 15;
            *(float4*)(sXS + r * 64 + sg * 4) = *(const float4*)(xsg + (size_t)r * 64 + sg * 4);
        }
        if (t < 64) { sN2G[t] = n2g[e * 64 + t]; sFB2[t] = fb2[e * 64 + t]; sLS2[t] = ls2[e * 64 + t]; }
        if (t < 256) sFB1[t] = fb1[e * 256 + t];
        if (t < 128) {
            int rr = r0 + t;
            sWGT[t] = (rr < rows_e) ? g_wslot[e * BTOK + rr / 20] : 0.f;
        }
    }
    __syncthreads();

#pragma unroll
    for (int i = 0; i < 16; i++) {
        int r = wid * 16 + i;
        float v0 = sXS[r * 64 + lane], v1 = sXS[r * 64 + 32 + lane];
        float ss = v0 * v0 + v1 * v1;
#pragma unroll
        for (int o = 16; o; o >>= 1) ss += __shfl_xor_sync(0xffffffffu, ss, o);
        float inv = 1.f / (sqrtf(ss * (1.f / 64.f)) + 1e-8f);
        sXN[r * 72 + lane]      = __float2bfloat16(v0 * inv * sN2G[lane]);
        sXN[r * 72 + 32 + lane] = __float2bfloat16(v1 * inv * sN2G[32 + lane]);
    }
    __syncthreads();

    uint32_t sbXN = smem_u32(sXN), sbW1 = smem_u32(sW1);
    uint32_t sbF1 = smem_u32(sF1), sbW2 = smem_u32(sW2);
    int a_r = (lane & 15), a_k = ((lane >> 4) << 3);
    int b_r = (lane & 7) + ((lane >> 4) << 3), b_k = (((lane >> 3) & 1) << 3);

    {
        int wm = wid & 1, wn = wid >> 1;
#pragma unroll
        for (int nh = 0; nh < 2; nh++) {
            float acc[4][4][4];
#pragma unroll
            for (int i = 0; i < 4; i++)
#pragma unroll
                for (int j = 0; j < 4; j++)
#pragma unroll
                    for (int q = 0; q < 4; q++) acc[i][j][q] = 0.f;
#pragma unroll
            for (int k16 = 0; k16 < 4; k16++) {
                int kb = k16 * 16;
                uint32_t bh[4][2];
#pragma unroll
                for (int np = 0; np < 2; np++) {
                    uint32_t boff = (uint32_t)((nh * 128 + wn * 32 + np * 16 + b_r) * 72 + kb + b_k) * 2;
                    ldm_x4(bh[np * 2][0], bh[np * 2][1], bh[np * 2 + 1][0], bh[np * 2 + 1][1], sbW1 + boff);
                }
#pragma unroll
                for (int mt2 = 0; mt2 < 4; mt2++) {
                    uint32_t aoff = (uint32_t)((wm * 64 + mt2 * 16 + a_r) * 72 + kb + a_k) * 2;
                    uint32_t ah[4];
                    ldm_x4(ah[0], ah[1], ah[2], ah[3], sbXN + aoff);
#pragma unroll
                    for (int ntl = 0; ntl < 4; ntl++) mma16816(acc[mt2][ntl], ah, bh[ntl]);
                }
            }
#pragma unroll
            for (int mt2 = 0; mt2 < 4; mt2++) {
#pragma unroll
                for (int ntl = 0; ntl < 4; ntl++) {
                    int col = nh * 128 + wn * 32 + ntl * 8 + (lane & 3) * 2;
                    int r1 = wm * 64 + mt2 * 16 + (lane >> 2), r2 = r1 + 8;
                    float b0 = sFB1[col], b1 = sFB1[col + 1];
                    float c0 = fmaxf(acc[mt2][ntl][0] + b0, 0.f);
                    float c1 = fmaxf(acc[mt2][ntl][1] + b1, 0.f);
                    float c2 = fmaxf(acc[mt2][ntl][2] + b0, 0.f);
                    float c3 = fmaxf(acc[mt2][ntl][3] + b1, 0.f);
                    *(__nv_bfloat162*)(sF1 + r1 * 264 + col) = __float22bfloat162_rn(make_float2(c0, c1));
                    *(__nv_bfloat162*)(sF1 + r2 * 264 + col) = __float22bfloat162_rn(make_float2(c2, c3));
                }
            }
        }
    }
    __syncthreads();

    {
        int wm2 = wid & 3, wn2 = wid >> 2;
        float acc2[2][4][4];
#pragma unroll
        for (int i = 0; i < 2; i++)
#pragma unroll
            for (int j = 0; j < 4; j++)
#pragma unroll
                for (int q = 0; q < 4; q++) acc2[i][j][q] = 0.f;
#pragma unroll
        for (int k16 = 0; k16 < 16; k16++) {
            int kb = k16 * 16;
            uint32_t bh[4][2];
#pragma unroll
            for (int np = 0; np < 2; np++) {
                uint32_t boff = (uint32_t)((wn2 * 32 + np * 16 + b_r) * 264 + kb + b_k) * 2;
                ldm_x4(bh[np * 2][0], bh[np * 2][1], bh[np * 2 + 1][0], bh[np * 2 + 1][1], sbW2 + boff);
            }
#pragma unroll
            for (int mt2 = 0; mt2 < 2; mt2++) {
                uint32_t aoff = (uint32_t)((wm2 * 32 + mt2 * 16 + a_r) * 264 + kb + a_k) * 2;
                uint32_t ah[4];
                ldm_x4(ah[0], ah[1], ah[2], ah[3], sbF1 + aoff);
#pragma unroll
                for (int ntl = 0; ntl < 4; ntl++) mma16816(acc2[mt2][ntl], ah, bh[ntl]);
            }
        }
        __half* ghf = g_hf + (size_t)e * BTOK * DDIM + (size_t)r0 * 64;
#pragma unroll
        for (int mt2 = 0; mt2 < 2; mt2++) {
#pragma unroll
            for (int ntl = 0; ntl < 4; ntl++) {
                int col = wn2 * 32 + ntl * 8 + (lane & 3) * 2;
                float b0 = sFB2[col], b1 = sFB2[col + 1];
                float l0 = sLS2[col], l1 = sLS2[col + 1];
#pragma unroll
                for (int half = 0; half < 2; half++) {
                    int r = wm2 * 32 + mt2 * 16 + (lane >> 2) + half * 8;
                    if (r0 + r < rows_e) {
                        float w = sWGT[r];
                        float v0 = w * (sXS[r * 64 + col]     + l0 * (acc2[mt2][ntl][half * 2]     + b0));
                        float v1 = w * (sXS[r * 64 + col + 1] + l1 * (acc2[mt2][ntl][half * 2 + 1] + b1));
                        *(__half2*)(ghf + (size_t)r * 64 + col) = __floats2half2_rn(v0, v1);
                    }
                }
            }
        }
    }
}

// ---------------- K3: warp-MMA fp16 x2-term proj GEMM, cp.async double-buffered ----------------
// D = A_fp16 * (Bh + Bl), B pre-scaled by 64; epilogue scales by 1/64.
#define KC 32
#define SSTRIDE 40                 // fp16 elems per row (32 + 8 pad) = 80B
#define PJ_TILE_BYTES 10240        // 128 rows * 80B
#define PJ_STAGE_BYTES (3 * PJ_TILE_BYTES)   // A, Bh, Bl
#define PJ_SMEM (2 * PJ_STAGE_BYTES)         // 61440

__global__ void __launch_bounds__(256, 2) k_proj_mma() {
    int e  = blockIdx.y >> 6;
    int mt = blockIdx.y & 63;
    int nt = blockIdx.x;
    int cnt = g_cnt[e];
    int row0 = mt * 128;
    if (row0 >= cnt) return;

    extern __shared__ char smb[];
    uint32_t sb0 = smem_u32(smb);

    int t = threadIdx.x;
    int wid = t >> 5, lane = t & 31;
    int wm = wid & 1, wn = wid >> 1;

    const __half* Af = g_hf + (size_t)(e * BTOK) * DDIM;
    const __half* Bh = g_pwh + (size_t)e * DDIM * DDIM + (size_t)(nt * 128) * DDIM;
    const __half* Bl = g_pwl + (size_t)e * DDIM * DDIM + (size_t)(nt * 128) * DDIM;

    float acc[4][4][4];
#pragma unroll
    for (int i = 0; i < 4; i++)
#pragma unroll
        for (int j = 0; j < 4; j++)
#pragma unroll
            for (int q = 0; q < 4; q++) acc[i][j][q] = 0.f;

    int rw0 = t >> 2, q0 = t & 3;
    int rw1 = rw0 + 64, q1 = q0;
    bool v0 = (row0 + rw0) < cnt, v1 = (row0 + rw1) < cnt;
    int ra0 = v0 ? (row0 + rw0) : 0, ra1 = v1 ? (row0 + rw1) : 0;
    int sz0 = v0 ? 16 : 0, sz1 = v1 ? 16 : 0;
    uint32_t off0 = (uint32_t)(rw0 * 5 + q0) * 16;
    uint32_t off1 = (uint32_t)(rw1 * 5 + q1) * 16;

#define PJ_ISSUE(cc, stg) do { \
        int k0 = (cc) * KC; \
        uint32_t db = sb0 + (uint32_t)(stg) * PJ_STAGE_BYTES; \
        size_t ea0 = (size_t)ra0 * DDIM + k0 + q0 * 8; \
        size_t ea1 = (size_t)ra1 * DDIM + k0 + q1 * 8; \
        size_t eb0 = (size_t)rw0 * DDIM + k0 + q0 * 8; \
        size_t eb1 = (size_t)rw1 * DDIM + k0 + q1 * 8; \
        cpa16(db + off0,                     Af + ea0, sz0); \
        cpa16(db + off1,                     Af + ea1, sz1); \
        cpa16(db + PJ_TILE_BYTES + off0,     Bh + eb0, 16); \
        cpa16(db + PJ_TILE_BYTES + off1,     Bh + eb1, 16); \
        cpa16(db + 2 * PJ_TILE_BYTES + off0, Bl + eb0, 16); \
        cpa16(db + 2 * PJ_TILE_BYTES + off1, Bl + eb1, 16); \
    } while (0)

    int a_r = (lane & 15), a_k = ((lane >> 4) << 3);
    int b_r = (lane & 7) + ((lane >> 4) << 3), b_k = (((lane >> 3) & 1) << 3);

    const int NCHUNK = DDIM / KC;     // 40
    PJ_ISSUE(0, 0); CPA_COMMIT();
    PJ_ISSUE(1, 1); CPA_COMMIT();

    for (int c = 0; c < NCHUNK; c++) {
        CPA_WAIT1();                  // chunk c resident (invariant: 1 group commit/iter)
        __syncthreads();
        int stg = c & 1;
        uint32_t base = sb0 + (uint32_t)stg * PJ_STAGE_BYTES;
        uint32_t sA = base;
        uint32_t sBh = base + PJ_TILE_BYTES, sBl = base + 2 * PJ_TILE_BYTES;

#pragma unroll
        for (int k16 = 0; k16 < 2; k16++) {
            int kb = k16 * 16;
            uint32_t bh[4][2], bl[4][2];
#pragma unroll
            for (int np = 0; np < 2; np++) {
                uint32_t boff = (uint32_t)((wn * 32 + np * 16 + b_r) * SSTRIDE + kb + b_k) * 2;
                ldm_x4(bh[np * 2][0], bh[np * 2][1], bh[np * 2 + 1][0], bh[np * 2 + 1][1], sBh + boff);
                ldm_x4(bl[np * 2][0], bl[np * 2][1], bl[np * 2 + 1][0], bl[np * 2 + 1][1], sBl + boff);
            }
#pragma unroll
            for (int mt2 = 0; mt2 < 4; mt2++) {
                uint32_t aoff = (uint32_t)((wm * 64 + mt2 * 16 + a_r) * SSTRIDE + kb + a_k) * 2;
                uint32_t ah[4];
                ldm_x4(ah[0], ah[1], ah[2], ah[3], sA + aoff);
#pragma unroll
                for (int ntl = 0; ntl < 4; ntl++) {
                    mma16816h(acc[mt2][ntl], ah, bh[ntl]);
                    mma16816h(acc[mt2][ntl], ah, bl[ntl]);
                }
            }
        }
        __syncthreads();              // all reads of stage done before refill
        if (c + 2 < NCHUNK) PJ_ISSUE(c + 2, stg);
        CPA_COMMIT();                 // exactly one group per iteration (may be empty)
    }

    const float SCL = 1.f / 64.f;     // undo B pre-scale
    int lrow = lane >> 2, lcol = (lane & 3) * 2;
    float* Ybase = g_y + (size_t)(e * BTOK) * DDIM;
#pragma unroll
    for (int mt2 = 0; mt2 < 4; mt2++) {
        int rbase = row0 + wm * 64 + mt2 * 16;
        int r1 = rbase + lrow, r2 = rbase + 8 + lrow;
#pragma unroll
        for (int ntl = 0; ntl < 4; ntl++) {
            int col = nt * 128 + wn * 32 + ntl * 8 + lcol;
            if (r1 < cnt) {
                float2 vv = make_float2(acc[mt2][ntl][0] * SCL, acc[mt2][ntl][1] * SCL);
                *(float2*)&Ybase[(size_t)r1 * DDIM + col] = vv;
            }
            if (r2 < cnt) {
                float2 vv = make_float2(acc[mt2][ntl][2] * SCL, acc[mt2][ntl][3] * SCL);
                *(float2*)&Ybase[(size_t)r2 * DDIM + col] = vv;
            }
        }
    }
}

// ---------------- K4: combine (+bias) + aux/load tail ----------------
__global__ void k_combine(const float* __restrict__ pb, float* __restrict__ out,
                          long long out_size) {
    long long idx = (long long)blockIdx.x * 256 + threadIdx.x;
    const long long TOT = (long long)BTOK * DDIM;
    if (idx < TOT) {
        int b = (int)(idx / DDIM), d = (int)(idx % DDIM);
        int s0 = g_slot[2 * b], s1 = g_slot[2 * b + 1];
        int e0 = g_tope[2 * b], e1 = g_tope[2 * b + 1];
        float v = g_y[(size_t)s0 * DDIM + d] + g_y[(size_t)s1 * DDIM + d]
                + g_topw[2 * b] * pb[e0 * DDIM + d]
                + g_topw[2 * b + 1] * pb[e1 * DDIM + d];
        out[idx] = v;
    }
    if (idx == 0 && out_size >= TOT + 5) {
        out[TOT] = 0.f;
#pragma unroll
        for (int e = 0; e < NEXP; e++) out[TOT + 1 + e] = (float)g_cnt[e];
    }
}

// ---------------- host launcher ----------------
extern "C" void kernel_launch(void* const* d_in, const int* in_sizes, int n_in,
                              void* d_out, int out_size) {
    const float* x    = (const float*)d_in[0];
    const float* gw1  = (const float*)d_in[1];
    const float* gb1  = (const float*)d_in[2];
    const float* gw2  = (const float*)d_in[3];
    const float* gb2  = (const float*)d_in[4];
    const float* pos  = (const float*)d_in[5];
    const float* n1g  = (const float*)d_in[6];
    const float* ipw  = (const float*)d_in[7];
    const float* ipb  = (const float*)d_in[8];
    const float* opw  = (const float*)d_in[9];
    const float* opb  = (const float*)d_in[10];
    const float* ls1  = (const float*)d_in[11];
    const float* n2g  = (const float*)d_in[12];
    const float* fw1  = (const float*)d_in[13];
    const float* fb1  = (const float*)d_in[14];
    const float* fw2  = (const float*)d_in[15];
    const float* fb2  = (const float*)d_in[16];
    const float* ls2  = (const float*)d_in[17];
    const float* pw   = (const float*)d_in[18];
    const float* pb   = (const float*)d_in[19];
    float* out = (float*)d_out;

    cudaFuncSetAttribute(k_att, cudaFuncAttributeMaxDynamicSharedMemorySize, T_TOT);
    cudaFuncSetAttribute(k_ffn, cudaFuncAttributeMaxDynamicSharedMemorySize, F_TOT);
    cudaFuncSetAttribute(k_proj_mma, cudaFuncAttributeMaxDynamicSharedMemorySize, PJ_SMEM);

    k_init<<<1, 32>>>();
    k_gate<<<BTOK / 8, 256>>>(x, gw1, gb1, gw2, gb2);
    {
        size_t tot4 = (size_t)NEXP * DDIM * DDIM / 4;
        k_convw<<<(unsigned)((tot4 + 255) / 256), 256>>>(pw);
    }
    k_convb<<<(NEXP * FFH * CDIM + 255) / 256, 256>>>(fw1, fw2, ipw, opw);
    k_att<<<dim3((BTOK + AT_TOK - 1) / AT_TOK, NEXP), 256, T_TOT>>>(x, pos, n1g, ipb, opb, ls1);
    k_ffn<<<dim3(BTOK * NCH / 128, NEXP), 256, F_TOT>>>(n2g, fb1, fb2, ls2);
    k_proj_mma<<<dim3(DDIM / 128, NEXP * 64), 256, PJ_SMEM>>>();
    long long tot = (long long)BTOK * DDIM;
    k_combine<<<(unsigned)((tot + 255) / 256), 256>>>(pb, out, (long long)out_size);
}

// round 9
// speedup vs baseline: 4.8867x; 1.1650x over previous
#include <cuda_runtime.h>
#include <cuda_bf16.h>
#include <cuda_fp16.h>
#include <math.h>
#include <cstdint>

// ---------------- problem constants ----------------
#define BTOK 8192
#define DDIM 1280
#define NEXP 4
#define NCH  20
#define CDIM 64
#define NHEAD 4
#define HDIM 16
#define FFH  256

// ---------------- device scratch (allocation-free) ----------------
__device__ float g_w[BTOK * NEXP];
__device__ float g_wslot[NEXP * BTOK];      // slot -> combine weight
__device__ int   g_tok[NEXP * BTOK];        // slot -> token id
__device__ int   g_cnt[NEXP];
__device__ int   g_slot[2 * BTOK];          // token -> global slot (e*B + slot)
__device__ int   g_tope[2 * BTOK];
__device__ float g_topw[2 * BTOK];
__device__ float g_xs[(size_t)NEXP * BTOK * DDIM];   // post-attn residual (slot-major)
__device__ __half g_hf [(size_t)NEXP * BTOK * DDIM]; // compact hidden, fp16 single
__device__ __half g_pwh[(size_t)NEXP * DDIM * DDIM]; // proj weight fp16 (x64)
__device__ __nv_bfloat16 g_fw1b[NEXP * FFH * CDIM];
__device__ __nv_bfloat16 g_fw2b[NEXP * CDIM * FFH];
__device__ __nv_bfloat16 g_ipwb[NEXP * 3 * CDIM * CDIM];   // 192x64 per expert
__device__ __nv_bfloat16 g_opwb[NEXP * CDIM * CDIM];       // 64x64 per expert
__device__ float g_y [(size_t)NEXP * BTOK * DDIM];

// ---------------- warp MMA helpers ----------------
__device__ __forceinline__ uint32_t smem_u32(const void* p) {
    uint32_t a;
    asm("{ .reg .u64 t; cvta.to.shared.u64 t, %1; cvt.u32.u64 %0, t; }" : "=r"(a) : "l"(p));
    return a;
}
__device__ __forceinline__ void ldm_x4(uint32_t& r0, uint32_t& r1, uint32_t& r2, uint32_t& r3,
                                       uint32_t addr) {
    asm volatile("ldmatrix.sync.aligned.m8n8.x4.shared.b16 {%0,%1,%2,%3}, [%4];"
                 : "=r"(r0), "=r"(r1), "=r"(r2), "=r"(r3) : "r"(addr));
}
__device__ __forceinline__ void mma16816(float* d, const uint32_t* a, const uint32_t* b) {
    asm volatile("mma.sync.aligned.m16n8k16.row.col.f32.bf16.bf16.f32 "
                 "{%0,%1,%2,%3}, {%4,%5,%6,%7}, {%8,%9}, {%0,%1,%2,%3};"
                 : "+f"(d[0]), "+f"(d[1]), "+f"(d[2]), "+f"(d[3])
                 : "r"(a[0]), "r"(a[1]), "r"(a[2]), "r"(a[3]), "r"(b[0]), "r"(b[1]));
}
__device__ __forceinline__ void mma16816h(float* d, const uint32_t* a, const uint32_t* b) {
    asm volatile("mma.sync.aligned.m16n8k16.row.col.f32.f16.f16.f32 "
                 "{%0,%1,%2,%3}, {%4,%5,%6,%7}, {%8,%9}, {%0,%1,%2,%3};"
                 : "+f"(d[0]), "+f"(d[1]), "+f"(d[2]), "+f"(d[3])
                 : "r"(a[0]), "r"(a[1]), "r"(a[2]), "r"(a[3]), "r"(b[0]), "r"(b[1]));
}
__device__ __forceinline__ void cpa16(uint32_t dst, const void* src, int srcsize) {
    asm volatile("cp.async.cg.shared.global [%0], [%1], 16, %2;"
                 :: "r"(dst), "l"(src), "r"(srcsize) : "memory");
}
#define CPA_COMMIT() asm volatile("cp.async.commit_group;" ::: "memory")
#define CPA_WAIT1()  asm volatile("cp.async.wait_group 1;" ::: "memory")

// ---------------- K0: init ----------------
__global__ void k_init() {
    if (threadIdx.x < NEXP) g_cnt[threadIdx.x] = 0;
}

// ---------------- K1: gating + routing ----------------
__global__ void k_gate(const float* __restrict__ x,
                       const float* __restrict__ gw1, const float* __restrict__ gb1,
                       const float* __restrict__ gw2, const float* __restrict__ gb2) {
    __shared__ float s_x[8][DDIM];
    int warp = threadIdx.x >> 5, lane = threadIdx.x & 31;
    int b = blockIdx.x * 8 + warp;
    const float* xr = x + (size_t)b * DDIM;
    for (int d = lane; d < DDIM; d += 32) s_x[warp][d] = xr[d];
    __syncwarp();
    float h1[16];
#pragma unroll
    for (int j = 0; j < 16; j++) {
        float s = 0.f;
        const float* wr = gw1 + j * DDIM;
        for (int d = lane; d < DDIM; d += 32) s += s_x[warp][d] * wr[d];
#pragma unroll
        for (int o = 16; o; o >>= 1) s += __shfl_xor_sync(0xffffffffu, s, o);
        h1[j] = tanhf(s + gb1[j]);
    }
    if (lane == 0) {
        float logits[NEXP];
#pragma unroll
        for (int e = 0; e < NEXP; e++) {
            float s = gb2[e];
#pragma unroll
            for (int j = 0; j < 16; j++) s += h1[j] * gw2[e * 16 + j];
            logits[e] = s;
        }
        float m = logits[0];
#pragma unroll
        for (int e = 1; e < NEXP; e++) m = fmaxf(m, logits[e]);
        float p[NEXP], sum = 0.f;
#pragma unroll
        for (int e = 0; e < NEXP; e++) { p[e] = expf(logits[e] - m); sum += p[e]; }
#pragma unroll
        for (int e = 0; e < NEXP; e++) p[e] /= sum;
        int e0 = 0;
#pragma unroll
        for (int e = 1; e < NEXP; e++) if (p[e] > p[e0]) e0 = e;
        int e1 = -1;
#pragma unroll
        for (int e = 0; e < NEXP; e++) {
            if (e == e0) continue;
            if (e1 < 0 || p[e] > p[e1]) e1 = e;
        }
        float den = p[e0] + p[e1] + 1e-6f;
        float w0 = p[e0] / den, w1 = p[e1] / den;
        int s0 = atomicAdd(&g_cnt[e0], 1);
        int s1 = atomicAdd(&g_cnt[e1], 1);
        g_slot[2 * b]     = e0 * BTOK + s0;
        g_slot[2 * b + 1] = e1 * BTOK + s1;
        g_wslot[e0 * BTOK + s0] = w0;
        g_wslot[e1 * BTOK + s1] = w1;
        g_tok[e0 * BTOK + s0] = b;
        g_tok[e1 * BTOK + s1] = b;
        g_tope[2 * b] = e0; g_tope[2 * b + 1] = e1;
        g_topw[2 * b] = w0; g_topw[2 * b + 1] = w1;
    }
}

// ---------------- K1b: convert proj weights to fp16 (x64 scaled) ----------------
__global__ void k_convw(const float* __restrict__ pw) {
    size_t i = ((size_t)blockIdx.x * 256 + threadIdx.x) * 4;
    const size_t TOT = (size_t)NEXP * DDIM * DDIM;
    if (i >= TOT) return;
    float4 v = *(const float4*)&pw[i];
    __half h0 = __float2half(v.x * 64.f), h1 = __float2half(v.y * 64.f);
    __half h2 = __float2half(v.z * 64.f), h3 = __float2half(v.w * 64.f);
    *(__half2*)&g_pwh[i]     = __half2(h0, h1);
    *(__half2*)&g_pwh[i + 2] = __half2(h2, h3);
}

// ---------------- K1c: convert small weights to bf16 ----------------
__global__ void k_convb(const float* __restrict__ fw1, const float* __restrict__ fw2,
                        const float* __restrict__ ipw, const float* __restrict__ opw) {
    int i = blockIdx.x * 256 + threadIdx.x;
    if (i < NEXP * FFH * CDIM) {
        g_fw1b[i] = __float2bfloat16(fw1[i]);
        g_fw2b[i] = __float2bfloat16(fw2[i]);
    }
    if (i < NEXP * 3 * CDIM * CDIM) g_ipwb[i] = __float2bfloat16(ipw[i]);
    if (i < NEXP * CDIM * CDIM)     g_opwb[i] = __float2bfloat16(opw[i]);
}

// ---------------- K2a: k_att — pos + rms1 + attn (all-MMA) + residual ----------------
#define AT_TOK 6
#define QS 200
#define T_QKV  0        // phase1: XS fp32 128x64 (32768); then QKV 128x200 bf16 (51200)
#define T_XN   51200    // XN 128x72 bf16 (18432); later O
#define T_IPW  69632    // 192x72 bf16 (27648)
#define T_OPW  97280    // 64x72 bf16 (9216)
#define T_IPB  106496   // 192 f
#define T_OPB  107264   // 64 f
#define T_N1G  107520
#define T_LS1  107776
#define T_TOK  108032
#define T_TOT  108064

__global__ void __launch_bounds__(256, 2) k_att(
    const float* __restrict__ x, const float* __restrict__ pos,
    const float* __restrict__ n1g, const float* __restrict__ ipb,
    const float* __restrict__ opb, const float* __restrict__ ls1) {
    int e   = blockIdx.y;
    int tk0 = blockIdx.x * AT_TOK;
    int cnt = g_cnt[e];
    if (tk0 >= cnt) return;
    int nval = min(AT_TOK, cnt - tk0);
    int rows = nval * NCH;

    extern __shared__ char smb[];
    float*         sXS  = (float*)(smb + T_QKV);            // alias (dead after rms)
    __nv_bfloat16* sQKV = (__nv_bfloat16*)(smb + T_QKV);
    __nv_bfloat16* sXN  = (__nv_bfloat16*)(smb + T_XN);
    __nv_bfloat16* sO   = (__nv_bfloat16*)(smb + T_XN);     // alias (XN dead after in_proj)
    __nv_bfloat16* sIPW = (__nv_bfloat16*)(smb + T_IPW);
    __nv_bfloat16* sOPW = (__nv_bfloat16*)(smb + T_OPW);
    float* sIPB = (float*)(smb + T_IPB);
    float* sOPB = (float*)(smb + T_OPB);
    float* sN1G = (float*)(smb + T_N1G);
    float* sLS1 = (float*)(smb + T_LS1);
    int*   sTok = (int*)(smb + T_TOK);

    int t = threadIdx.x, wid = t >> 5, lane = t & 31;

    if (t < AT_TOK) sTok[t] = (t < nval) ? g_tok[e * BTOK + tk0 + t] : 0;
    __syncthreads();

    // ---- staging ----
    {
        const __nv_bfloat16* ipwg = g_ipwb + e * 192 * 64;
        const __nv_bfloat16* opwg = g_opwb + e * 64 * 64;
#pragma unroll
        for (int i = t; i < 1536; i += 256) {        // ipw 192x64
            int j = i >> 3, sg = i & 7;
            *(uint4*)(sIPW + j * 72 + sg * 8) = *(const uint4*)(ipwg + j * 64 + sg * 8);
        }
#pragma unroll
        for (int i = t; i < 512; i += 256) {         // opw 64x64
            int j = i >> 3, sg = i & 7;
            *(uint4*)(sOPW + j * 72 + sg * 8) = *(const uint4*)(opwg + j * 64 + sg * 8);
        }
#pragma unroll
        for (int i = t; i < 2048; i += 256) {        // xs gather 128 rows x 16 float4
            int r = i >> 4, q = i & 15;
            float4 v = make_float4(0.f, 0.f, 0.f, 0.f);
            if (r < rows) {
                int tok = sTok[r / NCH], c = r % NCH;
                float4 xv = *(const float4*)(x + (size_t)tok * DDIM + c * 64 + q * 4);
                float4 pv = *(const float4*)(pos + (size_t)e * DDIM + c * 64 + q * 4);
                v = make_float4(xv.x + pv.x, xv.y + pv.y, xv.z + pv.z, xv.w + pv.w);
            }
            *(float4*)(sXS + r * 64 + q * 4) = v;
        }
        if (t < 192) sIPB[t] = ipb[e * 192 + t];
        if (t < 64) {
            sOPB[t] = opb[e * 64 + t];
            sN1G[t] = n1g[e * 64 + t];
            sLS1[t] = ls1[e * 64 + t];
        }
    }
    __syncthreads();

    // ---- rms1: XS -> XN bf16 (XS dead afterwards) ----
#pragma unroll
    for (int i = 0; i < 16; i++) {
        int r = wid * 16 + i;
        float v0 = sXS[r * 64 + lane], v1 = sXS[r * 64 + 32 + lane];
        float ss = v0 * v0 + v1 * v1;
#pragma unroll
        for (int o = 16; o; o >>= 1) ss += __shfl_xor_sync(0xffffffffu, ss, o);
        float inv = 1.f / (sqrtf(ss * (1.f / 64.f)) + 1e-8f);
        sXN[r * 72 + lane]      = __float2bfloat16(v0 * inv * sN1G[lane]);
        sXN[r * 72 + 32 + lane] = __float2bfloat16(v1 * inv * sN1G[32 + lane]);
    }
    __syncthreads();

    uint32_t sbXN = smem_u32(sXN), sbIPW = smem_u32(sIPW);
    uint32_t sbO  = smem_u32(sO),  sbOPW = smem_u32(sOPW);
    int a_r = (lane & 15), a_k = ((lane >> 4) << 3);
    int b_r = (lane & 7) + ((lane >> 4) << 3), b_k = (((lane >> 3) & 1) << 3);

    // ---- in_proj MMA: [128,64] x [192,64]^T + bias -> sQKV (overwrites XS; 2 N-halves) ----
    {
        int wm4 = wid & 3, wn2 = wid >> 2;   // 4(M) x 2(N); warp = 32 rows x 48 cols
#pragma unroll
        for (int nh = 0; nh < 2; nh++) {
            float acc[2][6][4];
#pragma unroll
            for (int i = 0; i < 2; i++)
#pragma unroll
                for (int j = 0; j < 6; j++)
#pragma unroll
                    for (int q = 0; q < 4; q++) acc[i][j][q] = 0.f;
#pragma unroll
            for (int k16 = 0; k16 < 4; k16++) {
                int kb = k16 * 16;
                uint32_t bh[6][2];
#pragma unroll
                for (int np = 0; np < 3; np++) {
                    uint32_t boff = (uint32_t)((nh * 96 + wn2 * 48 + np * 16 + b_r) * 72 + kb + b_k) * 2;
                    ldm_x4(bh[np * 2][0], bh[np * 2][1], bh[np * 2 + 1][0], bh[np * 2 + 1][1], sbIPW + boff);
                }
#pragma unroll
                for (int mt2 = 0; mt2 < 2; mt2++) {
                    uint32_t aoff = (uint32_t)((wm4 * 32 + mt2 * 16 + a_r) * 72 + kb + a_k) * 2;
                    uint32_t ah[4];
                    ldm_x4(ah[0], ah[1], ah[2], ah[3], sbXN + aoff);
#pragma unroll
                    for (int ntl = 0; ntl < 6; ntl++) mma16816(acc[mt2][ntl], ah, bh[ntl]);
                }
            }
#pragma unroll
            for (int mt2 = 0; mt2 < 2; mt2++) {
#pragma unroll
                for (int ntl = 0; ntl < 6; ntl++) {
                    int col = nh * 96 + wn2 * 48 + ntl * 8 + (lane & 3) * 2;
                    int r1 = wm4 * 32 + mt2 * 16 + (lane >> 2), r2 = r1 + 8;
                    float b0 = sIPB[col], b1 = sIPB[col + 1];
                    *(__nv_bfloat162*)(sQKV + r1 * QS + col) =
                        __float22bfloat162_rn(make_float2(acc[mt2][ntl][0] + b0, acc[mt2][ntl][1] + b1));
                    *(__nv_bfloat162*)(sQKV + r2 * QS + col) =
                        __float22bfloat162_rn(make_float2(acc[mt2][ntl][2] + b0, acc[mt2][ntl][3] + b1));
                }
            }
        }
    }
    __syncthreads();

    // ---- attention: 24 (token,head) tasks, in-lane softmax; writes sO (= XN region) ----
    for (int task = wid; task < AT_TOK * NHEAD; task += 8) {
        int tk = task >> 2, h = task & 3;
        if (tk >= nval) continue;
        if (lane < NCH) {
            const __nv_bfloat16* qrow = sQKV + (tk * NCH + lane) * QS + h * 16;
            float qv[16];
#pragma unroll
            for (int d2 = 0; d2 < 8; d2++) {
                float2 f = __bfloat1622float2(*(const __nv_bfloat162*)(qrow + d2 * 2));
                qv[d2 * 2] = f.x; qv[d2 * 2 + 1] = f.y;
            }
            float s[NCH];
#pragma unroll
            for (int c2 = 0; c2 < NCH; c2++) {
                const __nv_bfloat16* krow = sQKV + (tk * NCH + c2) * QS + 64 + h * 16;
                float dot = 0.f;
#pragma unroll
                for (int d2 = 0; d2 < 8; d2++) {
                    float2 f = __bfloat1622float2(*(const __nv_bfloat162*)(krow + d2 * 2));
                    dot += qv[d2 * 2] * f.x + qv[d2 * 2 + 1] * f.y;
                }
                s[c2] = dot * 0.25f;
            }
            float m = s[0];
#pragma unroll
            for (int c2 = 1; c2 < NCH; c2++) m = fmaxf(m, s[c2]);
            float sum = 0.f;
#pragma unroll
            for (int c2 = 0; c2 < NCH; c2++) { s[c2] = __expf(s[c2] - m); sum += s[c2]; }
            float inv = 1.f / sum;
            float o[16];
#pragma unroll
            for (int d = 0; d < 16; d++) o[d] = 0.f;
#pragma unroll
            for (int c2 = 0; c2 < NCH; c2++) {
                float a = s[c2] * inv;
                const __nv_bfloat16* vrow = sQKV + (tk * NCH + c2) * QS + 128 + h * 16;
#pragma unroll
                for (int d2 = 0; d2 < 8; d2++) {
                    float2 f = __bfloat1622float2(*(const __nv_bfloat162*)(vrow + d2 * 2));
                    o[d2 * 2] += a * f.x; o[d2 * 2 + 1] += a * f.y;
                }
            }
            __nv_bfloat16* orow = sO + (tk * NCH + lane) * 72 + h * 16;
#pragma unroll
            for (int d2 = 0; d2 < 8; d2++)
                *(__nv_bfloat162*)(orow + d2 * 2) =
                    __float22bfloat162_rn(make_float2(o[d2 * 2], o[d2 * 2 + 1]));
        }
    }
    __syncthreads();

    // ---- out_proj MMA + residual (re-gathered from global) + ls1 -> g_xs ----
    {
        int wm = wid & 1, wn = wid >> 1;   // warp: 64 rows x 16 cols
        float acc[4][2][4];
#pragma unroll
        for (int i = 0; i < 4; i++)
#pragma unroll
            for (int j = 0; j < 2; j++)
#pragma unroll
                for (int q = 0; q < 4; q++) acc[i][j][q] = 0.f;
#pragma unroll
        for (int k16 = 0; k16 < 4; k16++) {
            int kb = k16 * 16;
            uint32_t bh[2][2];
            uint32_t boff = (uint32_t)((wn * 16 + b_r) * 72 + kb + b_k) * 2;
            ldm_x4(bh[0][0], bh[0][1], bh[1][0], bh[1][1], sbOPW + boff);
#pragma unroll
            for (int mt2 = 0; mt2 < 4; mt2++) {
                uint32_t aoff = (uint32_t)((wm * 64 + mt2 * 16 + a_r) * 72 + kb + a_k) * 2;
                uint32_t ah[4];
                ldm_x4(ah[0], ah[1], ah[2], ah[3], sbO + aoff);
#pragma unroll
                for (int ntl = 0; ntl < 2; ntl++) mma16816(acc[mt2][ntl], ah, bh[ntl]);
            }
        }
        float* gout = g_xs + ((size_t)(e * BTOK + tk0)) * DDIM;
        const float* posE = pos + (size_t)e * DDIM;
#pragma unroll
        for (int mt2 = 0; mt2 < 4; mt2++) {
#pragma unroll
            for (int ntl = 0; ntl < 2; ntl++) {
                int col = wn * 16 + ntl * 8 + (lane & 3) * 2;
                float b0 = sOPB[col], b1 = sOPB[col + 1];
                float l0 = sLS1[col], l1 = sLS1[col + 1];
#pragma unroll
                for (int half = 0; half < 2; half++) {
                    int r = wm * 64 + mt2 * 16 + (lane >> 2) + half * 8;
                    if (r < rows) {
                        int tok = sTok[r / NCH], ch = r % NCH;
                        float2 xv = *(const float2*)(x + (size_t)tok * DDIM + ch * 64 + col);
                        float2 pv = *(const float2*)(posE + ch * 64 + col);
                        float v0 = (xv.x + pv.x) + l0 * (acc[mt2][ntl][half * 2]     + b0);
                        float v1 = (xv.y + pv.y) + l1 * (acc[mt2][ntl][half * 2 + 1] + b1);
                        *(float2*)(gout + (size_t)r * 64 + col) = make_float2(v0, v1);
                    }
                }
            }
        }
    }
}

// ---------------- K2b: warp-MMA FFN over compact chunk-rows ----------------
#define F_XS   0          // 128x64 f32      (32768)
#define F_XN   32768      // 128x72 bf16     (18432)
#define F_F1   51200      // 128x264 bf16    (67584)
#define F_W1   118784     // 256x72 bf16     (36864)
#define F_W2   155648     // 64x264 bf16     (33792)
#define F_N2G  189440
#define F_FB1  189696
#define F_FB2  190720
#define F_LS2  190976
#define F_WGT  191232
#define F_TOT  191744

__global__ void __launch_bounds__(256) k_ffn(
    const float* __restrict__ n2g, const float* __restrict__ fb1,
    const float* __restrict__ fb2, const float* __restrict__ ls2) {
    int e  = blockIdx.y;
    int r0 = blockIdx.x * 128;
    int rows_e = g_cnt[e] * NCH;
    if (r0 >= rows_e) return;

    extern __shared__ char smb[];
    float*          sXS  = (float*)(smb + F_XS);
    __nv_bfloat16*  sXN  = (__nv_bfloat16*)(smb + F_XN);
    __nv_bfloat16*  sF1  = (__nv_bfloat16*)(smb + F_F1);
    __nv_bfloat16*  sW1  = (__nv_bfloat16*)(smb + F_W1);
    __nv_bfloat16*  sW2  = (__nv_bfloat16*)(smb + F_W2);
    float*          sN2G = (float*)(smb + F_N2G);
    float*          sFB1 = (float*)(smb + F_FB1);
    float*          sFB2 = (float*)(smb + F_FB2);
    float*          sLS2 = (float*)(smb + F_LS2);
    float*          sWGT = (float*)(smb + F_WGT);

    int t = threadIdx.x, wid = t >> 5, lane = t & 31;

    {
        const __nv_bfloat16* w1g = g_fw1b + e * FFH * CDIM;
        const __nv_bfloat16* w2g = g_fw2b + e * CDIM * FFH;
        const float* xsg = g_xs + (size_t)e * BTOK * DDIM + (size_t)r0 * 64;
#pragma unroll
        for (int i = t; i < 2048; i += 256) {
            int j = i >> 3, sg = i & 7;
            *(uint4*)(sW1 + j * 72 + sg * 8) = *(const uint4*)(w1g + j * 64 + sg * 8);
        }
#pragma unroll
        for (int i = t; i < 2048; i += 256) {
            int n = i >> 5, sg = i & 31;
            *(uint4*)(sW2 + n * 264 + sg * 8) = *(const uint4*)(w2g + n * 256 + sg * 8);
        }
#pragma unroll
        for (int i = t; i < 2048; i += 256) {
            int r = i >> 4, sg = i & 15;
            *(float4*)(sXS + r * 64 + sg * 4) = *(const float4*)(xsg + (size_t)r * 64 + sg * 4);
        }
        if (t < 64) { sN2G[t] = n2g[e * 64 + t]; sFB2[t] = fb2[e * 64 + t]; sLS2[t] = ls2[e * 64 + t]; }
        if (t < 256) sFB1[t] = fb1[e * 256 + t];
        if (t < 128) {
            int rr = r0 + t;
            sWGT[t] = (rr < rows_e) ? g_wslot[e * BTOK + rr / 20] : 0.f;
        }
    }
    __syncthreads();

#pragma unroll
    for (int i = 0; i < 16; i++) {
        int r = wid * 16 + i;
        float v0 = sXS[r * 64 + lane], v1 = sXS[r * 64 + 32 + lane];
        float ss = v0 * v0 + v1 * v1;
#pragma unroll
        for (int o = 16; o; o >>= 1) ss += __shfl_xor_sync(0xffffffffu, ss, o);
        float inv = 1.f / (sqrtf(ss * (1.f / 64.f)) + 1e-8f);
        sXN[r * 72 + lane]      = __float2bfloat16(v0 * inv * sN2G[lane]);
        sXN[r * 72 + 32 + lane] = __float2bfloat16(v1 * inv * sN2G[32 + lane]);
    }
    __syncthreads();

    uint32_t sbXN = smem_u32(sXN), sbW1 = smem_u32(sW1);
    uint32_t sbF1 = smem_u32(sF1), sbW2 = smem_u32(sW2);
    int a_r = (lane & 15), a_k = ((lane >> 4) << 3);
    int b_r = (lane & 7) + ((lane >> 4) << 3), b_k = (((lane >> 3) & 1) << 3);

    {
        int wm = wid & 1, wn = wid >> 1;
#pragma unroll
        for (int nh = 0; nh < 2; nh++) {
            float acc[4][4][4];
#pragma unroll
            for (int i = 0; i < 4; i++)
#pragma unroll
                for (int j = 0; j < 4; j++)
#pragma unroll
                    for (int q = 0; q < 4; q++) acc[i][j][q] = 0.f;
#pragma unroll
            for (int k16 = 0; k16 < 4; k16++) {
                int kb = k16 * 16;
                uint32_t bh[4][2];
#pragma unroll
                for (int np = 0; np < 2; np++) {
                    uint32_t boff = (uint32_t)((nh * 128 + wn * 32 + np * 16 + b_r) * 72 + kb + b_k) * 2;
                    ldm_x4(bh[np * 2][0], bh[np * 2][1], bh[np * 2 + 1][0], bh[np * 2 + 1][1], sbW1 + boff);
                }
#pragma unroll
                for (int mt2 = 0; mt2 < 4; mt2++) {
                    uint32_t aoff = (uint32_t)((wm * 64 + mt2 * 16 + a_r) * 72 + kb + a_k) * 2;
                    uint32_t ah[4];
                    ldm_x4(ah[0], ah[1], ah[2], ah[3], sbXN + aoff);
#pragma unroll
                    for (int ntl = 0; ntl < 4; ntl++) mma16816(acc[mt2][ntl], ah, bh[ntl]);
                }
            }
#pragma unroll
            for (int mt2 = 0; mt2 < 4; mt2++) {
#pragma unroll
                for (int ntl = 0; ntl < 4; ntl++) {
                    int col = nh * 128 + wn * 32 + ntl * 8 + (lane & 3) * 2;
                    int r1 = wm * 64 + mt2 * 16 + (lane >> 2), r2 = r1 + 8;
                    float b0 = sFB1[col], b1 = sFB1[col + 1];
                    float c0 = fmaxf(acc[mt2][ntl][0] + b0, 0.f);
                    float c1 = fmaxf(acc[mt2][ntl][1] + b1, 0.f);
                    float c2 = fmaxf(acc[mt2][ntl][2] + b0, 0.f);
                    float c3 = fmaxf(acc[mt2][ntl][3] + b1, 0.f);
                    *(__nv_bfloat162*)(sF1 + r1 * 264 + col) = __float22bfloat162_rn(make_float2(c0, c1));
                    *(__nv_bfloat162*)(sF1 + r2 * 264 + col) = __float22bfloat162_rn(make_float2(c2, c3));
                }
            }
        }
    }
    __syncthreads();

    {
        int wm2 = wid & 3, wn2 = wid >> 2;
        float acc2[2][4][4];
#pragma unroll
        for (int i = 0; i < 2; i++)
#pragma unroll
            for (int j = 0; j < 4; j++)
#pragma unroll
                for (int q = 0; q < 4; q++) acc2[i][j][q] = 0.f;
#pragma unroll
        for (int k16 = 0; k16 < 16; k16++) {
            int kb = k16 * 16;
            uint32_t bh[4][2];
#pragma unroll
            for (int np = 0; np < 2; np++) {
                uint32_t boff = (uint32_t)((wn2 * 32 + np * 16 + b_r) * 264 + kb + b_k) * 2;
                ldm_x4(bh[np * 2][0], bh[np * 2][1], bh[np * 2 + 1][0], bh[np * 2 + 1][1], sbW2 + boff);
            }
#pragma unroll
            for (int mt2 = 0; mt2 < 2; mt2++) {
                uint32_t aoff = (uint32_t)((wm2 * 32 + mt2 * 16 + a_r) * 264 + kb + a_k) * 2;
                uint32_t ah[4];
                ldm_x4(ah[0], ah[1], ah[2], ah[3], sbF1 + aoff);
#pragma unroll
                for (int ntl = 0; ntl < 4; ntl++) mma16816(acc2[mt2][ntl], ah, bh[ntl]);
            }
        }
        __half* ghf = g_hf + (size_t)e * BTOK * DDIM + (size_t)r0 * 64;
#pragma unroll
        for (int mt2 = 0; mt2 < 2; mt2++) {
#pragma unroll
            for (int ntl = 0; ntl < 4; ntl++) {
                int col = wn2 * 32 + ntl * 8 + (lane & 3) * 2;
                float b0 = sFB2[col], b1 = sFB2[col + 1];
                float l0 = sLS2[col], l1 = sLS2[col + 1];
#pragma unroll
                for (int half = 0; half < 2; half++) {
                    int r = wm2 * 32 + mt2 * 16 + (lane >> 2) + half * 8;
                    if (r0 + r < rows_e) {
                        float w = sWGT[r];
                        float v0 = w * (sXS[r * 64 + col]     + l0 * (acc2[mt2][ntl][half * 2]     + b0));
                        float v1 = w * (sXS[r * 64 + col + 1] + l1 * (acc2[mt2][ntl][half * 2 + 1] + b1));
                        *(__half2*)(ghf + (size_t)r * 64 + col) = __floats2half2_rn(v0, v1);
                    }
                }
            }
        }
    }
}

// ---------------- K3: warp-MMA fp16 single-term proj GEMM, cp.async double-buffered ----------------
// D = A_fp16 * B_fp16 (B pre-scaled by 64); epilogue scales by 1/64.
#define KC 32
#define SSTRIDE 40                 // fp16 elems per row (32 + 8 pad) = 80B
#define PJ_TILE_BYTES 10240        // 128 rows * 80B
#define PJ_STAGE_BYTES (2 * PJ_TILE_BYTES)   // A, B
#define PJ_SMEM (2 * PJ_STAGE_BYTES)         // 40960

__global__ void __launch_bounds__(256, 2) k_proj_mma() {
    int e  = blockIdx.y >> 6;
    int mt = blockIdx.y & 63;
    int nt = blockIdx.x;
    int cnt = g_cnt[e];
    int row0 = mt * 128;
    if (row0 >= cnt) return;

    extern __shared__ char smb[];
    uint32_t sb0 = smem_u32(smb);

    int t = threadIdx.x;
    int wid = t >> 5, lane = t & 31;
    int wm = wid & 1, wn = wid >> 1;

    const __half* Af = g_hf + (size_t)(e * BTOK) * DDIM;
    const __half* Bf = g_pwh + (size_t)e * DDIM * DDIM + (size_t)(nt * 128) * DDIM;

    float acc[4][4][4];
#pragma unroll
    for (int i = 0; i < 4; i++)
#pragma unroll
        for (int j = 0; j < 4; j++)
#pragma unroll
            for (int q = 0; q < 4; q++) acc[i][j][q] = 0.f;

    int rw0 = t >> 2, q0 = t & 3;
    int rw1 = rw0 + 64, q1 = q0;
    bool v0 = (row0 + rw0) < cnt, v1 = (row0 + rw1) < cnt;
    int ra0 = v0 ? (row0 + rw0) : 0, ra1 = v1 ? (row0 + rw1) : 0;
    int sz0 = v0 ? 16 : 0, sz1 = v1 ? 16 : 0;
    uint32_t off0 = (uint32_t)(rw0 * 5 + q0) * 16;
    uint32_t off1 = (uint32_t)(rw1 * 5 + q1) * 16;

#define PJ_ISSUE(cc, stg) do { \
        int k0 = (cc) * KC; \
        uint32_t db = sb0 + (uint32_t)(stg) * PJ_STAGE_BYTES; \
        size_t ea0 = (size_t)ra0 * DDIM + k0 + q0 * 8; \
        size_t ea1 = (size_t)ra1 * DDIM + k0 + q1 * 8; \
        size_t eb0 = (size_t)rw0 * DDIM + k0 + q0 * 8; \
        size_t eb1 = (size_t)rw1 * DDIM + k0 + q1 * 8; \
        cpa16(db + off0,                 Af + ea0, sz0); \
        cpa16(db + off1,                 Af + ea1, sz1); \
        cpa16(db + PJ_TILE_BYTES + off0, Bf + eb0, 16); \
        cpa16(db + PJ_TILE_BYTES + off1, Bf + eb1, 16); \
    } while (0)

    int a_r = (lane & 15), a_k = ((lane >> 4) << 3);
    int b_r = (lane & 7) + ((lane >> 4) << 3), b_k = (((lane >> 3) & 1) << 3);

    const int NCHUNK = DDIM / KC;     // 40
    PJ_ISSUE(0, 0); CPA_COMMIT();
    PJ_ISSUE(1, 1); CPA_COMMIT();

    for (int c = 0; c < NCHUNK; c++) {
        CPA_WAIT1();                  // chunk c resident (invariant: 1 group commit/iter)
        __syncthreads();
        int stg = c & 1;
        uint32_t base = sb0 + (uint32_t)stg * PJ_STAGE_BYTES;
        uint32_t sA = base, sB = base + PJ_TILE_BYTES;

#pragma unroll
        for (int k16 = 0; k16 < 2; k16++) {
            int kb = k16 * 16;
            uint32_t bh[4][2];
#pragma unroll
            for (int np = 0; np < 2; np++) {
                uint32_t boff = (uint32_t)((wn * 32 + np * 16 + b_r) * SSTRIDE + kb + b_k) * 2;
                ldm_x4(bh[np * 2][0], bh[np * 2][1], bh[np * 2 + 1][0], bh[np * 2 + 1][1], sB + boff);
            }
#pragma unroll
            for (int mt2 = 0; mt2 < 4; mt2++) {
                uint32_t aoff = (uint32_t)((wm * 64 + mt2 * 16 + a_r) * SSTRIDE + kb + a_k) * 2;
                uint32_t ah[4];
                ldm_x4(ah[0], ah[1], ah[2], ah[3], sA + aoff);
#pragma unroll
                for (int ntl = 0; ntl < 4; ntl++)
                    mma16816h(acc[mt2][ntl], ah, bh[ntl]);
            }
        }
        __syncthreads();              // all reads of stage done before refill
        if (c + 2 < NCHUNK) PJ_ISSUE(c + 2, stg);
        CPA_COMMIT();                 // exactly one group per iteration (may be empty)
    }

    const float SCL = 1.f / 64.f;     // undo B pre-scale
    int lrow = lane >> 2, lcol = (lane & 3) * 2;
    float* Ybase = g_y + (size_t)(e * BTOK) * DDIM;
#pragma unroll
    for (int mt2 = 0; mt2 < 4; mt2++) {
        int rbase = row0 + wm * 64 + mt2 * 16;
        int r1 = rbase + lrow, r2 = rbase + 8 + lrow;
#pragma unroll
        for (int ntl = 0; ntl < 4; ntl++) {
            int col = nt * 128 + wn * 32 + ntl * 8 + lcol;
            if (r1 < cnt) {
                float2 vv = make_float2(acc[mt2][ntl][0] * SCL, acc[mt2][ntl][1] * SCL);
                *(float2*)&Ybase[(size_t)r1 * DDIM + col] = vv;
            }
            if (r2 < cnt) {
                float2 vv = make_float2(acc[mt2][ntl][2] * SCL, acc[mt2][ntl][3] * SCL);
                *(float2*)&Ybase[(size_t)r2 * DDIM + col] = vv;
            }
        }
    }
}

// ---------------- K4: combine (+bias) + aux/load tail ----------------
__global__ void k_combine(const float* __restrict__ pb, float* __restrict__ out,
                          long long out_size) {
    long long idx = (long long)blockIdx.x * 256 + threadIdx.x;
    const long long TOT = (long long)BTOK * DDIM;
    if (idx < TOT) {
        int b = (int)(idx / DDIM), d = (int)(idx % DDIM);
        int s0 = g_slot[2 * b], s1 = g_slot[2 * b + 1];
        int e0 = g_tope[2 * b], e1 = g_tope[2 * b + 1];
        float v = g_y[(size_t)s0 * DDIM + d] + g_y[(size_t)s1 * DDIM + d]
                + g_topw[2 * b] * pb[e0 * DDIM + d]
                + g_topw[2 * b + 1] * pb[e1 * DDIM + d];
        out[idx] = v;
    }
    if (idx == 0 && out_size >= TOT + 5) {
        out[TOT] = 0.f;
#pragma unroll
        for (int e = 0; e < NEXP; e++) out[TOT + 1 + e] = (float)g_cnt[e];
    }
}

// ---------------- host launcher ----------------
extern "C" void kernel_launch(void* const* d_in, const int* in_sizes, int n_in,
                              void* d_out, int out_size) {
    const float* x    = (const float*)d_in[0];
    const float* gw1  = (const float*)d_in[1];
    const float* gb1  = (const float*)d_in[2];
    const float* gw2  = (const float*)d_in[3];
    const float* gb2  = (const float*)d_in[4];
    const float* pos  = (const float*)d_in[5];
    const float* n1g  = (const float*)d_in[6];
    const float* ipw  = (const float*)d_in[7];
    const float* ipb  = (const float*)d_in[8];
    const float* opw  = (const float*)d_in[9];
    const float* opb  = (const float*)d_in[10];
    const float* ls1  = (const float*)d_in[11];
    const float* n2g  = (const float*)d_in[12];
    const float* fw1  = (const float*)d_in[13];
    const float* fb1  = (const float*)d_in[14];
    const float* fw2  = (const float*)d_in[15];
    const float* fb2  = (const float*)d_in[16];
    const float* ls2  = (const float*)d_in[17];
    const float* pw   = (const float*)d_in[18];
    const float* pb   = (const float*)d_in[19];
    float* out = (float*)d_out;

    cudaFuncSetAttribute(k_att, cudaFuncAttributeMaxDynamicSharedMemorySize, T_TOT);
    cudaFuncSetAttribute(k_ffn, cudaFuncAttributeMaxDynamicSharedMemorySize, F_TOT);
    cudaFuncSetAttribute(k_proj_mma, cudaFuncAttributeMaxDynamicSharedMemorySize, PJ_SMEM);

    k_init<<<1, 32>>>();
    k_gate<<<BTOK / 8, 256>>>(x, gw1, gb1, gw2, gb2);
    {
        size_t tot4 = (size_t)NEXP * DDIM * DDIM / 4;
        k_convw<<<(unsigned)((tot4 + 255) / 256), 256>>>(pw);
    }
    k_convb<<<(NEXP * FFH * CDIM + 255) / 256, 256>>>(fw1, fw2, ipw, opw);
    k_att<<<dim3((BTOK + AT_TOK - 1) / AT_TOK, NEXP), 256, T_TOT>>>(x, pos, n1g, ipb, opb, ls1);
    k_ffn<<<dim3(BTOK * NCH / 128, NEXP), 256, F_TOT>>>(n2g, fb1, fb2, ls2);
    k_proj_mma<<<dim3(DDIM / 128, NEXP * 64), 256, PJ_SMEM>>>();
    long long tot = (long long)BTOK * DDIM;
    k_combine<<<(unsigned)((tot + 255) / 256), 256>>>(pb, out, (long long)out_size);
}